// round 7
// baseline (speedup 1.0000x reference)
#include <cuda_runtime.h>
#include <cstdint>

#define Bb 2
#define Nn 2000
#define Ff 64
#define Dd 128
#define NHEADS 4
#define DH 32
#define HN 3
#define DEEP 384
#define SLOPE 0.1f
#define NEG_INF -1e30f
#define TJ 64
#define NTILES 63            /* ceil(2000/32) */
#define NCHUNK 32            /* 2000 / 64 rounded up: 32*64=2048 */
#define LOG2E 1.44269504f
#define PITCH 136            /* h tile pitch in floats: banks 8t+g conflict-free */

__device__ float g_hbuf[Bb*Nn*Dd];
__device__ float g_ssrc[Bb*NHEADS*Nn];
__device__ float g_sdst[Bb*NHEADS*Nn];
__device__ float g_tmax[Bb*NHEADS];
__device__ float g_abar[HN*Bb*Ff];

__device__ __forceinline__ float lrelu(float x){ return fmaxf(x, SLOPE*x); }

__device__ __forceinline__ uint32_t tf32_rna(float x){
    uint32_t r;
    asm("cvt.rna.tf32.f32 %0, %1;" : "=r"(r) : "f"(x));
    return r;
}
__device__ __forceinline__ void mma_tf32(float* c,
    uint32_t a0, uint32_t a1, uint32_t a2, uint32_t a3,
    uint32_t b0, uint32_t b1)
{
    asm volatile(
        "mma.sync.aligned.m16n8k8.row.col.f32.tf32.tf32.f32 "
        "{%0,%1,%2,%3}, {%4,%5,%6,%7}, {%8,%9}, {%0,%1,%2,%3};"
        : "+f"(c[0]), "+f"(c[1]), "+f"(c[2]), "+f"(c[3])
        : "r"(a0), "r"(a1), "r"(a2), "r"(a3), "r"(b0), "r"(b1));
}

// ---------------- BN + encoder MLP ----------------
__global__ __launch_bounds__(256) void encoder_kernel(const float* __restrict__ feats,
    const float* __restrict__ gamma, const float* __restrict__ beta,
    const float* __restrict__ mean, const float* __restrict__ var,
    const float* __restrict__ W1, const float* __restrict__ b1,
    const float* __restrict__ W2, const float* __restrict__ b2,
    float* __restrict__ C)
{
    __shared__ float xn[16][Ff];
    __shared__ float hid[16][Dd];
    int tid = threadIdx.x;
    int col = tid & 127, grp = tid >> 7;
    int row0 = blockIdx.x * 16;
    for (int idx = tid; idx < 16*Ff; idx += 256) {
        int r = idx >> 6, f = idx & 63;
        float v = feats[(size_t)(row0+r)*Ff + f];
        xn[r][f] = (v - mean[f]) * rsqrtf(var[f] + 1e-5f) * gamma[f] + beta[f];
    }
    __syncthreads();
    float acc[8];
    float bb = b1[col];
    #pragma unroll
    for (int r=0;r<8;r++) acc[r] = bb;
    #pragma unroll 4
    for (int f=0; f<Ff; f++){
        float w = W1[f*Dd + col];
        #pragma unroll
        for (int r=0;r<8;r++) acc[r] += xn[grp*8+r][f]*w;
    }
    #pragma unroll
    for (int r=0;r<8;r++) hid[grp*8+r][col] = fmaxf(acc[r], 0.f);
    __syncthreads();
    bb = b2[col];
    #pragma unroll
    for (int r=0;r<8;r++) acc[r] = bb;
    #pragma unroll 4
    for (int k=0;k<Dd;k++){
        float w = W2[k*Dd + col];
        #pragma unroll
        for (int r=0;r<8;r++) acc[r] += hid[grp*8+r][k]*w;
    }
    #pragma unroll
    for (int r=0;r<8;r++) C[(size_t)(row0+grp*8+r)*Dd + col] = acc[r];
}

// ---------------- GAT projection: h = X@W (f32, row-major) + s_src/s_dst ----
__global__ __launch_bounds__(256) void gat_proj_kernel(const float* __restrict__ X,
    const float* __restrict__ W, const float* __restrict__ a_src,
    const float* __restrict__ a_dst)
{
    __shared__ float xs[16][Dd];
    int tid = threadIdx.x;
    int col = tid & 127, grp = tid >> 7;
    int row0 = blockIdx.x * 16;
    for (int idx = tid; idx < 16*32; idx += 256){
        int r = idx >> 5, c4 = idx & 31;
        *(float4*)&xs[r][c4*4] = *(const float4*)(X + (size_t)(row0+r)*Dd + c4*4);
    }
    __syncthreads();
    float acc[8];
    #pragma unroll
    for (int r=0;r<8;r++) acc[r]=0.f;
    #pragma unroll 4
    for (int k=0;k<Dd;k++){
        float w = W[k*Dd + col];
        #pragma unroll
        for (int r=0;r<8;r++) acc[r] += xs[grp*8+r][k]*w;
    }
    int head = col >> 5, lane = col & 31;
    float av = a_src[head*DH + lane];
    float bv = a_dst[head*DH + lane];
    #pragma unroll
    for (int r=0;r<8;r++){
        int g = row0 + grp*8 + r;
        g_hbuf[(size_t)g*Dd + col] = acc[r];
        float p = acc[r]*av, q = acc[r]*bv;
        #pragma unroll
        for (int off=16; off; off>>=1){
            p += __shfl_xor_sync(0xffffffffu, p, off);
            q += __shfl_xor_sync(0xffffffffu, q, off);
        }
        if (lane == 0){
            int b = g / Nn, n = g % Nn;
            g_ssrc[(b*NHEADS+head)*Nn + n] = p;
            g_sdst[(b*NHEADS+head)*Nn + n] = q;
        }
    }
}

// ---------------- per-(b,head) max of s_dst ----------------
__global__ void tmax_kernel()
{
    __shared__ float red[256];
    const float* t = g_sdst + blockIdx.x * Nn;
    float m = NEG_INF;
    for (int n = threadIdx.x; n < Nn; n += 256) m = fmaxf(m, t[n]);
    red[threadIdx.x] = m;
    __syncthreads();
    #pragma unroll
    for (int s=128; s; s>>=1){
        if (threadIdx.x < s) red[threadIdx.x] = fmaxf(red[threadIdx.x], red[threadIdx.x+s]);
        __syncthreads();
    }
    if (threadIdx.x == 0) g_tmax[blockIdx.x] = red[0];
}

// ---------------- GAT attention via warp mma.sync tf32 (3-term hi/lo) -------
// 256 thr / 8 warps. Warp w: head=w&3, row-half mh=w>>2 (rows mh*16..+15 of the
// 32-row tile). Lane (g=l>>2, t=l&3) builds A fragments in-register:
//   a0=w[g][k=t], a1=w[g+8][k=t], a2=w[g][k=t+4], a3=w[g+8][k=t+4]
// B fragment (k8 x n8): b0=h[k=t][n=g], b1=h[k=t+4][n=g], plain LDS.
// C: c0=C[g][2t], c1=C[g][2t+1], c2=C[g+8][2t], c3=C[g+8][2t+1].
#define SM_HHI 0
#define SM_HLO (TJ*PITCH)
#define SM_T   (2*TJ*PITCH)
#define SM_MB  (2*TJ*PITCH + NHEADS*TJ)
#define SM_FLOATS (2*TJ*PITCH + NHEADS*TJ + 64)

__global__ __launch_bounds__(256) void gat_attn_tc(const int* __restrict__ mask,
    const float* __restrict__ Cin, float* __restrict__ Hout, float* __restrict__ Cbar)
{
    extern __shared__ float sm[];
    float* h_hi = sm + SM_HHI;
    float* h_lo = sm + SM_HLO;
    float* t_tile = sm + SM_T;
    unsigned long long* m_bits = (unsigned long long*)(sm + SM_MB);

    int tid = threadIdx.x;
    int w = tid >> 5, lane = tid & 31;
    int h = w & 3, mh = w >> 2;
    int g = lane >> 2, t = lane & 3;
    int b  = blockIdx.x / NTILES;
    int i0 = (blockIdx.x % NTILES) * 32;
    int il0 = mh*16 + g, il1 = il0 + 8;
    int gi0 = i0 + il0, gi1 = i0 + il1;

    float tmx = g_tmax[b*NHEADS + h];
    float s0 = (gi0 < Nn) ? g_ssrc[(b*NHEADS+h)*Nn + gi0] : 0.f;
    float s1 = (gi1 < Nn) ? g_ssrc[(b*NHEADS+h)*Nn + gi1] : 0.f;
    float m20 = lrelu(s0 + tmx) * LOG2E;
    float m21 = lrelu(s1 + tmx) * LOG2E;
    float lv0 = 0.f, lv1 = 0.f;
    float acc[4][4];
    #pragma unroll
    for (int nt=0;nt<4;nt++){ acc[nt][0]=0.f; acc[nt][1]=0.f; acc[nt][2]=0.f; acc[nt][3]=0.f; }

    const float* hb = g_hbuf + (size_t)b*Nn*Dd;
    const int* mrow = mask + (size_t)b*Nn*Nn + (size_t)i0*Nn;

    // per-thread mask fill coords
    int mr = tid >> 3, moct = tid & 7;

    for (int c = 0; c < NCHUNK; c++){
        int j0 = c * TJ;
        __syncthreads();
        // h tile fill: 64 j x 32 float4, cvt to tf32 hi + residual lo
        for (int idx = tid; idx < TJ*32; idx += 256){
            int jj = idx >> 5, c4 = idx & 31;
            float4 v = make_float4(0.f,0.f,0.f,0.f);
            if (j0 + jj < Nn) v = *(const float4*)(hb + (size_t)(j0+jj)*Dd + c4*4);
            float4 hi, lo;
            hi.x = __uint_as_float(tf32_rna(v.x)); lo.x = v.x - hi.x;
            hi.y = __uint_as_float(tf32_rna(v.y)); lo.y = v.y - hi.y;
            hi.z = __uint_as_float(tf32_rna(v.z)); lo.z = v.z - hi.z;
            hi.w = __uint_as_float(tf32_rna(v.w)); lo.w = v.w - hi.w;
            *(float4*)&h_hi[jj*PITCH + c4*4] = hi;
            *(float4*)&h_lo[jj*PITCH + c4*4] = lo;
        }
        // t tile: 4 heads x 64 j
        {
            int hh = tid >> 6, jj = tid & 63;
            t_tile[hh*TJ + jj] = (j0+jj < Nn) ? g_sdst[(b*NHEADS+hh)*Nn + j0+jj] : 0.f;
        }
        // mask bits: row mr (0..31), 8 j per thread -> one byte
        {
            unsigned int byte = 0;
            int j = j0 + moct*8;
            if (i0 + mr < Nn){
                const int* p = mrow + (size_t)mr*Nn + j;
                if (j + 7 < Nn){
                    int4 A = *(const int4*)p;
                    int4 Bv = *(const int4*)(p+4);
                    byte = (unsigned)(A.x!=0) | ((unsigned)(A.y!=0)<<1)
                         | ((unsigned)(A.z!=0)<<2) | ((unsigned)(A.w!=0)<<3)
                         | ((unsigned)(Bv.x!=0)<<4) | ((unsigned)(Bv.y!=0)<<5)
                         | ((unsigned)(Bv.z!=0)<<6) | ((unsigned)(Bv.w!=0)<<7);
                } else {
                    #pragma unroll
                    for (int k=0;k<8;k++)
                        if (j+k < Nn && p[k] != 0) byte |= (1u<<k);
                }
            }
            ((unsigned char*)m_bits)[mr*8 + moct] = (unsigned char)byte;
        }
        __syncthreads();

        unsigned long long bits0 = m_bits[il0];
        unsigned long long bits1 = m_bits[il1];

        #pragma unroll
        for (int s=0; s<8; s++){
            int ja = s*8 + t, jb = ja + 4;
            float ta = t_tile[h*TJ + ja];
            float tb = t_tile[h*TJ + jb];
            float e00 = lrelu(s0 + ta), e01 = lrelu(s0 + tb);
            float e10 = lrelu(s1 + ta), e11 = lrelu(s1 + tb);
            float w00 = ((bits0 >> ja) & 1ull) ? exp2f(fmaf(e00, LOG2E, -m20)) : 0.f;
            float w01 = ((bits0 >> jb) & 1ull) ? exp2f(fmaf(e01, LOG2E, -m20)) : 0.f;
            float w10 = ((bits1 >> ja) & 1ull) ? exp2f(fmaf(e10, LOG2E, -m21)) : 0.f;
            float w11 = ((bits1 >> jb) & 1ull) ? exp2f(fmaf(e11, LOG2E, -m21)) : 0.f;
            lv0 += w00 + w01;
            lv1 += w10 + w11;
            // A fragments: hi + residual lo
            uint32_t ah0 = tf32_rna(w00), ah1 = tf32_rna(w10);
            uint32_t ah2 = tf32_rna(w01), ah3 = tf32_rna(w11);
            uint32_t al0 = tf32_rna(w00 - __uint_as_float(ah0));
            uint32_t al1 = tf32_rna(w10 - __uint_as_float(ah1));
            uint32_t al2 = tf32_rna(w01 - __uint_as_float(ah2));
            uint32_t al3 = tf32_rna(w11 - __uint_as_float(ah3));
            // B base rows: k = s*8 + t (b0) and +4 (b1); n = h*32 + nt*8 + g
            int r0 = (s*8 + t)*PITCH + h*32 + g;
            int r1 = r0 + 4*PITCH;
            #pragma unroll
            for (int nt=0; nt<4; nt++){
                uint32_t bh0 = __float_as_uint(h_hi[r0 + nt*8]);
                uint32_t bh1 = __float_as_uint(h_hi[r1 + nt*8]);
                uint32_t bl0 = __float_as_uint(h_lo[r0 + nt*8]);
                uint32_t bl1 = __float_as_uint(h_lo[r1 + nt*8]);
                mma_tf32(acc[nt], ah0, ah1, ah2, ah3, bh0, bh1);
                mma_tf32(acc[nt], ah0, ah1, ah2, ah3, bl0, bl1);
                mma_tf32(acc[nt], al0, al1, al2, al3, bh0, bh1);
            }
        }
    }

    // lv: reduce over the 4 lanes of the quad (t bits = lane bits 0,1)
    lv0 += __shfl_xor_sync(0xffffffffu, lv0, 1);
    lv0 += __shfl_xor_sync(0xffffffffu, lv0, 2);
    lv1 += __shfl_xor_sync(0xffffffffu, lv1, 1);
    lv1 += __shfl_xor_sync(0xffffffffu, lv1, 2);
    float inv0 = 1.f / lv0;
    float inv1 = 1.f / lv1;

    // epilogue: lane writes (rows gi0, gi1) x (cols d0, d0+1) per nt
    #pragma unroll
    for (int nt=0; nt<4; nt++){
        int d0 = h*32 + nt*8 + 2*t;
        if (gi0 < Nn){
            size_t x = ((size_t)(b*Nn + gi0))*Dd + d0;
            float o0 = acc[nt][0]*inv0, o1 = acc[nt][1]*inv0;
            float2 ci = *(const float2*)(Cin + x);
            *(float2*)(Hout + x) = make_float2(o0, o1);
            *(float2*)(Cbar + x) = make_float2(ci.x - o0, ci.y - o1);
        }
        if (gi1 < Nn){
            size_t x = ((size_t)(b*Nn + gi1))*Dd + d0;
            float o2 = acc[nt][2]*inv1, o3 = acc[nt][3]*inv1;
            float2 ci = *(const float2*)(Cin + x);
            *(float2*)(Hout + x) = make_float2(o2, o3);
            *(float2*)(Cbar + x) = make_float2(ci.x - o2, ci.y - o3);
        }
    }
}

// ---------------- per-horizon deep factor heads ----------------
__global__ void factors_kernel(const float* __restrict__ Cc,
    const float* __restrict__ Cbi, const float* __restrict__ Cbu,
    const float* __restrict__ hW, const float* __restrict__ hb,
    float* __restrict__ out)
{
    int w = threadIdx.x >> 5, lane = threadIdx.x & 31;
    int r = blockIdx.x*4 + w;
    if (r >= Bb*Nn) return;
    float a0=0.f, a1=0.f, a2=0.f;
    #pragma unroll
    for (int it=0; it<12; it++){
        int idx = it*32 + lane;
        const float* src = (idx < 128) ? Cc : (idx < 256 ? Cbi : Cbu);
        int c = idx & 127;
        float v = src[(size_t)r*Dd + c];
        a0 += v*hW[0*DEEP+idx];
        a1 += v*hW[1*DEEP+idx];
        a2 += v*hW[2*DEEP+idx];
    }
    #pragma unroll
    for (int off=16; off; off>>=1){
        a0 += __shfl_xor_sync(0xffffffffu, a0, off);
        a1 += __shfl_xor_sync(0xffffffffu, a1, off);
        a2 += __shfl_xor_sync(0xffffffffu, a2, off);
    }
    if (lane==0){
        out[0*Bb*Nn + r] = lrelu(a0 + hb[0]);
        out[1*Bb*Nn + r] = lrelu(a1 + hb[1]);
        out[2*Bb*Nn + r] = lrelu(a2 + hb[2]);
    }
}

// ---------------- factor attention: U -> A ----------------
__global__ void fa_kernel(const float* __restrict__ feats,
    const float* __restrict__ projW, float* __restrict__ A)
{
    __shared__ float pw[64][65];
    __shared__ float ft[64][64];
    int tid = threadIdx.x;
    int ntile = blockIdx.x & 31;
    int hb_   = blockIdx.x >> 5;
    int hn = hb_ >> 1, b = hb_ & 1;
    int n0 = ntile*64;
    const float* P = projW + (size_t)hn*64*64;
    for (int idx=tid; idx<4096; idx+=256) pw[idx>>6][idx&63] = P[idx];
    for (int idx=tid; idx<4096; idx+=256){
        int r=idx>>6, m=idx&63; int n=n0+r;
        ft[r][m] = (n<Nn) ? feats[((size_t)(b*Nn+n))*Ff+m] : 0.f;
    }
    __syncthreads();
    int w = tid>>5, lane = tid&31;
    for (int rr=0; rr<8; rr++){
        int r = w*8+rr; int n=n0+r;
        if (n>=Nn) continue;
        float u0=0.f,u1=0.f;
        #pragma unroll
        for (int m=0;m<64;m++){
            float f = ft[r][m];
            u0 += f*pw[lane][m];
            u1 += f*pw[lane+32][m];
        }
        u0 = lrelu(u0); u1 = lrelu(u1);
        float mx = fmaxf(u0,u1);
        #pragma unroll
        for (int off=16; off; off>>=1)
            mx = fmaxf(mx, __shfl_xor_sync(0xffffffffu, mx, off));
        float e0 = __expf(u0-mx), e1 = __expf(u1-mx);
        float ss = e0+e1;
        #pragma unroll
        for (int off=16; off; off>>=1)
            ss += __shfl_xor_sync(0xffffffffu, ss, off);
        float inv = 1.f/ss;
        size_t base = ((size_t)hb_*Nn + n)*64;
        A[base+lane]    = e0*inv;
        A[base+lane+32] = e1*inv;
    }
}

// ---------------- a_bar = A.mean(axis=n) ----------------
__global__ void abar_kernel(const float* __restrict__ A)
{
    __shared__ float red[8][64];
    int tid=threadIdx.x; int k=tid&63, grp=tid>>6;
    const float* base = A + (size_t)blockIdx.x*Nn*64;
    float s=0.f;
    for (int n=grp; n<Nn; n+=8) s += base[(size_t)n*64+k];
    red[grp][k]=s;
    __syncthreads();
    if (grp==0){
        float t=0.f;
        #pragma unroll
        for (int g=0; g<8; g++) t += red[g][k];
        g_abar[blockIdx.x*64+k] = t * (1.f/Nn);
    }
}

// ---------------- recon = feats @ a_bar ----------------
__global__ void recon_kernel(const float* __restrict__ feats, float* __restrict__ out)
{
    int w = threadIdx.x>>5, lane=threadIdx.x&31;
    int ro = blockIdx.x*8 + w;
    if (ro >= HN*Bb*Nn) return;
    int hn = ro / (Bb*Nn);
    int rem = ro % (Bb*Nn);
    int b = rem / Nn, n = rem % Nn;
    const float* f  = feats  + (size_t)(b*Nn+n)*Ff;
    const float* ab = g_abar + (hn*Bb+b)*Ff;
    float p = f[lane]*ab[lane] + f[lane+32]*ab[lane+32];
    #pragma unroll
    for (int off=16; off; off>>=1)
        p += __shfl_xor_sync(0xffffffffu, p, off);
    if (lane==0) out[ro] = p;
}

extern "C" void kernel_launch(void* const* d_in, const int* in_sizes, int n_in,
                              void* d_out, int out_size)
{
    const float* feats = (const float*)d_in[0];
    const int* ind = (const int*)d_in[1];
    const int* uni = (const int*)d_in[2];
    const float* bn_g = (const float*)d_in[3];
    const float* bn_b = (const float*)d_in[4];
    const float* bn_m = (const float*)d_in[5];
    const float* bn_v = (const float*)d_in[6];
    const float* W1   = (const float*)d_in[7];
    const float* b1   = (const float*)d_in[8];
    const float* W2   = (const float*)d_in[9];
    const float* b2   = (const float*)d_in[10];
    const float* giW  = (const float*)d_in[11];
    const float* gias = (const float*)d_in[12];
    const float* giad = (const float*)d_in[13];
    const float* guW  = (const float*)d_in[14];
    const float* guas = (const float*)d_in[15];
    const float* guad = (const float*)d_in[16];
    const float* hW   = (const float*)d_in[17];
    const float* hb   = (const float*)d_in[18];
    const float* pW   = (const float*)d_in[19];

    float* out  = (float*)d_out;
    float* C    = out;
    float* CBI  = out + 512000;
    float* CBU  = out + 1024000;
    float* HI   = out + 1536000;
    float* HU   = out + 2048000;
    float* FOUT = out + 2560000;
    float* ROUT = out + 2572000;
    float* AOUT = out + 2584000;

    static int smem_set = 0;
    const int smem_bytes = SM_FLOATS * 4;
    if (!smem_set){
        cudaFuncSetAttribute(gat_attn_tc,
            cudaFuncAttributeMaxDynamicSharedMemorySize, smem_bytes);
        smem_set = 1;
    }

    encoder_kernel<<<250,256>>>(feats, bn_g, bn_b, bn_m, bn_v, W1, b1, W2, b2, C);

    gat_proj_kernel<<<250,256>>>(C, giW, gias, giad);
    tmax_kernel<<<8,256>>>();
    gat_attn_tc<<<Bb*NTILES,256,smem_bytes>>>(ind, C, HI, CBI);

    gat_proj_kernel<<<250,256>>>(CBI, guW, guas, guad);
    tmax_kernel<<<8,256>>>();
    gat_attn_tc<<<Bb*NTILES,256,smem_bytes>>>(uni, CBI, HU, CBU);

    factors_kernel<<<1000,128>>>(C, CBI, CBU, hW, hb, FOUT);

    fa_kernel<<<192,256>>>(feats, pW, AOUT);
    abar_kernel<<<6,512>>>(AOUT);
    recon_kernel<<<1500,256>>>(feats, ROUT);
}

// round 8
// speedup vs baseline: 1.4366x; 1.4366x over previous
#include <cuda_runtime.h>
#include <cstdint>

#define Bb 2
#define Nn 2000
#define Ff 64
#define Dd 128
#define NHEADS 4
#define DH 32
#define HN 3
#define DEEP 384
#define SLOPE 0.1f
#define NEG_INF -1e30f
#define TJ 64
#define NTILES 63            /* ceil(2000/32) */
#define NCHUNK 32            /* 32*64 = 2048 >= 2000 */
#define SPLITS 4
#define CPS (NCHUNK/SPLITS)  /* chunks per split = 8 */
#define LOG2E 1.44269504f
#define PITCH 136

__device__ float g_hbuf[Bb*Nn*Dd];
__device__ float g_ssrc[Bb*NHEADS*Nn];
__device__ float g_sdst[Bb*NHEADS*Nn];
__device__ float g_tmax[Bb*NHEADS];
__device__ float g_abar[HN*Bb*Ff];
__device__ float g_pacc[SPLITS][Bb*Nn*Dd];
__device__ float g_plv[SPLITS][Bb*NHEADS*Nn];

__device__ __forceinline__ float lrelu(float x){ return fmaxf(x, SLOPE*x); }

__device__ __forceinline__ uint32_t tf32_rna(float x){
    uint32_t r;
    asm("cvt.rna.tf32.f32 %0, %1;" : "=r"(r) : "f"(x));
    return r;
}
__device__ __forceinline__ void mma_tf32(float* c,
    uint32_t a0, uint32_t a1, uint32_t a2, uint32_t a3,
    uint32_t b0, uint32_t b1)
{
    asm volatile(
        "mma.sync.aligned.m16n8k8.row.col.f32.tf32.tf32.f32 "
        "{%0,%1,%2,%3}, {%4,%5,%6,%7}, {%8,%9}, {%0,%1,%2,%3};"
        : "+f"(c[0]), "+f"(c[1]), "+f"(c[2]), "+f"(c[3])
        : "r"(a0), "r"(a1), "r"(a2), "r"(a3), "r"(b0), "r"(b1));
}

// ---------------- BN + encoder MLP ----------------
__global__ __launch_bounds__(256) void encoder_kernel(const float* __restrict__ feats,
    const float* __restrict__ gamma, const float* __restrict__ beta,
    const float* __restrict__ mean, const float* __restrict__ var,
    const float* __restrict__ W1, const float* __restrict__ b1,
    const float* __restrict__ W2, const float* __restrict__ b2,
    float* __restrict__ C)
{
    __shared__ float xn[16][Ff];
    __shared__ float hid[16][Dd];
    int tid = threadIdx.x;
    int col = tid & 127, grp = tid >> 7;
    int row0 = blockIdx.x * 16;
    for (int idx = tid; idx < 16*Ff; idx += 256) {
        int r = idx >> 6, f = idx & 63;
        float v = feats[(size_t)(row0+r)*Ff + f];
        xn[r][f] = (v - mean[f]) * rsqrtf(var[f] + 1e-5f) * gamma[f] + beta[f];
    }
    __syncthreads();
    float acc[8];
    float bb = b1[col];
    #pragma unroll
    for (int r=0;r<8;r++) acc[r] = bb;
    #pragma unroll 4
    for (int f=0; f<Ff; f++){
        float w = W1[f*Dd + col];
        #pragma unroll
        for (int r=0;r<8;r++) acc[r] += xn[grp*8+r][f]*w;
    }
    #pragma unroll
    for (int r=0;r<8;r++) hid[grp*8+r][col] = fmaxf(acc[r], 0.f);
    __syncthreads();
    bb = b2[col];
    #pragma unroll
    for (int r=0;r<8;r++) acc[r] = bb;
    #pragma unroll 4
    for (int k=0;k<Dd;k++){
        float w = W2[k*Dd + col];
        #pragma unroll
        for (int r=0;r<8;r++) acc[r] += hid[grp*8+r][k]*w;
    }
    #pragma unroll
    for (int r=0;r<8;r++) C[(size_t)(row0+grp*8+r)*Dd + col] = acc[r];
}

// ---------------- GAT projection ----------------
__global__ __launch_bounds__(256) void gat_proj_kernel(const float* __restrict__ X,
    const float* __restrict__ W, const float* __restrict__ a_src,
    const float* __restrict__ a_dst)
{
    __shared__ float xs[16][Dd];
    int tid = threadIdx.x;
    int col = tid & 127, grp = tid >> 7;
    int row0 = blockIdx.x * 16;
    for (int idx = tid; idx < 16*32; idx += 256){
        int r = idx >> 5, c4 = idx & 31;
        *(float4*)&xs[r][c4*4] = *(const float4*)(X + (size_t)(row0+r)*Dd + c4*4);
    }
    __syncthreads();
    float acc[8];
    #pragma unroll
    for (int r=0;r<8;r++) acc[r]=0.f;
    #pragma unroll 4
    for (int k=0;k<Dd;k++){
        float w = W[k*Dd + col];
        #pragma unroll
        for (int r=0;r<8;r++) acc[r] += xs[grp*8+r][k]*w;
    }
    int head = col >> 5, lane = col & 31;
    float av = a_src[head*DH + lane];
    float bv = a_dst[head*DH + lane];
    #pragma unroll
    for (int r=0;r<8;r++){
        int g = row0 + grp*8 + r;
        g_hbuf[(size_t)g*Dd + col] = acc[r];
        float p = acc[r]*av, q = acc[r]*bv;
        #pragma unroll
        for (int off=16; off; off>>=1){
            p += __shfl_xor_sync(0xffffffffu, p, off);
            q += __shfl_xor_sync(0xffffffffu, q, off);
        }
        if (lane == 0){
            int b = g / Nn, n = g % Nn;
            g_ssrc[(b*NHEADS+head)*Nn + n] = p;
            g_sdst[(b*NHEADS+head)*Nn + n] = q;
        }
    }
}

// ---------------- per-(b,head) max of s_dst ----------------
__global__ void tmax_kernel()
{
    __shared__ float red[256];
    const float* t = g_sdst + blockIdx.x * Nn;
    float m = NEG_INF;
    for (int n = threadIdx.x; n < Nn; n += 256) m = fmaxf(m, t[n]);
    red[threadIdx.x] = m;
    __syncthreads();
    #pragma unroll
    for (int s=128; s; s>>=1){
        if (threadIdx.x < s) red[threadIdx.x] = fmaxf(red[threadIdx.x], red[threadIdx.x+s]);
        __syncthreads();
    }
    if (threadIdx.x == 0) g_tmax[blockIdx.x] = red[0];
}

// ---------------- GAT attention: tf32 mma.sync, j-split partials ------------
// grid = Bb*NTILES*SPLITS. blockIdx: split = x%SPLITS; tile/(b) above.
// Warp w: head=w&3, row-half mh=w>>2. Lane (g=l>>2, t=l&3).
// Writes UNNORMALIZED acc to g_pacc[split] and per-row lv to g_plv[split].
#define SM_HHI 0
#define SM_HLO (TJ*PITCH)
#define SM_T   (2*TJ*PITCH)
#define SM_MB  (2*TJ*PITCH + NHEADS*TJ)
#define SM_FLOATS (2*TJ*PITCH + NHEADS*TJ + 64)

__global__ __launch_bounds__(256) void gat_attn_tc(const int* __restrict__ mask)
{
    extern __shared__ float sm[];
    float* h_hi = sm + SM_HHI;
    float* h_lo = sm + SM_HLO;
    float* t_tile = sm + SM_T;
    unsigned long long* m_bits = (unsigned long long*)(sm + SM_MB);

    int tid = threadIdx.x;
    int w = tid >> 5, lane = tid & 31;
    int h = w & 3, mh = w >> 2;
    int g = lane >> 2, t = lane & 3;
    int split = blockIdx.x % SPLITS;
    int tmp   = blockIdx.x / SPLITS;
    int b     = tmp / NTILES;
    int i0    = (tmp % NTILES) * 32;
    int il0 = mh*16 + g, il1 = il0 + 8;
    int gi0 = i0 + il0, gi1 = i0 + il1;

    float tmx = g_tmax[b*NHEADS + h];
    float s0 = (gi0 < Nn) ? g_ssrc[(b*NHEADS+h)*Nn + gi0] : 0.f;
    float s1 = (gi1 < Nn) ? g_ssrc[(b*NHEADS+h)*Nn + gi1] : 0.f;
    float m20 = lrelu(s0 + tmx) * LOG2E;
    float m21 = lrelu(s1 + tmx) * LOG2E;
    float lv0 = 0.f, lv1 = 0.f;
    float acc[4][4];
    #pragma unroll
    for (int nt=0;nt<4;nt++){ acc[nt][0]=0.f; acc[nt][1]=0.f; acc[nt][2]=0.f; acc[nt][3]=0.f; }

    const float* hb = g_hbuf + (size_t)b*Nn*Dd;
    const int* mrow = mask + (size_t)b*Nn*Nn + (size_t)i0*Nn;
    int mr = tid >> 3, moct = tid & 7;

    int c0 = split * CPS;
    for (int c = c0; c < c0 + CPS; c++){
        int j0 = c * TJ;
        __syncthreads();
        // h tile fill: tf32 hi + residual lo
        for (int idx = tid; idx < TJ*32; idx += 256){
            int jj = idx >> 5, c4 = idx & 31;
            float4 v = make_float4(0.f,0.f,0.f,0.f);
            if (j0 + jj < Nn) v = *(const float4*)(hb + (size_t)(j0+jj)*Dd + c4*4);
            float4 hi, lo;
            hi.x = __uint_as_float(tf32_rna(v.x)); lo.x = v.x - hi.x;
            hi.y = __uint_as_float(tf32_rna(v.y)); lo.y = v.y - hi.y;
            hi.z = __uint_as_float(tf32_rna(v.z)); lo.z = v.z - hi.z;
            hi.w = __uint_as_float(tf32_rna(v.w)); lo.w = v.w - hi.w;
            *(float4*)&h_hi[jj*PITCH + c4*4] = hi;
            *(float4*)&h_lo[jj*PITCH + c4*4] = lo;
        }
        // t tile
        {
            int hh = tid >> 6, jj = tid & 63;
            t_tile[hh*TJ + jj] = (j0+jj < Nn) ? g_sdst[(b*NHEADS+hh)*Nn + j0+jj] : 0.f;
        }
        // mask bits
        {
            unsigned int byte = 0;
            int j = j0 + moct*8;
            if (i0 + mr < Nn){
                const int* p = mrow + (size_t)mr*Nn + j;
                if (j + 7 < Nn){
                    int4 A = *(const int4*)p;
                    int4 Bv = *(const int4*)(p+4);
                    byte = (unsigned)(A.x!=0) | ((unsigned)(A.y!=0)<<1)
                         | ((unsigned)(A.z!=0)<<2) | ((unsigned)(A.w!=0)<<3)
                         | ((unsigned)(Bv.x!=0)<<4) | ((unsigned)(Bv.y!=0)<<5)
                         | ((unsigned)(Bv.z!=0)<<6) | ((unsigned)(Bv.w!=0)<<7);
                } else {
                    #pragma unroll
                    for (int k=0;k<8;k++)
                        if (j+k < Nn && p[k] != 0) byte |= (1u<<k);
                }
            }
            ((unsigned char*)m_bits)[mr*8 + moct] = (unsigned char)byte;
        }
        __syncthreads();

        unsigned long long bits0 = m_bits[il0];
        unsigned long long bits1 = m_bits[il1];

        #pragma unroll
        for (int s=0; s<8; s++){
            int ja = s*8 + t, jb = ja + 4;
            float ta = t_tile[h*TJ + ja];
            float tb = t_tile[h*TJ + jb];
            float e00 = lrelu(s0 + ta), e01 = lrelu(s0 + tb);
            float e10 = lrelu(s1 + ta), e11 = lrelu(s1 + tb);
            float w00 = ((bits0 >> ja) & 1ull) ? exp2f(fmaf(e00, LOG2E, -m20)) : 0.f;
            float w01 = ((bits0 >> jb) & 1ull) ? exp2f(fmaf(e01, LOG2E, -m20)) : 0.f;
            float w10 = ((bits1 >> ja) & 1ull) ? exp2f(fmaf(e10, LOG2E, -m21)) : 0.f;
            float w11 = ((bits1 >> jb) & 1ull) ? exp2f(fmaf(e11, LOG2E, -m21)) : 0.f;
            lv0 += w00 + w01;
            lv1 += w10 + w11;
            uint32_t ah0 = tf32_rna(w00), ah1 = tf32_rna(w10);
            uint32_t ah2 = tf32_rna(w01), ah3 = tf32_rna(w11);
            uint32_t al0 = tf32_rna(w00 - __uint_as_float(ah0));
            uint32_t al1 = tf32_rna(w10 - __uint_as_float(ah1));
            uint32_t al2 = tf32_rna(w01 - __uint_as_float(ah2));
            uint32_t al3 = tf32_rna(w11 - __uint_as_float(ah3));
            int r0 = (s*8 + t)*PITCH + h*32 + g;
            int r1 = r0 + 4*PITCH;
            #pragma unroll
            for (int nt=0; nt<4; nt++){
                uint32_t bh0 = __float_as_uint(h_hi[r0 + nt*8]);
                uint32_t bh1 = __float_as_uint(h_hi[r1 + nt*8]);
                uint32_t bl0 = __float_as_uint(h_lo[r0 + nt*8]);
                uint32_t bl1 = __float_as_uint(h_lo[r1 + nt*8]);
                mma_tf32(acc[nt], ah0, ah1, ah2, ah3, bh0, bh1);
                mma_tf32(acc[nt], ah0, ah1, ah2, ah3, bl0, bl1);
                mma_tf32(acc[nt], al0, al1, al2, al3, bh0, bh1);
            }
        }
    }

    // lv: reduce over t within quad
    lv0 += __shfl_xor_sync(0xffffffffu, lv0, 1);
    lv0 += __shfl_xor_sync(0xffffffffu, lv0, 2);
    lv1 += __shfl_xor_sync(0xffffffffu, lv1, 1);
    lv1 += __shfl_xor_sync(0xffffffffu, lv1, 2);
    if (t == 0){
        if (gi0 < Nn) g_plv[split][(b*NHEADS+h)*Nn + gi0] = lv0;
        if (gi1 < Nn) g_plv[split][(b*NHEADS+h)*Nn + gi1] = lv1;
    }

    // write unnormalized partials
    float* pac = g_pacc[split];
    #pragma unroll
    for (int nt=0; nt<4; nt++){
        int d0 = h*32 + nt*8 + 2*t;
        if (gi0 < Nn){
            size_t x = ((size_t)(b*Nn + gi0))*Dd + d0;
            *(float2*)(pac + x) = make_float2(acc[nt][0], acc[nt][1]);
        }
        if (gi1 < Nn){
            size_t x = ((size_t)(b*Nn + gi1))*Dd + d0;
            *(float2*)(pac + x) = make_float2(acc[nt][2], acc[nt][3]);
        }
    }
}

// ---------------- combine partials: H = sum(acc)/sum(lv), Cbar = C - H ------
__global__ __launch_bounds__(256) void gat_combine(const float* __restrict__ Cin,
    float* __restrict__ Hout, float* __restrict__ Cbar)
{
    int gi  = blockIdx.x*2 + (threadIdx.x >> 7);   // 0..3999
    int col = threadIdx.x & 127;
    if (gi >= Bb*Nn) return;
    int b = gi / Nn, i = gi % Nn;
    int head = col >> 5;
    size_t x = (size_t)gi*Dd + col;
    float a = 0.f, lv = 0.f;
    #pragma unroll
    for (int s=0;s<SPLITS;s++){
        a  += g_pacc[s][x];
        lv += g_plv[s][(b*NHEADS+head)*Nn + i];
    }
    float o = a / lv;
    Hout[x] = o;
    Cbar[x] = Cin[x] - o;
}

// ---------------- per-horizon deep factor heads ----------------
__global__ void factors_kernel(const float* __restrict__ Cc,
    const float* __restrict__ Cbi, const float* __restrict__ Cbu,
    const float* __restrict__ hW, const float* __restrict__ hb,
    float* __restrict__ out)
{
    int w = threadIdx.x >> 5, lane = threadIdx.x & 31;
    int r = blockIdx.x*4 + w;
    if (r >= Bb*Nn) return;
    float a0=0.f, a1=0.f, a2=0.f;
    #pragma unroll
    for (int it=0; it<12; it++){
        int idx = it*32 + lane;
        const float* src = (idx < 128) ? Cc : (idx < 256 ? Cbi : Cbu);
        int c = idx & 127;
        float v = src[(size_t)r*Dd + c];
        a0 += v*hW[0*DEEP+idx];
        a1 += v*hW[1*DEEP+idx];
        a2 += v*hW[2*DEEP+idx];
    }
    #pragma unroll
    for (int off=16; off; off>>=1){
        a0 += __shfl_xor_sync(0xffffffffu, a0, off);
        a1 += __shfl_xor_sync(0xffffffffu, a1, off);
        a2 += __shfl_xor_sync(0xffffffffu, a2, off);
    }
    if (lane==0){
        out[0*Bb*Nn + r] = lrelu(a0 + hb[0]);
        out[1*Bb*Nn + r] = lrelu(a1 + hb[1]);
        out[2*Bb*Nn + r] = lrelu(a2 + hb[2]);
    }
}

// ---------------- factor attention: U -> A ----------------
__global__ void fa_kernel(const float* __restrict__ feats,
    const float* __restrict__ projW, float* __restrict__ A)
{
    __shared__ float pw[64][65];
    __shared__ float ft[64][64];
    int tid = threadIdx.x;
    int ntile = blockIdx.x & 31;
    int hb_   = blockIdx.x >> 5;
    int hn = hb_ >> 1, b = hb_ & 1;
    int n0 = ntile*64;
    const float* P = projW + (size_t)hn*64*64;
    for (int idx=tid; idx<4096; idx+=256) pw[idx>>6][idx&63] = P[idx];
    for (int idx=tid; idx<4096; idx+=256){
        int r=idx>>6, m=idx&63; int n=n0+r;
        ft[r][m] = (n<Nn) ? feats[((size_t)(b*Nn+n))*Ff+m] : 0.f;
    }
    __syncthreads();
    int w = tid>>5, lane = tid&31;
    for (int rr=0; rr<8; rr++){
        int r = w*8+rr; int n=n0+r;
        if (n>=Nn) continue;
        float u0=0.f,u1=0.f;
        #pragma unroll
        for (int m=0;m<64;m++){
            float f = ft[r][m];
            u0 += f*pw[lane][m];
            u1 += f*pw[lane+32][m];
        }
        u0 = lrelu(u0); u1 = lrelu(u1);
        float mx = fmaxf(u0,u1);
        #pragma unroll
        for (int off=16; off; off>>=1)
            mx = fmaxf(mx, __shfl_xor_sync(0xffffffffu, mx, off));
        float e0 = __expf(u0-mx), e1 = __expf(u1-mx);
        float ss = e0+e1;
        #pragma unroll
        for (int off=16; off; off>>=1)
            ss += __shfl_xor_sync(0xffffffffu, ss, off);
        float inv = 1.f/ss;
        size_t base = ((size_t)hb_*Nn + n)*64;
        A[base+lane]    = e0*inv;
        A[base+lane+32] = e1*inv;
    }
}

// ---------------- a_bar = A.mean(axis=n) ----------------
__global__ void abar_kernel(const float* __restrict__ A)
{
    __shared__ float red[8][64];
    int tid=threadIdx.x; int k=tid&63, grp=tid>>6;
    const float* base = A + (size_t)blockIdx.x*Nn*64;
    float s=0.f;
    for (int n=grp; n<Nn; n+=8) s += base[(size_t)n*64+k];
    red[grp][k]=s;
    __syncthreads();
    if (grp==0){
        float t=0.f;
        #pragma unroll
        for (int g=0; g<8; g++) t += red[g][k];
        g_abar[blockIdx.x*64+k] = t * (1.f/Nn);
    }
}

// ---------------- recon = feats @ a_bar ----------------
__global__ void recon_kernel(const float* __restrict__ feats, float* __restrict__ out)
{
    int w = threadIdx.x>>5, lane=threadIdx.x&31;
    int ro = blockIdx.x*8 + w;
    if (ro >= HN*Bb*Nn) return;
    int hn = ro / (Bb*Nn);
    int rem = ro % (Bb*Nn);
    int b = rem / Nn, n = rem % Nn;
    const float* f  = feats  + (size_t)(b*Nn+n)*Ff;
    const float* ab = g_abar + (hn*Bb+b)*Ff;
    float p = f[lane]*ab[lane] + f[lane+32]*ab[lane+32];
    #pragma unroll
    for (int off=16; off; off>>=1)
        p += __shfl_xor_sync(0xffffffffu, p, off);
    if (lane==0) out[ro] = p;
}

extern "C" void kernel_launch(void* const* d_in, const int* in_sizes, int n_in,
                              void* d_out, int out_size)
{
    const float* feats = (const float*)d_in[0];
    const int* ind = (const int*)d_in[1];
    const int* uni = (const int*)d_in[2];
    const float* bn_g = (const float*)d_in[3];
    const float* bn_b = (const float*)d_in[4];
    const float* bn_m = (const float*)d_in[5];
    const float* bn_v = (const float*)d_in[6];
    const float* W1   = (const float*)d_in[7];
    const float* b1   = (const float*)d_in[8];
    const float* W2   = (const float*)d_in[9];
    const float* b2   = (const float*)d_in[10];
    const float* giW  = (const float*)d_in[11];
    const float* gias = (const float*)d_in[12];
    const float* giad = (const float*)d_in[13];
    const float* guW  = (const float*)d_in[14];
    const float* guas = (const float*)d_in[15];
    const float* guad = (const float*)d_in[16];
    const float* hW   = (const float*)d_in[17];
    const float* hb   = (const float*)d_in[18];
    const float* pW   = (const float*)d_in[19];

    float* out  = (float*)d_out;
    float* C    = out;
    float* CBI  = out + 512000;
    float* CBU  = out + 1024000;
    float* HI   = out + 1536000;
    float* HU   = out + 2048000;
    float* FOUT = out + 2560000;
    float* ROUT = out + 2572000;
    float* AOUT = out + 2584000;

    static int smem_set = 0;
    const int smem_bytes = SM_FLOATS * 4;
    if (!smem_set){
        cudaFuncSetAttribute(gat_attn_tc,
            cudaFuncAttributeMaxDynamicSharedMemorySize, smem_bytes);
        smem_set = 1;
    }

    encoder_kernel<<<250,256>>>(feats, bn_g, bn_b, bn_m, bn_v, W1, b1, W2, b2, C);

    gat_proj_kernel<<<250,256>>>(C, giW, gias, giad);
    tmax_kernel<<<8,256>>>();
    gat_attn_tc<<<Bb*NTILES*SPLITS,256,smem_bytes>>>(ind);
    gat_combine<<<Bb*Nn/2,256>>>(C, HI, CBI);

    gat_proj_kernel<<<250,256>>>(CBI, guW, guas, guad);
    tmax_kernel<<<8,256>>>();
    gat_attn_tc<<<Bb*NTILES*SPLITS,256,smem_bytes>>>(uni);
    gat_combine<<<Bb*Nn/2,256>>>(CBI, HU, CBU);

    factors_kernel<<<1000,128>>>(C, CBI, CBU, hW, hb, FOUT);

    fa_kernel<<<192,256>>>(feats, pW, AOUT);
    abar_kernel<<<6,512>>>(AOUT);
    recon_kernel<<<1500,256>>>(feats, ROUT);
}

// round 9
// speedup vs baseline: 1.6334x; 1.1370x over previous
#include <cuda_runtime.h>
#include <cstdint>

#define Bb 2
#define Nn 2000
#define NP 2048              /* padded rows for g_hi/g_lo */
#define Ff 64
#define Dd 128
#define NHEADS 4
#define DH 32
#define HN 3
#define DEEP 384
#define SLOPE 0.1f
#define NEG_INF -1e30f
#define TJ 64
#define NTILES 63            /* ceil(2000/32) */
#define NCHUNK 32            /* 32*64 = 2048 >= 2000 */
#define SPLITS 4
#define CPS (NCHUNK/SPLITS)
#define LOG2E 1.44269504f
#define PITCH 136

__device__ float g_hi[Bb*NP*Dd];
__device__ float g_lo[Bb*NP*Dd];
__device__ float g_ssrc[Bb*NHEADS*Nn];
__device__ float g_sdst[Bb*NHEADS*Nn];
__device__ float g_tmax[Bb*NHEADS];
__device__ float g_abar[HN*Bb*Ff];
__device__ float g_pacc[SPLITS][Bb*Nn*Dd];
__device__ float g_plv[SPLITS][Bb*NHEADS*Nn];

__device__ __forceinline__ float lrelu(float x){ return fmaxf(x, SLOPE*x); }

__device__ __forceinline__ uint32_t tf32_rna(float x){
    uint32_t r;
    asm("cvt.rna.tf32.f32 %0, %1;" : "=r"(r) : "f"(x));
    return r;
}
__device__ __forceinline__ void mma_tf32(float* c,
    uint32_t a0, uint32_t a1, uint32_t a2, uint32_t a3,
    uint32_t b0, uint32_t b1)
{
    asm volatile(
        "mma.sync.aligned.m16n8k8.row.col.f32.tf32.tf32.f32 "
        "{%0,%1,%2,%3}, {%4,%5,%6,%7}, {%8,%9}, {%0,%1,%2,%3};"
        : "+f"(c[0]), "+f"(c[1]), "+f"(c[2]), "+f"(c[3])
        : "r"(a0), "r"(a1), "r"(a2), "r"(a3), "r"(b0), "r"(b1));
}
__device__ __forceinline__ uint32_t smem_u32(const void* p){
    uint32_t a;
    asm("{ .reg .u64 t; cvta.to.shared.u64 t, %1; cvt.u32.u64 %0, t; }" : "=r"(a) : "l"(p));
    return a;
}
__device__ __forceinline__ void cp16(uint32_t dst, const void* src){
    asm volatile("cp.async.cg.shared.global [%0], [%1], 16;" :: "r"(dst), "l"(src));
}
#define CP_COMMIT() asm volatile("cp.async.commit_group;" ::: "memory")
#define CP_WAIT0()  asm volatile("cp.async.wait_group 0;" ::: "memory")

// ---------------- BN + encoder MLP ----------------
__global__ __launch_bounds__(256) void encoder_kernel(const float* __restrict__ feats,
    const float* __restrict__ gamma, const float* __restrict__ beta,
    const float* __restrict__ mean, const float* __restrict__ var,
    const float* __restrict__ W1, const float* __restrict__ b1,
    const float* __restrict__ W2, const float* __restrict__ b2,
    float* __restrict__ C)
{
    __shared__ float xn[16][Ff];
    __shared__ float hid[16][Dd];
    int tid = threadIdx.x;
    int col = tid & 127, grp = tid >> 7;
    int row0 = blockIdx.x * 16;
    for (int idx = tid; idx < 16*Ff; idx += 256) {
        int r = idx >> 6, f = idx & 63;
        float v = feats[(size_t)(row0+r)*Ff + f];
        xn[r][f] = (v - mean[f]) * rsqrtf(var[f] + 1e-5f) * gamma[f] + beta[f];
    }
    __syncthreads();
    float acc[8];
    float bb = b1[col];
    #pragma unroll
    for (int r=0;r<8;r++) acc[r] = bb;
    #pragma unroll 4
    for (int f=0; f<Ff; f++){
        float w = W1[f*Dd + col];
        #pragma unroll
        for (int r=0;r<8;r++) acc[r] += xn[grp*8+r][f]*w;
    }
    #pragma unroll
    for (int r=0;r<8;r++) hid[grp*8+r][col] = fmaxf(acc[r], 0.f);
    __syncthreads();
    bb = b2[col];
    #pragma unroll
    for (int r=0;r<8;r++) acc[r] = bb;
    #pragma unroll 4
    for (int k=0;k<Dd;k++){
        float w = W2[k*Dd + col];
        #pragma unroll
        for (int r=0;r<8;r++) acc[r] += hid[grp*8+r][k]*w;
    }
    #pragma unroll
    for (int r=0;r<8;r++) C[(size_t)(row0+grp*8+r)*Dd + col] = acc[r];
}

// ---------------- GAT projection: h = X@W -> tf32 hi/lo + s_src/s_dst -------
__global__ __launch_bounds__(256) void gat_proj_kernel(const float* __restrict__ X,
    const float* __restrict__ W, const float* __restrict__ a_src,
    const float* __restrict__ a_dst)
{
    __shared__ float xs[16][Dd];
    int tid = threadIdx.x;
    int col = tid & 127, grp = tid >> 7;
    int row0 = blockIdx.x * 16;
    for (int idx = tid; idx < 16*32; idx += 256){
        int r = idx >> 5, c4 = idx & 31;
        *(float4*)&xs[r][c4*4] = *(const float4*)(X + (size_t)(row0+r)*Dd + c4*4);
    }
    __syncthreads();
    float acc[8];
    #pragma unroll
    for (int r=0;r<8;r++) acc[r]=0.f;
    #pragma unroll 4
    for (int k=0;k<Dd;k++){
        float w = W[k*Dd + col];
        #pragma unroll
        for (int r=0;r<8;r++) acc[r] += xs[grp*8+r][k]*w;
    }
    int head = col >> 5, lane = col & 31;
    float av = a_src[head*DH + lane];
    float bv = a_dst[head*DH + lane];
    #pragma unroll
    for (int r=0;r<8;r++){
        int g = row0 + grp*8 + r;
        int b = g / Nn, n = g % Nn;
        uint32_t hv = tf32_rna(acc[r]);
        float lov = acc[r] - __uint_as_float(hv);
        size_t x = ((size_t)(b*NP + n))*Dd + col;
        g_hi[x] = __uint_as_float(hv);
        g_lo[x] = lov;
        float p = acc[r]*av, q = acc[r]*bv;
        #pragma unroll
        for (int off=16; off; off>>=1){
            p += __shfl_xor_sync(0xffffffffu, p, off);
            q += __shfl_xor_sync(0xffffffffu, q, off);
        }
        if (lane == 0){
            g_ssrc[(b*NHEADS+head)*Nn + n] = p;
            g_sdst[(b*NHEADS+head)*Nn + n] = q;
        }
    }
    // zero the padding rows [Nn, NP) of both batches (12288 elems per array)
    int tg = blockIdx.x*256 + tid;
    if (tg < Bb*(NP-Nn)*Dd){
        int bb = tg / ((NP-Nn)*Dd);
        int rem = tg % ((NP-Nn)*Dd);
        size_t x = ((size_t)(bb*NP + Nn))*Dd + rem;
        g_hi[x] = 0.f;
        g_lo[x] = 0.f;
    }
}

// ---------------- per-(b,head) max of s_dst ----------------
__global__ void tmax_kernel()
{
    __shared__ float red[256];
    const float* t = g_sdst + blockIdx.x * Nn;
    float m = NEG_INF;
    for (int n = threadIdx.x; n < Nn; n += 256) m = fmaxf(m, t[n]);
    red[threadIdx.x] = m;
    __syncthreads();
    #pragma unroll
    for (int s=128; s; s>>=1){
        if (threadIdx.x < s) red[threadIdx.x] = fmaxf(red[threadIdx.x], red[threadIdx.x+s]);
        __syncthreads();
    }
    if (threadIdx.x == 0) g_tmax[blockIdx.x] = red[0];
}

// ---------------- GAT attention: tf32 mma.sync, cp.async fills --------------
#define SM_HHI 0
#define SM_HLO (TJ*PITCH)
#define SM_T   (2*TJ*PITCH)
#define SM_MB  (2*TJ*PITCH + NHEADS*TJ)
#define SM_FLOATS (2*TJ*PITCH + NHEADS*TJ + 64)

__global__ __launch_bounds__(256) void gat_attn_tc(const int* __restrict__ mask)
{
    extern __shared__ float sm[];
    float* h_hi = sm + SM_HHI;
    float* h_lo = sm + SM_HLO;
    float* t_tile = sm + SM_T;
    unsigned long long* m_bits = (unsigned long long*)(sm + SM_MB);
    uint32_t sbase = smem_u32(sm);
    uint32_t sb_hhi = sbase + SM_HHI*4;
    uint32_t sb_hlo = sbase + SM_HLO*4;

    int tid = threadIdx.x;
    int w = tid >> 5, lane = tid & 31;
    int h = w & 3, mh = w >> 2;
    int g = lane >> 2, t = lane & 3;
    int split = blockIdx.x % SPLITS;
    int tmp   = blockIdx.x / SPLITS;
    int b     = tmp / NTILES;
    int i0    = (tmp % NTILES) * 32;
    int il0 = mh*16 + g, il1 = il0 + 8;
    int gi0 = i0 + il0, gi1 = i0 + il1;

    float tmx = g_tmax[b*NHEADS + h];
    float s0 = (gi0 < Nn) ? g_ssrc[(b*NHEADS+h)*Nn + gi0] : 0.f;
    float s1 = (gi1 < Nn) ? g_ssrc[(b*NHEADS+h)*Nn + gi1] : 0.f;
    float m20 = lrelu(s0 + tmx) * LOG2E;
    float m21 = lrelu(s1 + tmx) * LOG2E;
    float lv0 = 0.f, lv1 = 0.f;
    float acc[4][4];
    #pragma unroll
    for (int nt=0;nt<4;nt++){ acc[nt][0]=0.f; acc[nt][1]=0.f; acc[nt][2]=0.f; acc[nt][3]=0.f; }

    const int* mrow = mask + (size_t)b*Nn*Nn + (size_t)i0*Nn;
    int mr = tid >> 3, moct = tid & 7;
    int fjj = tid >> 5, fc4 = tid & 31;   // fill coords: 8 rows apart per step

    int c0 = split * CPS;
    for (int c = c0; c < c0 + CPS; c++){
        int j0 = c * TJ;
        __syncthreads();    // previous chunk fully consumed

        // h tiles via cp.async (rows j0..j0+63 guaranteed in-bounds of NP, pad=0)
        const float* srch = g_hi + ((size_t)b*NP + j0)*Dd;
        const float* srcl = g_lo + ((size_t)b*NP + j0)*Dd;
        #pragma unroll
        for (int u=0; u<8; u++){
            int jj = fjj + u*8;
            uint32_t doff = (uint32_t)(jj*(PITCH*4) + fc4*16);
            const float* so = srch + (size_t)jj*Dd + fc4*4;
            const float* sl = srcl + (size_t)jj*Dd + fc4*4;
            cp16(sb_hhi + doff, so);
            cp16(sb_hlo + doff, sl);
        }
        CP_COMMIT();

        // t tile
        {
            int hh = tid >> 6, jj = tid & 63;
            t_tile[hh*TJ + jj] = (j0+jj < Nn) ? g_sdst[(b*NHEADS+hh)*Nn + j0+jj] : 0.f;
        }
        // mask bits: row mr, 8 j per thread -> one byte
        {
            unsigned int byte = 0;
            int j = j0 + moct*8;
            if (i0 + mr < Nn){
                const int* p = mrow + (size_t)mr*Nn + j;
                if (j + 7 < Nn){
                    int4 A = *(const int4*)p;
                    int4 Bv = *(const int4*)(p+4);
                    byte = (unsigned)(A.x!=0) | ((unsigned)(A.y!=0)<<1)
                         | ((unsigned)(A.z!=0)<<2) | ((unsigned)(A.w!=0)<<3)
                         | ((unsigned)(Bv.x!=0)<<4) | ((unsigned)(Bv.y!=0)<<5)
                         | ((unsigned)(Bv.z!=0)<<6) | ((unsigned)(Bv.w!=0)<<7);
                } else {
                    #pragma unroll
                    for (int k=0;k<8;k++)
                        if (j+k < Nn && p[k] != 0) byte |= (1u<<k);
                }
            }
            ((unsigned char*)m_bits)[mr*8 + moct] = (unsigned char)byte;
        }
        CP_WAIT0();
        __syncthreads();   // h + t + masks visible everywhere

        unsigned long long bits0 = m_bits[il0] >> t;
        unsigned long long bits1 = m_bits[il1] >> t;

        #pragma unroll
        for (int s=0; s<8; s++){
            float ta = t_tile[h*TJ + s*8 + t];
            float tb = t_tile[h*TJ + s*8 + t + 4];
            float e00 = lrelu(s0 + ta), e01 = lrelu(s0 + tb);
            float e10 = lrelu(s1 + ta), e11 = lrelu(s1 + tb);
            float w00 = ((bits0 >> (8*s))   & 1ull) ? exp2f(fmaf(e00, LOG2E, -m20)) : 0.f;
            float w01 = ((bits0 >> (8*s+4)) & 1ull) ? exp2f(fmaf(e01, LOG2E, -m20)) : 0.f;
            float w10 = ((bits1 >> (8*s))   & 1ull) ? exp2f(fmaf(e10, LOG2E, -m21)) : 0.f;
            float w11 = ((bits1 >> (8*s+4)) & 1ull) ? exp2f(fmaf(e11, LOG2E, -m21)) : 0.f;
            lv0 += w00 + w01;
            lv1 += w10 + w11;
            uint32_t ah0 = tf32_rna(w00), ah1 = tf32_rna(w10);
            uint32_t ah2 = tf32_rna(w01), ah3 = tf32_rna(w11);
            // residuals passed as raw f32 bits (HW truncates to tf32; err ~2^-21)
            uint32_t al0 = __float_as_uint(w00 - __uint_as_float(ah0));
            uint32_t al1 = __float_as_uint(w10 - __uint_as_float(ah1));
            uint32_t al2 = __float_as_uint(w01 - __uint_as_float(ah2));
            uint32_t al3 = __float_as_uint(w11 - __uint_as_float(ah3));
            int r0 = (s*8 + t)*PITCH + h*32 + g;
            int r1 = r0 + 4*PITCH;
            #pragma unroll
            for (int nt=0; nt<4; nt++){
                uint32_t bh0 = __float_as_uint(h_hi[r0 + nt*8]);
                uint32_t bh1 = __float_as_uint(h_hi[r1 + nt*8]);
                uint32_t bl0 = __float_as_uint(h_lo[r0 + nt*8]);
                uint32_t bl1 = __float_as_uint(h_lo[r1 + nt*8]);
                mma_tf32(acc[nt], ah0, ah1, ah2, ah3, bh0, bh1);
                mma_tf32(acc[nt], ah0, ah1, ah2, ah3, bl0, bl1);
                mma_tf32(acc[nt], al0, al1, al2, al3, bh0, bh1);
            }
        }
    }

    // lv: reduce over t within quad
    lv0 += __shfl_xor_sync(0xffffffffu, lv0, 1);
    lv0 += __shfl_xor_sync(0xffffffffu, lv0, 2);
    lv1 += __shfl_xor_sync(0xffffffffu, lv1, 1);
    lv1 += __shfl_xor_sync(0xffffffffu, lv1, 2);
    if (t == 0){
        if (gi0 < Nn) g_plv[split][(b*NHEADS+h)*Nn + gi0] = lv0;
        if (gi1 < Nn) g_plv[split][(b*NHEADS+h)*Nn + gi1] = lv1;
    }

    // write unnormalized partials
    float* pac = g_pacc[split];
    #pragma unroll
    for (int nt=0; nt<4; nt++){
        int d0 = h*32 + nt*8 + 2*t;
        if (gi0 < Nn){
            size_t x = ((size_t)(b*Nn + gi0))*Dd + d0;
            *(float2*)(pac + x) = make_float2(acc[nt][0], acc[nt][1]);
        }
        if (gi1 < Nn){
            size_t x = ((size_t)(b*Nn + gi1))*Dd + d0;
            *(float2*)(pac + x) = make_float2(acc[nt][2], acc[nt][3]);
        }
    }
}

// ---------------- combine partials: H = sum(acc)/sum(lv), Cbar = C - H ------
__global__ __launch_bounds__(256) void gat_combine(const float* __restrict__ Cin,
    float* __restrict__ Hout, float* __restrict__ Cbar)
{
    int gi  = blockIdx.x*2 + (threadIdx.x >> 7);
    int col = threadIdx.x & 127;
    if (gi >= Bb*Nn) return;
    int b = gi / Nn, i = gi % Nn;
    int head = col >> 5;
    size_t x = (size_t)gi*Dd + col;
    float a = 0.f, lv = 0.f;
    #pragma unroll
    for (int s=0;s<SPLITS;s++){
        a  += g_pacc[s][x];
        lv += g_plv[s][(b*NHEADS+head)*Nn + i];
    }
    float o = a / lv;
    Hout[x] = o;
    Cbar[x] = Cin[x] - o;
}

// ---------------- per-horizon deep factor heads ----------------
__global__ void factors_kernel(const float* __restrict__ Cc,
    const float* __restrict__ Cbi, const float* __restrict__ Cbu,
    const float* __restrict__ hW, const float* __restrict__ hb,
    float* __restrict__ out)
{
    int w = threadIdx.x >> 5, lane = threadIdx.x & 31;
    int r = blockIdx.x*4 + w;
    if (r >= Bb*Nn) return;
    float a0=0.f, a1=0.f, a2=0.f;
    #pragma unroll
    for (int it=0; it<12; it++){
        int idx = it*32 + lane;
        const float* src = (idx < 128) ? Cc : (idx < 256 ? Cbi : Cbu);
        int c = idx & 127;
        float v = src[(size_t)r*Dd + c];
        a0 += v*hW[0*DEEP+idx];
        a1 += v*hW[1*DEEP+idx];
        a2 += v*hW[2*DEEP+idx];
    }
    #pragma unroll
    for (int off=16; off; off>>=1){
        a0 += __shfl_xor_sync(0xffffffffu, a0, off);
        a1 += __shfl_xor_sync(0xffffffffu, a1, off);
        a2 += __shfl_xor_sync(0xffffffffu, a2, off);
    }
    if (lane==0){
        out[0*Bb*Nn + r] = lrelu(a0 + hb[0]);
        out[1*Bb*Nn + r] = lrelu(a1 + hb[1]);
        out[2*Bb*Nn + r] = lrelu(a2 + hb[2]);
    }
}

// ---------------- factor attention: U -> A ----------------
__global__ void fa_kernel(const float* __restrict__ feats,
    const float* __restrict__ projW, float* __restrict__ A)
{
    __shared__ float pw[64][65];
    __shared__ float ft[64][64];
    int tid = threadIdx.x;
    int ntile = blockIdx.x & 31;
    int hb_   = blockIdx.x >> 5;
    int hn = hb_ >> 1, b = hb_ & 1;
    int n0 = ntile*64;
    const float* P = projW + (size_t)hn*64*64;
    for (int idx=tid; idx<4096; idx+=256) pw[idx>>6][idx&63] = P[idx];
    for (int idx=tid; idx<4096; idx+=256){
        int r=idx>>6, m=idx&63; int n=n0+r;
        ft[r][m] = (n<Nn) ? feats[((size_t)(b*Nn+n))*Ff+m] : 0.f;
    }
    __syncthreads();
    int w = tid>>5, lane = tid&31;
    for (int rr=0; rr<8; rr++){
        int r = w*8+rr; int n=n0+r;
        if (n>=Nn) continue;
        float u0=0.f,u1=0.f;
        #pragma unroll
        for (int m=0;m<64;m++){
            float f = ft[r][m];
            u0 += f*pw[lane][m];
            u1 += f*pw[lane+32][m];
        }
        u0 = lrelu(u0); u1 = lrelu(u1);
        float mx = fmaxf(u0,u1);
        #pragma unroll
        for (int off=16; off; off>>=1)
            mx = fmaxf(mx, __shfl_xor_sync(0xffffffffu, mx, off));
        float e0 = __expf(u0-mx), e1 = __expf(u1-mx);
        float ss = e0+e1;
        #pragma unroll
        for (int off=16; off; off>>=1)
            ss += __shfl_xor_sync(0xffffffffu, ss, off);
        float inv = 1.f/ss;
        size_t base = ((size_t)hb_*Nn + n)*64;
        A[base+lane]    = e0*inv;
        A[base+lane+32] = e1*inv;
    }
}

// ---------------- a_bar = A.mean(axis=n) ----------------
__global__ void abar_kernel(const float* __restrict__ A)
{
    __shared__ float red[8][64];
    int tid=threadIdx.x; int k=tid&63, grp=tid>>6;
    const float* base = A + (size_t)blockIdx.x*Nn*64;
    float s=0.f;
    for (int n=grp; n<Nn; n+=8) s += base[(size_t)n*64+k];
    red[grp][k]=s;
    __syncthreads();
    if (grp==0){
        float t=0.f;
        #pragma unroll
        for (int g=0; g<8; g++) t += red[g][k];
        g_abar[blockIdx.x*64+k] = t * (1.f/Nn);
    }
}

// ---------------- recon = feats @ a_bar ----------------
__global__ void recon_kernel(const float* __restrict__ feats, float* __restrict__ out)
{
    int w = threadIdx.x>>5, lane=threadIdx.x&31;
    int ro = blockIdx.x*8 + w;
    if (ro >= HN*Bb*Nn) return;
    int hn = ro / (Bb*Nn);
    int rem = ro % (Bb*Nn);
    int b = rem / Nn, n = rem % Nn;
    const float* f  = feats  + (size_t)(b*Nn+n)*Ff;
    const float* ab = g_abar + (hn*Bb+b)*Ff;
    float p = f[lane]*ab[lane] + f[lane+32]*ab[lane+32];
    #pragma unroll
    for (int off=16; off; off>>=1)
        p += __shfl_xor_sync(0xffffffffu, p, off);
    if (lane==0) out[ro] = p;
}

extern "C" void kernel_launch(void* const* d_in, const int* in_sizes, int n_in,
                              void* d_out, int out_size)
{
    const float* feats = (const float*)d_in[0];
    const int* ind = (const int*)d_in[1];
    const int* uni = (const int*)d_in[2];
    const float* bn_g = (const float*)d_in[3];
    const float* bn_b = (const float*)d_in[4];
    const float* bn_m = (const float*)d_in[5];
    const float* bn_v = (const float*)d_in[6];
    const float* W1   = (const float*)d_in[7];
    const float* b1   = (const float*)d_in[8];
    const float* W2   = (const float*)d_in[9];
    const float* b2   = (const float*)d_in[10];
    const float* giW  = (const float*)d_in[11];
    const float* gias = (const float*)d_in[12];
    const float* giad = (const float*)d_in[13];
    const float* guW  = (const float*)d_in[14];
    const float* guas = (const float*)d_in[15];
    const float* guad = (const float*)d_in[16];
    const float* hW   = (const float*)d_in[17];
    const float* hb   = (const float*)d_in[18];
    const float* pW   = (const float*)d_in[19];

    float* out  = (float*)d_out;
    float* C    = out;
    float* CBI  = out + 512000;
    float* CBU  = out + 1024000;
    float* HI   = out + 1536000;
    float* HU   = out + 2048000;
    float* FOUT = out + 2560000;
    float* ROUT = out + 2572000;
    float* AOUT = out + 2584000;

    static int smem_set = 0;
    const int smem_bytes = SM_FLOATS * 4;
    if (!smem_set){
        cudaFuncSetAttribute(gat_attn_tc,
            cudaFuncAttributeMaxDynamicSharedMemorySize, smem_bytes);
        smem_set = 1;
    }

    encoder_kernel<<<250,256>>>(feats, bn_g, bn_b, bn_m, bn_v, W1, b1, W2, b2, C);

    gat_proj_kernel<<<250,256>>>(C, giW, gias, giad);
    tmax_kernel<<<8,256>>>();
    gat_attn_tc<<<Bb*NTILES*SPLITS,256,smem_bytes>>>(ind);
    gat_combine<<<Bb*Nn/2,256>>>(C, HI, CBI);

    gat_proj_kernel<<<250,256>>>(CBI, guW, guas, guad);
    tmax_kernel<<<8,256>>>();
    gat_attn_tc<<<Bb*NTILES*SPLITS,256,smem_bytes>>>(uni);
    gat_combine<<<Bb*Nn/2,256>>>(CBI, HU, CBU);

    factors_kernel<<<1000,128>>>(C, CBI, CBU, hW, hb, FOUT);

    fa_kernel<<<192,256>>>(feats, pW, AOUT);
    abar_kernel<<<6,512>>>(AOUT);
    recon_kernel<<<1500,256>>>(feats, ROUT);
}

// round 10
// speedup vs baseline: 1.7612x; 1.0783x over previous
#include <cuda_runtime.h>
#include <cstdint>

#define Bb 2
#define Nn 2000
#define NP 2048
#define Ff 64
#define Dd 128
#define NHEADS 4
#define DH 32
#define HN 3
#define DEEP 384
#define SLOPE 0.1f
#define NEG_INF -1e30f
#define TJ 64
#define NTILES 63
#define NCHUNK 32
#define SPLITS 8
#define CPS (NCHUNK/SPLITS)
#define LOG2E 1.44269504f
#define PITCH 136

__device__ float g_hi[Bb*NP*Dd];
__device__ float g_lo[Bb*NP*Dd];
__device__ float g_ssrc[Bb*NHEADS*Nn];
__device__ float g_sdst[Bb*NHEADS*Nn];
__device__ float g_tmax[Bb*NHEADS];
__device__ float g_abar[HN*Bb*Ff];
__device__ float g_pacc[SPLITS][Bb*Nn*Dd];
__device__ float g_plv[SPLITS][Bb*NHEADS*Nn];

__device__ __forceinline__ float lrelu(float x){ return fmaxf(x, SLOPE*x); }

__device__ __forceinline__ uint32_t tf32_rna(float x){
    uint32_t r;
    asm("cvt.rna.tf32.f32 %0, %1;" : "=r"(r) : "f"(x));
    return r;
}
__device__ __forceinline__ void mma_tf32(float* c,
    uint32_t a0, uint32_t a1, uint32_t a2, uint32_t a3,
    uint32_t b0, uint32_t b1)
{
    asm volatile(
        "mma.sync.aligned.m16n8k8.row.col.f32.tf32.tf32.f32 "
        "{%0,%1,%2,%3}, {%4,%5,%6,%7}, {%8,%9}, {%0,%1,%2,%3};"
        : "+f"(c[0]), "+f"(c[1]), "+f"(c[2]), "+f"(c[3])
        : "r"(a0), "r"(a1), "r"(a2), "r"(a3), "r"(b0), "r"(b1));
}
__device__ __forceinline__ uint32_t smem_u32(const void* p){
    uint32_t a;
    asm("{ .reg .u64 t; cvta.to.shared.u64 t, %1; cvt.u32.u64 %0, t; }" : "=r"(a) : "l"(p));
    return a;
}
__device__ __forceinline__ void cp16(uint32_t dst, const void* src){
    asm volatile("cp.async.cg.shared.global [%0], [%1], 16;" :: "r"(dst), "l"(src));
}
#define CP_COMMIT() asm volatile("cp.async.commit_group;" ::: "memory")
#define CP_WAIT0()  asm volatile("cp.async.wait_group 0;" ::: "memory")

// ---- shared proj tail: xs[16][Dd] (input rows) -> g_hi/g_lo + scores -------
__device__ __forceinline__ void proj_tail(const float xs[16][Dd],
    const float* __restrict__ W, const float* __restrict__ a_src,
    const float* __restrict__ a_dst, int row0, int tid)
{
    int col = tid & 127, grp = tid >> 7;
    float acc[8];
    #pragma unroll
    for (int r=0;r<8;r++) acc[r]=0.f;
    #pragma unroll 4
    for (int k=0;k<Dd;k++){
        float w = W[k*Dd + col];
        #pragma unroll
        for (int r=0;r<8;r++) acc[r] += xs[grp*8+r][k]*w;
    }
    int head = col >> 5, lane = col & 31;
    float av = a_src[head*DH + lane];
    float bv = a_dst[head*DH + lane];
    #pragma unroll
    for (int r=0;r<8;r++){
        int g = row0 + grp*8 + r;
        int b = g / Nn, n = g % Nn;
        uint32_t hv = tf32_rna(acc[r]);
        float lov = acc[r] - __uint_as_float(hv);
        size_t x = ((size_t)(b*NP + n))*Dd + col;
        g_hi[x] = __uint_as_float(hv);
        g_lo[x] = lov;
        float p = acc[r]*av, q = acc[r]*bv;
        #pragma unroll
        for (int off=16; off; off>>=1){
            p += __shfl_xor_sync(0xffffffffu, p, off);
            q += __shfl_xor_sync(0xffffffffu, q, off);
        }
        if (lane == 0){
            g_ssrc[(b*NHEADS+head)*Nn + n] = p;
            g_sdst[(b*NHEADS+head)*Nn + n] = q;
        }
    }
}

// ---------------- fused BN + encoder MLP + GAT1 projection ----------------
__global__ __launch_bounds__(256) void enc_proj1(const float* __restrict__ feats,
    const float* __restrict__ gamma, const float* __restrict__ beta,
    const float* __restrict__ mean, const float* __restrict__ var,
    const float* __restrict__ W1, const float* __restrict__ b1,
    const float* __restrict__ W2, const float* __restrict__ b2,
    float* __restrict__ C,
    const float* __restrict__ giW, const float* __restrict__ gias,
    const float* __restrict__ giad)
{
    __shared__ float xn[16][Ff];
    __shared__ float hid[16][Dd];
    __shared__ float xs[16][Dd];
    int tid = threadIdx.x;
    int col = tid & 127, grp = tid >> 7;
    int row0 = blockIdx.x * 16;
    for (int idx = tid; idx < 16*Ff; idx += 256) {
        int r = idx >> 6, f = idx & 63;
        float v = feats[(size_t)(row0+r)*Ff + f];
        xn[r][f] = (v - mean[f]) * rsqrtf(var[f] + 1e-5f) * gamma[f] + beta[f];
    }
    __syncthreads();
    float acc[8];
    float bb = b1[col];
    #pragma unroll
    for (int r=0;r<8;r++) acc[r] = bb;
    #pragma unroll 4
    for (int f=0; f<Ff; f++){
        float w = W1[f*Dd + col];
        #pragma unroll
        for (int r=0;r<8;r++) acc[r] += xn[grp*8+r][f]*w;
    }
    #pragma unroll
    for (int r=0;r<8;r++) hid[grp*8+r][col] = fmaxf(acc[r], 0.f);
    __syncthreads();
    bb = b2[col];
    #pragma unroll
    for (int r=0;r<8;r++) acc[r] = bb;
    #pragma unroll 4
    for (int k=0;k<Dd;k++){
        float w = W2[k*Dd + col];
        #pragma unroll
        for (int r=0;r<8;r++) acc[r] += hid[grp*8+r][k]*w;
    }
    #pragma unroll
    for (int r=0;r<8;r++){
        C[(size_t)(row0+grp*8+r)*Dd + col] = acc[r];
        xs[grp*8+r][col] = acc[r];
    }
    __syncthreads();
    proj_tail(xs, giW, gias, giad, row0, tid);

    // zero padding rows [Nn,NP) of g_hi/g_lo (once; stage 2 reuses them)
    int tg = blockIdx.x*256 + tid;
    if (tg < Bb*(NP-Nn)*Dd){
        int bb2 = tg / ((NP-Nn)*Dd);
        int rem = tg % ((NP-Nn)*Dd);
        size_t x = ((size_t)(bb2*NP + Nn))*Dd + rem;
        g_hi[x] = 0.f;
        g_lo[x] = 0.f;
    }
}

// ---------------- fused combine(GAT1) + GAT2 projection ----------------
__global__ __launch_bounds__(256) void comb_proj2(const float* __restrict__ C,
    const float* __restrict__ guW, const float* __restrict__ guas,
    const float* __restrict__ guad,
    float* __restrict__ HI, float* __restrict__ CBI)
{
    __shared__ float xs[16][Dd];
    int tid = threadIdx.x;
    int col = tid & 127, grp = tid >> 7;
    int row0 = blockIdx.x * 16;
    int head = col >> 5;
    #pragma unroll
    for (int r=0;r<8;r++){
        int gr = row0 + grp*8 + r;
        int b = gr / Nn, i = gr % Nn;
        size_t x = (size_t)gr*Dd + col;
        float a = 0.f, lv = 0.f;
        #pragma unroll
        for (int s=0;s<SPLITS;s++){
            a  += g_pacc[s][x];
            lv += g_plv[s][(b*NHEADS+head)*Nn + i];
        }
        float o = a / lv;
        float cb = C[x] - o;
        HI[x] = o;
        CBI[x] = cb;
        xs[grp*8+r][col] = cb;
    }
    __syncthreads();
    proj_tail(xs, guW, guas, guad, row0, tid);
}

// ---------------- fused combine(GAT2) + factor heads ----------------
__global__ __launch_bounds__(256) void comb2_fact(const float* __restrict__ Cc,
    const float* __restrict__ CBI,
    const float* __restrict__ hW, const float* __restrict__ hb,
    float* __restrict__ HU, float* __restrict__ CBU, float* __restrict__ FOUT)
{
    __shared__ float cbis[16][Dd];
    __shared__ float cbus[16][Dd];
    int tid = threadIdx.x;
    int col = tid & 127, grp = tid >> 7;
    int row0 = blockIdx.x * 16;
    int head = col >> 5;
    #pragma unroll
    for (int r=0;r<8;r++){
        int gr = row0 + grp*8 + r;
        int b = gr / Nn, i = gr % Nn;
        size_t x = (size_t)gr*Dd + col;
        float a = 0.f, lv = 0.f;
        #pragma unroll
        for (int s=0;s<SPLITS;s++){
            a  += g_pacc[s][x];
            lv += g_plv[s][(b*NHEADS+head)*Nn + i];
        }
        float o = a / lv;
        float ci = CBI[x];
        float cb = ci - o;
        HU[x] = o;
        CBU[x] = cb;
        cbis[grp*8+r][col] = ci;
        cbus[grp*8+r][col] = cb;
    }
    __syncthreads();
    // factors: warp w owns local rows 2w, 2w+1
    int w = tid >> 5, lane = tid & 31;
    #pragma unroll
    for (int rr=0; rr<2; rr++){
        int rl = w*2 + rr;
        int gr = row0 + rl;
        float a0=0.f, a1=0.f, a2=0.f;
        #pragma unroll
        for (int it=0; it<12; it++){
            int idx = it*32 + lane;
            float v;
            if (idx < 128)      v = Cc[(size_t)gr*Dd + idx];
            else if (idx < 256) v = cbis[rl][idx-128];
            else                v = cbus[rl][idx-256];
            a0 += v*hW[0*DEEP+idx];
            a1 += v*hW[1*DEEP+idx];
            a2 += v*hW[2*DEEP+idx];
        }
        #pragma unroll
        for (int off=16; off; off>>=1){
            a0 += __shfl_xor_sync(0xffffffffu, a0, off);
            a1 += __shfl_xor_sync(0xffffffffu, a1, off);
            a2 += __shfl_xor_sync(0xffffffffu, a2, off);
        }
        if (lane==0){
            FOUT[0*Bb*Nn + gr] = lrelu(a0 + hb[0]);
            FOUT[1*Bb*Nn + gr] = lrelu(a1 + hb[1]);
            FOUT[2*Bb*Nn + gr] = lrelu(a2 + hb[2]);
        }
    }
}

// ---------------- per-(b,head) max of s_dst ----------------
__global__ void tmax_kernel()
{
    __shared__ float red[256];
    const float* t = g_sdst + blockIdx.x * Nn;
    float m = NEG_INF;
    for (int n = threadIdx.x; n < Nn; n += 256) m = fmaxf(m, t[n]);
    red[threadIdx.x] = m;
    __syncthreads();
    #pragma unroll
    for (int s=128; s; s>>=1){
        if (threadIdx.x < s) red[threadIdx.x] = fmaxf(red[threadIdx.x], red[threadIdx.x+s]);
        __syncthreads();
    }
    if (threadIdx.x == 0) g_tmax[blockIdx.x] = red[0];
}

// ---------------- GAT attention: tf32 mma.sync, cp.async fills --------------
#define SM_HHI 0
#define SM_HLO (TJ*PITCH)
#define SM_T   (2*TJ*PITCH)
#define SM_MB  (2*TJ*PITCH + NHEADS*TJ)
#define SM_FLOATS (2*TJ*PITCH + NHEADS*TJ + 64)

__global__ __launch_bounds__(256) void gat_attn_tc(const int* __restrict__ mask)
{
    extern __shared__ float sm[];
    float* h_hi = sm + SM_HHI;
    float* h_lo = sm + SM_HLO;
    float* t_tile = sm + SM_T;
    unsigned long long* m_bits = (unsigned long long*)(sm + SM_MB);
    uint32_t sbase = smem_u32(sm);
    uint32_t sb_hhi = sbase + SM_HHI*4;
    uint32_t sb_hlo = sbase + SM_HLO*4;

    int tid = threadIdx.x;
    int w = tid >> 5, lane = tid & 31;
    int h = w & 3, mh = w >> 2;
    int g = lane >> 2, t = lane & 3;
    int split = blockIdx.x % SPLITS;
    int tmp   = blockIdx.x / SPLITS;
    int b     = tmp / NTILES;
    int i0    = (tmp % NTILES) * 32;
    int il0 = mh*16 + g, il1 = il0 + 8;
    int gi0 = i0 + il0, gi1 = i0 + il1;

    float tmx = g_tmax[b*NHEADS + h];
    float s0 = (gi0 < Nn) ? g_ssrc[(b*NHEADS+h)*Nn + gi0] : 0.f;
    float s1 = (gi1 < Nn) ? g_ssrc[(b*NHEADS+h)*Nn + gi1] : 0.f;
    float m20 = lrelu(s0 + tmx) * LOG2E;
    float m21 = lrelu(s1 + tmx) * LOG2E;
    float lv0 = 0.f, lv1 = 0.f;
    float acc[4][4];
    #pragma unroll
    for (int nt=0;nt<4;nt++){ acc[nt][0]=0.f; acc[nt][1]=0.f; acc[nt][2]=0.f; acc[nt][3]=0.f; }

    const int* mrow = mask + (size_t)b*Nn*Nn + (size_t)i0*Nn;
    int mr = tid >> 3, moct = tid & 7;
    int fjj = tid >> 5, fc4 = tid & 31;

    int c0 = split * CPS;
    for (int c = c0; c < c0 + CPS; c++){
        int j0 = c * TJ;
        __syncthreads();

        const float* srch = g_hi + ((size_t)b*NP + j0)*Dd;
        const float* srcl = g_lo + ((size_t)b*NP + j0)*Dd;
        #pragma unroll
        for (int u=0; u<8; u++){
            int jj = fjj + u*8;
            uint32_t doff = (uint32_t)(jj*(PITCH*4) + fc4*16);
            cp16(sb_hhi + doff, srch + (size_t)jj*Dd + fc4*4);
            cp16(sb_hlo + doff, srcl + (size_t)jj*Dd + fc4*4);
        }
        CP_COMMIT();

        {
            int hh = tid >> 6, jj = tid & 63;
            t_tile[hh*TJ + jj] = (j0+jj < Nn) ? g_sdst[(b*NHEADS+hh)*Nn + j0+jj] : 0.f;
        }
        {
            unsigned int byte = 0;
            int j = j0 + moct*8;
            if (i0 + mr < Nn){
                const int* p = mrow + (size_t)mr*Nn + j;
                if (j + 7 < Nn){
                    int4 A = *(const int4*)p;
                    int4 Bv = *(const int4*)(p+4);
                    byte = (unsigned)(A.x!=0) | ((unsigned)(A.y!=0)<<1)
                         | ((unsigned)(A.z!=0)<<2) | ((unsigned)(A.w!=0)<<3)
                         | ((unsigned)(Bv.x!=0)<<4) | ((unsigned)(Bv.y!=0)<<5)
                         | ((unsigned)(Bv.z!=0)<<6) | ((unsigned)(Bv.w!=0)<<7);
                } else {
                    #pragma unroll
                    for (int k=0;k<8;k++)
                        if (j+k < Nn && p[k] != 0) byte |= (1u<<k);
                }
            }
            ((unsigned char*)m_bits)[mr*8 + moct] = (unsigned char)byte;
        }
        CP_WAIT0();
        __syncthreads();

        unsigned long long bits0 = m_bits[il0] >> t;
        unsigned long long bits1 = m_bits[il1] >> t;

        #pragma unroll
        for (int s=0; s<8; s++){
            float ta = t_tile[h*TJ + s*8 + t];
            float tb = t_tile[h*TJ + s*8 + t + 4];
            float e00 = lrelu(s0 + ta), e01 = lrelu(s0 + tb);
            float e10 = lrelu(s1 + ta), e11 = lrelu(s1 + tb);
            float w00 = ((bits0 >> (8*s))   & 1ull) ? exp2f(fmaf(e00, LOG2E, -m20)) : 0.f;
            float w01 = ((bits0 >> (8*s+4)) & 1ull) ? exp2f(fmaf(e01, LOG2E, -m20)) : 0.f;
            float w10 = ((bits1 >> (8*s))   & 1ull) ? exp2f(fmaf(e10, LOG2E, -m21)) : 0.f;
            float w11 = ((bits1 >> (8*s+4)) & 1ull) ? exp2f(fmaf(e11, LOG2E, -m21)) : 0.f;
            lv0 += w00 + w01;
            lv1 += w10 + w11;
            uint32_t ah0 = tf32_rna(w00), ah1 = tf32_rna(w10);
            uint32_t ah2 = tf32_rna(w01), ah3 = tf32_rna(w11);
            uint32_t al0 = __float_as_uint(w00 - __uint_as_float(ah0));
            uint32_t al1 = __float_as_uint(w10 - __uint_as_float(ah1));
            uint32_t al2 = __float_as_uint(w01 - __uint_as_float(ah2));
            uint32_t al3 = __float_as_uint(w11 - __uint_as_float(ah3));
            int r0 = (s*8 + t)*PITCH + h*32 + g;
            int r1 = r0 + 4*PITCH;
            #pragma unroll
            for (int nt=0; nt<4; nt++){
                uint32_t bh0 = __float_as_uint(h_hi[r0 + nt*8]);
                uint32_t bh1 = __float_as_uint(h_hi[r1 + nt*8]);
                uint32_t bl0 = __float_as_uint(h_lo[r0 + nt*8]);
                uint32_t bl1 = __float_as_uint(h_lo[r1 + nt*8]);
                mma_tf32(acc[nt], ah0, ah1, ah2, ah3, bh0, bh1);
                mma_tf32(acc[nt], ah0, ah1, ah2, ah3, bl0, bl1);
                mma_tf32(acc[nt], al0, al1, al2, al3, bh0, bh1);
            }
        }
    }

    lv0 += __shfl_xor_sync(0xffffffffu, lv0, 1);
    lv0 += __shfl_xor_sync(0xffffffffu, lv0, 2);
    lv1 += __shfl_xor_sync(0xffffffffu, lv1, 1);
    lv1 += __shfl_xor_sync(0xffffffffu, lv1, 2);
    if (t == 0){
        if (gi0 < Nn) g_plv[split][(b*NHEADS+h)*Nn + gi0] = lv0;
        if (gi1 < Nn) g_plv[split][(b*NHEADS+h)*Nn + gi1] = lv1;
    }

    float* pac = g_pacc[split];
    #pragma unroll
    for (int nt=0; nt<4; nt++){
        int d0 = h*32 + nt*8 + 2*t;
        if (gi0 < Nn){
            size_t x = ((size_t)(b*Nn + gi0))*Dd + d0;
            *(float2*)(pac + x) = make_float2(acc[nt][0], acc[nt][1]);
        }
        if (gi1 < Nn){
            size_t x = ((size_t)(b*Nn + gi1))*Dd + d0;
            *(float2*)(pac + x) = make_float2(acc[nt][2], acc[nt][3]);
        }
    }
}

// ---------------- factor attention: U -> A ----------------
__global__ void fa_kernel(const float* __restrict__ feats,
    const float* __restrict__ projW, float* __restrict__ A)
{
    __shared__ float pw[64][65];
    __shared__ float ft[64][64];
    int tid = threadIdx.x;
    int ntile = blockIdx.x & 31;
    int hb_   = blockIdx.x >> 5;
    int hn = hb_ >> 1, b = hb_ & 1;
    int n0 = ntile*64;
    const float* P = projW + (size_t)hn*64*64;
    for (int idx=tid; idx<4096; idx+=256) pw[idx>>6][idx&63] = P[idx];
    for (int idx=tid; idx<4096; idx+=256){
        int r=idx>>6, m=idx&63; int n=n0+r;
        ft[r][m] = (n<Nn) ? feats[((size_t)(b*Nn+n))*Ff+m] : 0.f;
    }
    __syncthreads();
    int w = tid>>5, lane = tid&31;
    for (int rr=0; rr<8; rr++){
        int r = w*8+rr; int n=n0+r;
        if (n>=Nn) continue;
        float u0=0.f,u1=0.f;
        #pragma unroll
        for (int m=0;m<64;m++){
            float f = ft[r][m];
            u0 += f*pw[lane][m];
            u1 += f*pw[lane+32][m];
        }
        u0 = lrelu(u0); u1 = lrelu(u1);
        float mx = fmaxf(u0,u1);
        #pragma unroll
        for (int off=16; off; off>>=1)
            mx = fmaxf(mx, __shfl_xor_sync(0xffffffffu, mx, off));
        float e0 = __expf(u0-mx), e1 = __expf(u1-mx);
        float ss = e0+e1;
        #pragma unroll
        for (int off=16; off; off>>=1)
            ss += __shfl_xor_sync(0xffffffffu, ss, off);
        float inv = 1.f/ss;
        size_t base = ((size_t)hb_*Nn + n)*64;
        A[base+lane]    = e0*inv;
        A[base+lane+32] = e1*inv;
    }
}

// ---------------- a_bar = A.mean(axis=n) ----------------
__global__ void abar_kernel(const float* __restrict__ A)
{
    __shared__ float red[8][64];
    int tid=threadIdx.x; int k=tid&63, grp=tid>>6;
    const float* base = A + (size_t)blockIdx.x*Nn*64;
    float s=0.f;
    for (int n=grp; n<Nn; n+=8) s += base[(size_t)n*64+k];
    red[grp][k]=s;
    __syncthreads();
    if (grp==0){
        float t=0.f;
        #pragma unroll
        for (int g=0; g<8; g++) t += red[g][k];
        g_abar[blockIdx.x*64+k] = t * (1.f/Nn);
    }
}

// ---------------- recon = feats @ a_bar ----------------
__global__ void recon_kernel(const float* __restrict__ feats, float* __restrict__ out)
{
    int w = threadIdx.x>>5, lane=threadIdx.x&31;
    int ro = blockIdx.x*8 + w;
    if (ro >= HN*Bb*Nn) return;
    int hn = ro / (Bb*Nn);
    int rem = ro % (Bb*Nn);
    int b = rem / Nn, n = rem % Nn;
    const float* f  = feats  + (size_t)(b*Nn+n)*Ff;
    const float* ab = g_abar + (hn*Bb+b)*Ff;
    float p = f[lane]*ab[lane] + f[lane+32]*ab[lane+32];
    #pragma unroll
    for (int off=16; off; off>>=1)
        p += __shfl_xor_sync(0xffffffffu, p, off);
    if (lane==0) out[ro] = p;
}

extern "C" void kernel_launch(void* const* d_in, const int* in_sizes, int n_in,
                              void* d_out, int out_size)
{
    const float* feats = (const float*)d_in[0];
    const int* ind = (const int*)d_in[1];
    const int* uni = (const int*)d_in[2];
    const float* bn_g = (const float*)d_in[3];
    const float* bn_b = (const float*)d_in[4];
    const float* bn_m = (const float*)d_in[5];
    const float* bn_v = (const float*)d_in[6];
    const float* W1   = (const float*)d_in[7];
    const float* b1   = (const float*)d_in[8];
    const float* W2   = (const float*)d_in[9];
    const float* b2   = (const float*)d_in[10];
    const float* giW  = (const float*)d_in[11];
    const float* gias = (const float*)d_in[12];
    const float* giad = (const float*)d_in[13];
    const float* guW  = (const float*)d_in[14];
    const float* guas = (const float*)d_in[15];
    const float* guad = (const float*)d_in[16];
    const float* hW   = (const float*)d_in[17];
    const float* hb   = (const float*)d_in[18];
    const float* pW   = (const float*)d_in[19];

    float* out  = (float*)d_out;
    float* C    = out;
    float* CBI  = out + 512000;
    float* CBU  = out + 1024000;
    float* HI   = out + 1536000;
    float* HU   = out + 2048000;
    float* FOUT = out + 2560000;
    float* ROUT = out + 2572000;
    float* AOUT = out + 2584000;

    static int smem_set = 0;
    const int smem_bytes = SM_FLOATS * 4;
    if (!smem_set){
        cudaFuncSetAttribute(gat_attn_tc,
            cudaFuncAttributeMaxDynamicSharedMemorySize, smem_bytes);
        smem_set = 1;
    }

    enc_proj1<<<250,256>>>(feats, bn_g, bn_b, bn_m, bn_v, W1, b1, W2, b2, C,
                           giW, gias, giad);
    tmax_kernel<<<8,256>>>();
    gat_attn_tc<<<Bb*NTILES*SPLITS,256,smem_bytes>>>(ind);

    comb_proj2<<<250,256>>>(C, guW, guas, guad, HI, CBI);
    tmax_kernel<<<8,256>>>();
    gat_attn_tc<<<Bb*NTILES*SPLITS,256,smem_bytes>>>(uni);

    comb2_fact<<<250,256>>>(C, CBI, hW, hb, HU, CBU, FOUT);

    fa_kernel<<<192,256>>>(feats, pW, AOUT);
    abar_kernel<<<6,512>>>(AOUT);
    recon_kernel<<<1500,256>>>(feats, ROUT);
}

// round 11
// speedup vs baseline: 1.8284x; 1.0381x over previous
#include <cuda_runtime.h>
#include <cstdint>

#define Bb 2
#define Nn 2000
#define NP 2048
#define Ff 64
#define Dd 128
#define NHEADS 4
#define DH 32
#define HN 3
#define DEEP 384
#define SLOPE 0.1f
#define NEG_INF -1e30f
#define TJ 64
#define NTILES 63
#define NCHUNK 32
#define SPLITS 16
#define CPS (NCHUNK/SPLITS)
#define LOG2E 1.44269504f
#define PITCH 136

__device__ float g_hi[Bb*NP*Dd];
__device__ float g_lo[Bb*NP*Dd];
__device__ float g_ssrc[Bb*NHEADS*Nn];
__device__ float g_sdst[Bb*NHEADS*Nn];
__device__ float g_tmax[Bb*NHEADS];
__device__ float g_abar[HN*Bb*Ff];
__device__ float g_pacc[SPLITS][Bb*Nn*Dd];
__device__ float g_plv[SPLITS][Bb*NHEADS*Nn];

__device__ __forceinline__ float lrelu(float x){ return fmaxf(x, SLOPE*x); }

__device__ __forceinline__ uint32_t tf32_rna(float x){
    uint32_t r;
    asm("cvt.rna.tf32.f32 %0, %1;" : "=r"(r) : "f"(x));
    return r;
}
__device__ __forceinline__ void mma_tf32(float* c,
    uint32_t a0, uint32_t a1, uint32_t a2, uint32_t a3,
    uint32_t b0, uint32_t b1)
{
    asm volatile(
        "mma.sync.aligned.m16n8k8.row.col.f32.tf32.tf32.f32 "
        "{%0,%1,%2,%3}, {%4,%5,%6,%7}, {%8,%9}, {%0,%1,%2,%3};"
        : "+f"(c[0]), "+f"(c[1]), "+f"(c[2]), "+f"(c[3])
        : "r"(a0), "r"(a1), "r"(a2), "r"(a3), "r"(b0), "r"(b1));
}
__device__ __forceinline__ uint32_t smem_u32(const void* p){
    uint32_t a;
    asm("{ .reg .u64 t; cvta.to.shared.u64 t, %1; cvt.u32.u64 %0, t; }" : "=r"(a) : "l"(p));
    return a;
}
__device__ __forceinline__ void cp16(uint32_t dst, const void* src){
    asm volatile("cp.async.cg.shared.global [%0], [%1], 16;" :: "r"(dst), "l"(src));
}
#define CP_COMMIT() asm volatile("cp.async.commit_group;" ::: "memory")
#define CP_WAIT0()  asm volatile("cp.async.wait_group 0;" ::: "memory")

// ---- proj tail, 8 rows: xs[8][Dd] -> g_hi/g_lo + scores --------------------
__device__ __forceinline__ void proj_tail8(const float xs[8][Dd],
    const float* __restrict__ W, const float* __restrict__ a_src,
    const float* __restrict__ a_dst, int row0, int tid)
{
    int col = tid & 127, grp = tid >> 7;
    float acc[4];
    #pragma unroll
    for (int r=0;r<4;r++) acc[r]=0.f;
    #pragma unroll 4
    for (int k=0;k<Dd;k++){
        float w = W[k*Dd + col];
        #pragma unroll
        for (int r=0;r<4;r++) acc[r] += xs[grp*4+r][k]*w;
    }
    int head = col >> 5, lane = col & 31;
    float av = a_src[head*DH + lane];
    float bv = a_dst[head*DH + lane];
    #pragma unroll
    for (int r=0;r<4;r++){
        int g = row0 + grp*4 + r;
        int b = g / Nn, n = g % Nn;
        uint32_t hv = tf32_rna(acc[r]);
        float lov = acc[r] - __uint_as_float(hv);
        size_t x = ((size_t)(b*NP + n))*Dd + col;
        g_hi[x] = __uint_as_float(hv);
        g_lo[x] = lov;
        float p = acc[r]*av, q = acc[r]*bv;
        #pragma unroll
        for (int off=16; off; off>>=1){
            p += __shfl_xor_sync(0xffffffffu, p, off);
            q += __shfl_xor_sync(0xffffffffu, q, off);
        }
        if (lane == 0){
            g_ssrc[(b*NHEADS+head)*Nn + n] = p;
            g_sdst[(b*NHEADS+head)*Nn + n] = q;
        }
    }
}

// ---------------- fused BN + encoder MLP + GAT1 projection (8 rows) ---------
__global__ __launch_bounds__(256) void enc_proj1(const float* __restrict__ feats,
    const float* __restrict__ gamma, const float* __restrict__ beta,
    const float* __restrict__ mean, const float* __restrict__ var,
    const float* __restrict__ W1, const float* __restrict__ b1,
    const float* __restrict__ W2, const float* __restrict__ b2,
    float* __restrict__ C,
    const float* __restrict__ giW, const float* __restrict__ gias,
    const float* __restrict__ giad)
{
    __shared__ float xn[8][Ff];
    __shared__ float hid[8][Dd];
    __shared__ float xs[8][Dd];
    int tid = threadIdx.x;
    int col = tid & 127, grp = tid >> 7;
    int row0 = blockIdx.x * 8;
    for (int idx = tid; idx < 8*Ff; idx += 256) {
        int r = idx >> 6, f = idx & 63;
        float v = feats[(size_t)(row0+r)*Ff + f];
        xn[r][f] = (v - mean[f]) * rsqrtf(var[f] + 1e-5f) * gamma[f] + beta[f];
    }
    __syncthreads();
    float acc[4];
    float bb = b1[col];
    #pragma unroll
    for (int r=0;r<4;r++) acc[r] = bb;
    #pragma unroll 4
    for (int f=0; f<Ff; f++){
        float w = W1[f*Dd + col];
        #pragma unroll
        for (int r=0;r<4;r++) acc[r] += xn[grp*4+r][f]*w;
    }
    #pragma unroll
    for (int r=0;r<4;r++) hid[grp*4+r][col] = fmaxf(acc[r], 0.f);
    __syncthreads();
    bb = b2[col];
    #pragma unroll
    for (int r=0;r<4;r++) acc[r] = bb;
    #pragma unroll 4
    for (int k=0;k<Dd;k++){
        float w = W2[k*Dd + col];
        #pragma unroll
        for (int r=0;r<4;r++) acc[r] += hid[grp*4+r][k]*w;
    }
    #pragma unroll
    for (int r=0;r<4;r++){
        C[(size_t)(row0+grp*4+r)*Dd + col] = acc[r];
        xs[grp*4+r][col] = acc[r];
    }
    __syncthreads();
    proj_tail8(xs, giW, gias, giad, row0, tid);

    // zero padding rows [Nn,NP) of g_hi/g_lo
    int tg = blockIdx.x*256 + tid;
    if (tg < Bb*(NP-Nn)*Dd){
        int bb2 = tg / ((NP-Nn)*Dd);
        int rem = tg % ((NP-Nn)*Dd);
        size_t x = ((size_t)(bb2*NP + Nn))*Dd + rem;
        g_hi[x] = 0.f;
        g_lo[x] = 0.f;
    }
}

// ---------------- fused combine(GAT1) + GAT2 projection (8 rows) ------------
__global__ __launch_bounds__(256) void comb_proj2(const float* __restrict__ C,
    const float* __restrict__ guW, const float* __restrict__ guas,
    const float* __restrict__ guad,
    float* __restrict__ HI, float* __restrict__ CBI)
{
    __shared__ float xs[8][Dd];
    int tid = threadIdx.x;
    int col = tid & 127, grp = tid >> 7;
    int row0 = blockIdx.x * 8;
    int head = col >> 5;
    #pragma unroll
    for (int r=0;r<4;r++){
        int gr = row0 + grp*4 + r;
        int b = gr / Nn, i = gr % Nn;
        size_t x = (size_t)gr*Dd + col;
        float a = 0.f, lv = 0.f;
        #pragma unroll
        for (int s=0;s<SPLITS;s++){
            a  += g_pacc[s][x];
            lv += g_plv[s][(b*NHEADS+head)*Nn + i];
        }
        float o = a / lv;
        float cb = C[x] - o;
        HI[x] = o;
        CBI[x] = cb;
        xs[grp*4+r][col] = cb;
    }
    __syncthreads();
    proj_tail8(xs, guW, guas, guad, row0, tid);
}

// ---------------- fused combine(GAT2) + factor heads (8 rows) ---------------
__global__ __launch_bounds__(256) void comb2_fact(const float* __restrict__ Cc,
    const float* __restrict__ CBI,
    const float* __restrict__ hW, const float* __restrict__ hb,
    float* __restrict__ HU, float* __restrict__ CBU, float* __restrict__ FOUT)
{
    __shared__ float cbis[8][Dd];
    __shared__ float cbus[8][Dd];
    int tid = threadIdx.x;
    int col = tid & 127, grp = tid >> 7;
    int row0 = blockIdx.x * 8;
    int head = col >> 5;
    #pragma unroll
    for (int r=0;r<4;r++){
        int gr = row0 + grp*4 + r;
        int b = gr / Nn, i = gr % Nn;
        size_t x = (size_t)gr*Dd + col;
        float a = 0.f, lv = 0.f;
        #pragma unroll
        for (int s=0;s<SPLITS;s++){
            a  += g_pacc[s][x];
            lv += g_plv[s][(b*NHEADS+head)*Nn + i];
        }
        float o = a / lv;
        float ci = CBI[x];
        float cb = ci - o;
        HU[x] = o;
        CBU[x] = cb;
        cbis[grp*4+r][col] = ci;
        cbus[grp*4+r][col] = cb;
    }
    __syncthreads();
    // factors: warp w owns local row w (8 rows, 8 warps)
    int w = tid >> 5, lane = tid & 31;
    int gr = row0 + w;
    float a0=0.f, a1=0.f, a2=0.f;
    #pragma unroll
    for (int it=0; it<12; it++){
        int idx = it*32 + lane;
        float v;
        if (idx < 128)      v = Cc[(size_t)gr*Dd + idx];
        else if (idx < 256) v = cbis[w][idx-128];
        else                v = cbus[w][idx-256];
        a0 += v*hW[0*DEEP+idx];
        a1 += v*hW[1*DEEP+idx];
        a2 += v*hW[2*DEEP+idx];
    }
    #pragma unroll
    for (int off=16; off; off>>=1){
        a0 += __shfl_xor_sync(0xffffffffu, a0, off);
        a1 += __shfl_xor_sync(0xffffffffu, a1, off);
        a2 += __shfl_xor_sync(0xffffffffu, a2, off);
    }
    if (lane==0){
        FOUT[0*Bb*Nn + gr] = lrelu(a0 + hb[0]);
        FOUT[1*Bb*Nn + gr] = lrelu(a1 + hb[1]);
        FOUT[2*Bb*Nn + gr] = lrelu(a2 + hb[2]);
    }
}

// ---------------- per-(b,head) max of s_dst ----------------
__global__ void tmax_kernel()
{
    __shared__ float red[256];
    const float* t = g_sdst + blockIdx.x * Nn;
    float m = NEG_INF;
    for (int n = threadIdx.x; n < Nn; n += 256) m = fmaxf(m, t[n]);
    red[threadIdx.x] = m;
    __syncthreads();
    #pragma unroll
    for (int s=128; s; s>>=1){
        if (threadIdx.x < s) red[threadIdx.x] = fmaxf(red[threadIdx.x], red[threadIdx.x+s]);
        __syncthreads();
    }
    if (threadIdx.x == 0) g_tmax[blockIdx.x] = red[0];
}

// ---------------- GAT attention: tf32 mma.sync, cp.async fills --------------
#define SM_HHI 0
#define SM_HLO (TJ*PITCH)
#define SM_T   (2*TJ*PITCH)
#define SM_MB  (2*TJ*PITCH + NHEADS*TJ)
#define SM_FLOATS (2*TJ*PITCH + NHEADS*TJ + 64)

__global__ __launch_bounds__(256) void gat_attn_tc(const int* __restrict__ mask)
{
    extern __shared__ float sm[];
    float* h_hi = sm + SM_HHI;
    float* h_lo = sm + SM_HLO;
    float* t_tile = sm + SM_T;
    unsigned long long* m_bits = (unsigned long long*)(sm + SM_MB);
    uint32_t sbase = smem_u32(sm);
    uint32_t sb_hhi = sbase + SM_HHI*4;
    uint32_t sb_hlo = sbase + SM_HLO*4;

    int tid = threadIdx.x;
    int w = tid >> 5, lane = tid & 31;
    int h = w & 3, mh = w >> 2;
    int g = lane >> 2, t = lane & 3;
    int split = blockIdx.x % SPLITS;
    int tmp   = blockIdx.x / SPLITS;
    int b     = tmp / NTILES;
    int i0    = (tmp % NTILES) * 32;
    int il0 = mh*16 + g, il1 = il0 + 8;
    int gi0 = i0 + il0, gi1 = i0 + il1;

    float tmx = g_tmax[b*NHEADS + h];
    float s0 = (gi0 < Nn) ? g_ssrc[(b*NHEADS+h)*Nn + gi0] : 0.f;
    float s1 = (gi1 < Nn) ? g_ssrc[(b*NHEADS+h)*Nn + gi1] : 0.f;
    float m20 = lrelu(s0 + tmx) * LOG2E;
    float m21 = lrelu(s1 + tmx) * LOG2E;
    float lv0 = 0.f, lv1 = 0.f;
    float acc[4][4];
    #pragma unroll
    for (int nt=0;nt<4;nt++){ acc[nt][0]=0.f; acc[nt][1]=0.f; acc[nt][2]=0.f; acc[nt][3]=0.f; }

    const int* mrow = mask + (size_t)b*Nn*Nn + (size_t)i0*Nn;
    int mr = tid >> 3, moct = tid & 7;
    int fjj = tid >> 5, fc4 = tid & 31;

    int c0 = split * CPS;
    for (int c = c0; c < c0 + CPS; c++){
        int j0 = c * TJ;
        __syncthreads();

        const float* srch = g_hi + ((size_t)b*NP + j0)*Dd;
        const float* srcl = g_lo + ((size_t)b*NP + j0)*Dd;
        #pragma unroll
        for (int u=0; u<8; u++){
            int jj = fjj + u*8;
            uint32_t doff = (uint32_t)(jj*(PITCH*4) + fc4*16);
            cp16(sb_hhi + doff, srch + (size_t)jj*Dd + fc4*4);
            cp16(sb_hlo + doff, srcl + (size_t)jj*Dd + fc4*4);
        }
        CP_COMMIT();

        {
            int hh = tid >> 6, jj = tid & 63;
            t_tile[hh*TJ + jj] = (j0+jj < Nn) ? g_sdst[(b*NHEADS+hh)*Nn + j0+jj] : 0.f;
        }
        {
            unsigned int byte = 0;
            int j = j0 + moct*8;
            if (i0 + mr < Nn){
                const int* p = mrow + (size_t)mr*Nn + j;
                if (j + 7 < Nn){
                    int4 A = *(const int4*)p;
                    int4 Bv = *(const int4*)(p+4);
                    byte = (unsigned)(A.x!=0) | ((unsigned)(A.y!=0)<<1)
                         | ((unsigned)(A.z!=0)<<2) | ((unsigned)(A.w!=0)<<3)
                         | ((unsigned)(Bv.x!=0)<<4) | ((unsigned)(Bv.y!=0)<<5)
                         | ((unsigned)(Bv.z!=0)<<6) | ((unsigned)(Bv.w!=0)<<7);
                } else {
                    #pragma unroll
                    for (int k=0;k<8;k++)
                        if (j+k < Nn && p[k] != 0) byte |= (1u<<k);
                }
            }
            ((unsigned char*)m_bits)[mr*8 + moct] = (unsigned char)byte;
        }
        CP_WAIT0();
        __syncthreads();

        unsigned long long bits0 = m_bits[il0] >> t;
        unsigned long long bits1 = m_bits[il1] >> t;

        #pragma unroll
        for (int s=0; s<8; s++){
            float ta = t_tile[h*TJ + s*8 + t];
            float tb = t_tile[h*TJ + s*8 + t + 4];
            float e00 = lrelu(s0 + ta), e01 = lrelu(s0 + tb);
            float e10 = lrelu(s1 + ta), e11 = lrelu(s1 + tb);
            float w00 = ((bits0 >> (8*s))   & 1ull) ? exp2f(fmaf(e00, LOG2E, -m20)) : 0.f;
            float w01 = ((bits0 >> (8*s+4)) & 1ull) ? exp2f(fmaf(e01, LOG2E, -m20)) : 0.f;
            float w10 = ((bits1 >> (8*s))   & 1ull) ? exp2f(fmaf(e10, LOG2E, -m21)) : 0.f;
            float w11 = ((bits1 >> (8*s+4)) & 1ull) ? exp2f(fmaf(e11, LOG2E, -m21)) : 0.f;
            lv0 += w00 + w01;
            lv1 += w10 + w11;
            uint32_t ah0 = tf32_rna(w00), ah1 = tf32_rna(w10);
            uint32_t ah2 = tf32_rna(w01), ah3 = tf32_rna(w11);
            uint32_t al0 = __float_as_uint(w00 - __uint_as_float(ah0));
            uint32_t al1 = __float_as_uint(w10 - __uint_as_float(ah1));
            uint32_t al2 = __float_as_uint(w01 - __uint_as_float(ah2));
            uint32_t al3 = __float_as_uint(w11 - __uint_as_float(ah3));
            int r0 = (s*8 + t)*PITCH + h*32 + g;
            int r1 = r0 + 4*PITCH;
            #pragma unroll
            for (int nt=0; nt<4; nt++){
                uint32_t bh0 = __float_as_uint(h_hi[r0 + nt*8]);
                uint32_t bh1 = __float_as_uint(h_hi[r1 + nt*8]);
                uint32_t bl0 = __float_as_uint(h_lo[r0 + nt*8]);
                uint32_t bl1 = __float_as_uint(h_lo[r1 + nt*8]);
                mma_tf32(acc[nt], ah0, ah1, ah2, ah3, bh0, bh1);
                mma_tf32(acc[nt], ah0, ah1, ah2, ah3, bl0, bl1);
                mma_tf32(acc[nt], al0, al1, al2, al3, bh0, bh1);
            }
        }
    }

    lv0 += __shfl_xor_sync(0xffffffffu, lv0, 1);
    lv0 += __shfl_xor_sync(0xffffffffu, lv0, 2);
    lv1 += __shfl_xor_sync(0xffffffffu, lv1, 1);
    lv1 += __shfl_xor_sync(0xffffffffu, lv1, 2);
    if (t == 0){
        if (gi0 < Nn) g_plv[split][(b*NHEADS+h)*Nn + gi0] = lv0;
        if (gi1 < Nn) g_plv[split][(b*NHEADS+h)*Nn + gi1] = lv1;
    }

    float* pac = g_pacc[split];
    #pragma unroll
    for (int nt=0; nt<4; nt++){
        int d0 = h*32 + nt*8 + 2*t;
        if (gi0 < Nn){
            size_t x = ((size_t)(b*Nn + gi0))*Dd + d0;
            *(float2*)(pac + x) = make_float2(acc[nt][0], acc[nt][1]);
        }
        if (gi1 < Nn){
            size_t x = ((size_t)(b*Nn + gi1))*Dd + d0;
            *(float2*)(pac + x) = make_float2(acc[nt][2], acc[nt][3]);
        }
    }
}

// ---------------- factor attention: U -> A ----------------
__global__ void fa_kernel(const float* __restrict__ feats,
    const float* __restrict__ projW, float* __restrict__ A)
{
    __shared__ float pw[64][65];
    __shared__ float ft[64][64];
    int tid = threadIdx.x;
    int ntile = blockIdx.x & 31;
    int hb_   = blockIdx.x >> 5;
    int hn = hb_ >> 1, b = hb_ & 1;
    int n0 = ntile*64;
    const float* P = projW + (size_t)hn*64*64;
    for (int idx=tid; idx<4096; idx+=256) pw[idx>>6][idx&63] = P[idx];
    for (int idx=tid; idx<4096; idx+=256){
        int r=idx>>6, m=idx&63; int n=n0+r;
        ft[r][m] = (n<Nn) ? feats[((size_t)(b*Nn+n))*Ff+m] : 0.f;
    }
    __syncthreads();
    int w = tid>>5, lane = tid&31;
    for (int rr=0; rr<8; rr++){
        int r = w*8+rr; int n=n0+r;
        if (n>=Nn) continue;
        float u0=0.f,u1=0.f;
        #pragma unroll
        for (int m=0;m<64;m++){
            float f = ft[r][m];
            u0 += f*pw[lane][m];
            u1 += f*pw[lane+32][m];
        }
        u0 = lrelu(u0); u1 = lrelu(u1);
        float mx = fmaxf(u0,u1);
        #pragma unroll
        for (int off=16; off; off>>=1)
            mx = fmaxf(mx, __shfl_xor_sync(0xffffffffu, mx, off));
        float e0 = __expf(u0-mx), e1 = __expf(u1-mx);
        float ss = e0+e1;
        #pragma unroll
        for (int off=16; off; off>>=1)
            ss += __shfl_xor_sync(0xffffffffu, ss, off);
        float inv = 1.f/ss;
        size_t base = ((size_t)hb_*Nn + n)*64;
        A[base+lane]    = e0*inv;
        A[base+lane+32] = e1*inv;
    }
}

// ---------------- a_bar = A.mean(axis=n) ----------------
__global__ void abar_kernel(const float* __restrict__ A)
{
    __shared__ float red[8][64];
    int tid=threadIdx.x; int k=tid&63, grp=tid>>6;
    const float* base = A + (size_t)blockIdx.x*Nn*64;
    float s=0.f;
    for (int n=grp; n<Nn; n+=8) s += base[(size_t)n*64+k];
    red[grp][k]=s;
    __syncthreads();
    if (grp==0){
        float t=0.f;
        #pragma unroll
        for (int g=0; g<8; g++) t += red[g][k];
        g_abar[blockIdx.x*64+k] = t * (1.f/Nn);
    }
}

// ---------------- recon = feats @ a_bar ----------------
__global__ void recon_kernel(const float* __restrict__ feats, float* __restrict__ out)
{
    int w = threadIdx.x>>5, lane=threadIdx.x&31;
    int ro = blockIdx.x*8 + w;
    if (ro >= HN*Bb*Nn) return;
    int hn = ro / (Bb*Nn);
    int rem = ro % (Bb*Nn);
    int b = rem / Nn, n = rem % Nn;
    const float* f  = feats  + (size_t)(b*Nn+n)*Ff;
    const float* ab = g_abar + (hn*Bb+b)*Ff;
    float p = f[lane]*ab[lane] + f[lane+32]*ab[lane+32];
    #pragma unroll
    for (int off=16; off; off>>=1)
        p += __shfl_xor_sync(0xffffffffu, p, off);
    if (lane==0) out[ro] = p;
}

extern "C" void kernel_launch(void* const* d_in, const int* in_sizes, int n_in,
                              void* d_out, int out_size)
{
    const float* feats = (const float*)d_in[0];
    const int* ind = (const int*)d_in[1];
    const int* uni = (const int*)d_in[2];
    const float* bn_g = (const float*)d_in[3];
    const float* bn_b = (const float*)d_in[4];
    const float* bn_m = (const float*)d_in[5];
    const float* bn_v = (const float*)d_in[6];
    const float* W1   = (const float*)d_in[7];
    const float* b1   = (const float*)d_in[8];
    const float* W2   = (const float*)d_in[9];
    const float* b2   = (const float*)d_in[10];
    const float* giW  = (const float*)d_in[11];
    const float* gias = (const float*)d_in[12];
    const float* giad = (const float*)d_in[13];
    const float* guW  = (const float*)d_in[14];
    const float* guas = (const float*)d_in[15];
    const float* guad = (const float*)d_in[16];
    const float* hW   = (const float*)d_in[17];
    const float* hb   = (const float*)d_in[18];
    const float* pW   = (const float*)d_in[19];

    float* out  = (float*)d_out;
    float* C    = out;
    float* CBI  = out + 512000;
    float* CBU  = out + 1024000;
    float* HI   = out + 1536000;
    float* HU   = out + 2048000;
    float* FOUT = out + 2560000;
    float* ROUT = out + 2572000;
    float* AOUT = out + 2584000;

    static int smem_set = 0;
    const int smem_bytes = SM_FLOATS * 4;
    if (!smem_set){
        cudaFuncSetAttribute(gat_attn_tc,
            cudaFuncAttributeMaxDynamicSharedMemorySize, smem_bytes);
        smem_set = 1;
    }

    enc_proj1<<<500,256>>>(feats, bn_g, bn_b, bn_m, bn_v, W1, b1, W2, b2, C,
                           giW, gias, giad);
    tmax_kernel<<<8,256>>>();
    gat_attn_tc<<<Bb*NTILES*SPLITS,256,smem_bytes>>>(ind);

    comb_proj2<<<500,256>>>(C, guW, guas, guad, HI, CBI);
    tmax_kernel<<<8,256>>>();
    gat_attn_tc<<<Bb*NTILES*SPLITS,256,smem_bytes>>>(uni);

    comb2_fact<<<500,256>>>(C, CBI, hW, hb, HU, CBU, FOUT);

    fa_kernel<<<192,256>>>(feats, pW, AOUT);
    abar_kernel<<<6,512>>>(AOUT);
    recon_kernel<<<1500,256>>>(feats, ROUT);
}

// round 12
// speedup vs baseline: 1.9195x; 1.0498x over previous
#include <cuda_runtime.h>
#include <cstdint>

#define Bb 2
#define Nn 2000
#define NP 2048
#define Ff 64
#define Dd 128
#define NHEADS 4
#define DH 32
#define HN 3
#define DEEP 384
#define SLOPE 0.1f
#define NEG_INF -1e30f
#define TJ 64
#define NTILES 63
#define NCHUNK 32
#define SPLITS 16
#define CPS (NCHUNK/SPLITS)
#define LOG2E 1.44269504f
#define PITCH 136

__device__ float g_hv[Bb*NP*Dd];
__device__ float g_ssrc[Bb*NHEADS*Nn];
__device__ float g_sdst[Bb*NHEADS*Nn];
__device__ float g_tmax[Bb*NHEADS];
__device__ float g_abar[HN*Bb*Ff];
__device__ float g_pacc[SPLITS][Bb*Nn*Dd];
__device__ float g_plv[SPLITS][Bb*NHEADS*Nn];

__device__ __forceinline__ float lrelu(float x){ return fmaxf(x, SLOPE*x); }

__device__ __forceinline__ uint32_t tf32_rna(float x){
    uint32_t r;
    asm("cvt.rna.tf32.f32 %0, %1;" : "=r"(r) : "f"(x));
    return r;
}
__device__ __forceinline__ void mma_tf32(float* c,
    uint32_t a0, uint32_t a1, uint32_t a2, uint32_t a3,
    uint32_t b0, uint32_t b1)
{
    asm volatile(
        "mma.sync.aligned.m16n8k8.row.col.f32.tf32.tf32.f32 "
        "{%0,%1,%2,%3}, {%4,%5,%6,%7}, {%8,%9}, {%0,%1,%2,%3};"
        : "+f"(c[0]), "+f"(c[1]), "+f"(c[2]), "+f"(c[3])
        : "r"(a0), "r"(a1), "r"(a2), "r"(a3), "r"(b0), "r"(b1));
}
__device__ __forceinline__ uint32_t smem_u32(const void* p){
    uint32_t a;
    asm("{ .reg .u64 t; cvta.to.shared.u64 t, %1; cvt.u32.u64 %0, t; }" : "=r"(a) : "l"(p));
    return a;
}
__device__ __forceinline__ void cp16(uint32_t dst, const void* src){
    asm volatile("cp.async.cg.shared.global [%0], [%1], 16;" :: "r"(dst), "l"(src));
}
#define CP_COMMIT() asm volatile("cp.async.commit_group;" ::: "memory")
#define CP_WAIT0()  asm volatile("cp.async.wait_group 0;" ::: "memory")

// ---- proj tail, 8 rows: xs[8][Dd] -> g_hv + scores --------------------------
__device__ __forceinline__ void proj_tail8(const float xs[8][Dd],
    const float* __restrict__ W, const float* __restrict__ a_src,
    const float* __restrict__ a_dst, int row0, int tid)
{
    int col = tid & 127, grp = tid >> 7;
    float acc[4];
    #pragma unroll
    for (int r=0;r<4;r++) acc[r]=0.f;
    #pragma unroll 4
    for (int k=0;k<Dd;k++){
        float w = W[k*Dd + col];
        #pragma unroll
        for (int r=0;r<4;r++) acc[r] += xs[grp*4+r][k]*w;
    }
    int head = col >> 5, lane = col & 31;
    float av = a_src[head*DH + lane];
    float bv = a_dst[head*DH + lane];
    #pragma unroll
    for (int r=0;r<4;r++){
        int g = row0 + grp*4 + r;
        int b = g / Nn, n = g % Nn;
        g_hv[((size_t)(b*NP + n))*Dd + col] = acc[r];
        float p = acc[r]*av, q = acc[r]*bv;
        #pragma unroll
        for (int off=16; off; off>>=1){
            p += __shfl_xor_sync(0xffffffffu, p, off);
            q += __shfl_xor_sync(0xffffffffu, q, off);
        }
        if (lane == 0){
            g_ssrc[(b*NHEADS+head)*Nn + n] = p;
            g_sdst[(b*NHEADS+head)*Nn + n] = q;
        }
    }
}

// ---- warp-per-row combine: returns o and writes H; acc over SPLITS ----------
__device__ __forceinline__ float4 combine_row(int gr, int lane)
{
    int b = gr / Nn, i = gr % Nn;
    int head = lane >> 3;
    size_t x4 = (size_t)gr*Dd + lane*4;
    float4 a = make_float4(0.f,0.f,0.f,0.f);
    float lv = 0.f;
    #pragma unroll
    for (int s=0;s<SPLITS;s++){
        float4 p = *(const float4*)(g_pacc[s] + x4);
        a.x += p.x; a.y += p.y; a.z += p.z; a.w += p.w;
        lv += g_plv[s][(b*NHEADS+head)*Nn + i];
    }
    float inv = 1.f / lv;
    return make_float4(a.x*inv, a.y*inv, a.z*inv, a.w*inv);
}

// ---------------- fused BN + encoder MLP + GAT1 projection (8 rows) ---------
__global__ __launch_bounds__(256) void enc_proj1(const float* __restrict__ feats,
    const float* __restrict__ gamma, const float* __restrict__ beta,
    const float* __restrict__ mean, const float* __restrict__ var,
    const float* __restrict__ W1, const float* __restrict__ b1,
    const float* __restrict__ W2, const float* __restrict__ b2,
    float* __restrict__ C,
    const float* __restrict__ giW, const float* __restrict__ gias,
    const float* __restrict__ giad)
{
    __shared__ float xn[8][Ff];
    __shared__ float hid[8][Dd];
    __shared__ float xs[8][Dd];
    int tid = threadIdx.x;
    int col = tid & 127, grp = tid >> 7;
    int row0 = blockIdx.x * 8;
    for (int idx = tid; idx < 8*Ff; idx += 256) {
        int r = idx >> 6, f = idx & 63;
        float v = feats[(size_t)(row0+r)*Ff + f];
        xn[r][f] = (v - mean[f]) * rsqrtf(var[f] + 1e-5f) * gamma[f] + beta[f];
    }
    __syncthreads();
    float acc[4];
    float bb = b1[col];
    #pragma unroll
    for (int r=0;r<4;r++) acc[r] = bb;
    #pragma unroll 4
    for (int f=0; f<Ff; f++){
        float w = W1[f*Dd + col];
        #pragma unroll
        for (int r=0;r<4;r++) acc[r] += xn[grp*4+r][f]*w;
    }
    #pragma unroll
    for (int r=0;r<4;r++) hid[grp*4+r][col] = fmaxf(acc[r], 0.f);
    __syncthreads();
    bb = b2[col];
    #pragma unroll
    for (int r=0;r<4;r++) acc[r] = bb;
    #pragma unroll 4
    for (int k=0;k<Dd;k++){
        float w = W2[k*Dd + col];
        #pragma unroll
        for (int r=0;r<4;r++) acc[r] += hid[grp*4+r][k]*w;
    }
    #pragma unroll
    for (int r=0;r<4;r++){
        C[(size_t)(row0+grp*4+r)*Dd + col] = acc[r];
        xs[grp*4+r][col] = acc[r];
    }
    __syncthreads();
    proj_tail8(xs, giW, gias, giad, row0, tid);

    // zero padding rows [Nn,NP) of g_hv
    int tg = blockIdx.x*256 + tid;
    if (tg < Bb*(NP-Nn)*Dd){
        int bb2 = tg / ((NP-Nn)*Dd);
        int rem = tg % ((NP-Nn)*Dd);
        g_hv[((size_t)(bb2*NP + Nn))*Dd + rem] = 0.f;
    }
}

// ---------------- fused combine(GAT1) + GAT2 projection (8 rows) ------------
__global__ __launch_bounds__(256) void comb_proj2(const float* __restrict__ C,
    const float* __restrict__ guW, const float* __restrict__ guas,
    const float* __restrict__ guad,
    float* __restrict__ HI, float* __restrict__ CBI)
{
    __shared__ float xs[8][Dd];
    int tid = threadIdx.x;
    int w = tid >> 5, lane = tid & 31;
    int row0 = blockIdx.x * 8;
    int gr = row0 + w;
    {
        float4 o = combine_row(gr, lane);
        size_t x4 = (size_t)gr*Dd + lane*4;
        float4 ci = *(const float4*)(C + x4);
        float4 cb = make_float4(ci.x-o.x, ci.y-o.y, ci.z-o.z, ci.w-o.w);
        *(float4*)(HI + x4)  = o;
        *(float4*)(CBI + x4) = cb;
        *(float4*)&xs[w][lane*4] = cb;
    }
    __syncthreads();
    proj_tail8(xs, guW, guas, guad, row0, tid);
}

// ---------------- fused combine(GAT2) + factor heads (8 rows) ---------------
__global__ __launch_bounds__(256) void comb2_fact(const float* __restrict__ Cc,
    const float* __restrict__ CBI,
    const float* __restrict__ hW, const float* __restrict__ hb,
    float* __restrict__ HU, float* __restrict__ CBU, float* __restrict__ FOUT)
{
    __shared__ float cbis[8][Dd];
    __shared__ float cbus[8][Dd];
    int tid = threadIdx.x;
    int w = tid >> 5, lane = tid & 31;
    int row0 = blockIdx.x * 8;
    int gr = row0 + w;
    {
        float4 o = combine_row(gr, lane);
        size_t x4 = (size_t)gr*Dd + lane*4;
        float4 ci = *(const float4*)(CBI + x4);
        float4 cb = make_float4(ci.x-o.x, ci.y-o.y, ci.z-o.z, ci.w-o.w);
        *(float4*)(HU + x4)  = o;
        *(float4*)(CBU + x4) = cb;
        *(float4*)&cbis[w][lane*4] = ci;
        *(float4*)&cbus[w][lane*4] = cb;
    }
    __syncthreads();
    // factors: warp w owns local row w
    float a0=0.f, a1=0.f, a2=0.f;
    #pragma unroll
    for (int it=0; it<12; it++){
        int idx = it*32 + lane;
        float v;
        if (idx < 128)      v = Cc[(size_t)gr*Dd + idx];
        else if (idx < 256) v = cbis[w][idx-128];
        else                v = cbus[w][idx-256];
        a0 += v*hW[0*DEEP+idx];
        a1 += v*hW[1*DEEP+idx];
        a2 += v*hW[2*DEEP+idx];
    }
    #pragma unroll
    for (int off=16; off; off>>=1){
        a0 += __shfl_xor_sync(0xffffffffu, a0, off);
        a1 += __shfl_xor_sync(0xffffffffu, a1, off);
        a2 += __shfl_xor_sync(0xffffffffu, a2, off);
    }
    if (lane==0){
        FOUT[0*Bb*Nn + gr] = lrelu(a0 + hb[0]);
        FOUT[1*Bb*Nn + gr] = lrelu(a1 + hb[1]);
        FOUT[2*Bb*Nn + gr] = lrelu(a2 + hb[2]);
    }
}

// ---------------- per-(b,head) max of s_dst ----------------
__global__ void tmax_kernel()
{
    __shared__ float red[256];
    const float* t = g_sdst + blockIdx.x * Nn;
    float m = NEG_INF;
    for (int n = threadIdx.x; n < Nn; n += 256) m = fmaxf(m, t[n]);
    red[threadIdx.x] = m;
    __syncthreads();
    #pragma unroll
    for (int s=128; s; s>>=1){
        if (threadIdx.x < s) red[threadIdx.x] = fmaxf(red[threadIdx.x], red[threadIdx.x+s]);
        __syncthreads();
    }
    if (threadIdx.x == 0) g_tmax[blockIdx.x] = red[0];
}

// ---------------- GAT attention: tf32 mma.sync, single h tile ----------------
#define SM_H   0
#define SM_T   (TJ*PITCH)
#define SM_MB  (TJ*PITCH + NHEADS*TJ)
#define SM_FLOATS (TJ*PITCH + NHEADS*TJ + 64)

__global__ __launch_bounds__(256) void gat_attn_tc(const int* __restrict__ mask)
{
    extern __shared__ float sm[];
    float* h_t = sm + SM_H;
    float* t_tile = sm + SM_T;
    unsigned long long* m_bits = (unsigned long long*)(sm + SM_MB);
    uint32_t sbase = smem_u32(sm);
    uint32_t sb_h = sbase + SM_H*4;

    int tid = threadIdx.x;
    int w = tid >> 5, lane = tid & 31;
    int h = w & 3, mh = w >> 2;
    int g = lane >> 2, t = lane & 3;
    int split = blockIdx.x % SPLITS;
    int tmp   = blockIdx.x / SPLITS;
    int b     = tmp / NTILES;
    int i0    = (tmp % NTILES) * 32;
    int il0 = mh*16 + g, il1 = il0 + 8;
    int gi0 = i0 + il0, gi1 = i0 + il1;

    float tmx = g_tmax[b*NHEADS + h];
    float s0 = (gi0 < Nn) ? g_ssrc[(b*NHEADS+h)*Nn + gi0] : 0.f;
    float s1 = (gi1 < Nn) ? g_ssrc[(b*NHEADS+h)*Nn + gi1] : 0.f;
    float m20 = lrelu(s0 + tmx) * LOG2E;
    float m21 = lrelu(s1 + tmx) * LOG2E;
    float lv0 = 0.f, lv1 = 0.f;
    float acc[4][4];
    #pragma unroll
    for (int nt=0;nt<4;nt++){ acc[nt][0]=0.f; acc[nt][1]=0.f; acc[nt][2]=0.f; acc[nt][3]=0.f; }

    const int* mrow = mask + (size_t)b*Nn*Nn + (size_t)i0*Nn;
    int mr = tid >> 3, moct = tid & 7;
    int fjj = tid >> 5, fc4 = tid & 31;

    int c0 = split * CPS;
    for (int c = c0; c < c0 + CPS; c++){
        int j0 = c * TJ;
        __syncthreads();

        const float* srch = g_hv + ((size_t)b*NP + j0)*Dd;
        #pragma unroll
        for (int u=0; u<8; u++){
            int jj = fjj + u*8;
            cp16(sb_h + (uint32_t)(jj*(PITCH*4) + fc4*16), srch + (size_t)jj*Dd + fc4*4);
        }
        CP_COMMIT();

        {
            int hh = tid >> 6, jj = tid & 63;
            t_tile[hh*TJ + jj] = (j0+jj < Nn) ? g_sdst[(b*NHEADS+hh)*Nn + j0+jj] : 0.f;
        }
        {
            unsigned int byte = 0;
            int j = j0 + moct*8;
            if (i0 + mr < Nn){
                const int* p = mrow + (size_t)mr*Nn + j;
                if (j + 7 < Nn){
                    int4 A = *(const int4*)p;
                    int4 Bv = *(const int4*)(p+4);
                    byte = (unsigned)(A.x!=0) | ((unsigned)(A.y!=0)<<1)
                         | ((unsigned)(A.z!=0)<<2) | ((unsigned)(A.w!=0)<<3)
                         | ((unsigned)(Bv.x!=0)<<4) | ((unsigned)(Bv.y!=0)<<5)
                         | ((unsigned)(Bv.z!=0)<<6) | ((unsigned)(Bv.w!=0)<<7);
                } else {
                    #pragma unroll
                    for (int k=0;k<8;k++)
                        if (j+k < Nn && p[k] != 0) byte |= (1u<<k);
                }
            }
            ((unsigned char*)m_bits)[mr*8 + moct] = (unsigned char)byte;
        }
        CP_WAIT0();
        __syncthreads();

        unsigned long long bits0 = m_bits[il0] >> t;
        unsigned long long bits1 = m_bits[il1] >> t;

        #pragma unroll
        for (int s=0; s<8; s++){
            float ta = t_tile[h*TJ + s*8 + t];
            float tb = t_tile[h*TJ + s*8 + t + 4];
            float e00 = lrelu(s0 + ta), e01 = lrelu(s0 + tb);
            float e10 = lrelu(s1 + ta), e11 = lrelu(s1 + tb);
            float w00 = ((bits0 >> (8*s))   & 1ull) ? exp2f(fmaf(e00, LOG2E, -m20)) : 0.f;
            float w01 = ((bits0 >> (8*s+4)) & 1ull) ? exp2f(fmaf(e01, LOG2E, -m20)) : 0.f;
            float w10 = ((bits1 >> (8*s))   & 1ull) ? exp2f(fmaf(e10, LOG2E, -m21)) : 0.f;
            float w11 = ((bits1 >> (8*s+4)) & 1ull) ? exp2f(fmaf(e11, LOG2E, -m21)) : 0.f;
            lv0 += w00 + w01;
            lv1 += w10 + w11;
            uint32_t ah0 = tf32_rna(w00), ah1 = tf32_rna(w10);
            uint32_t ah2 = tf32_rna(w01), ah3 = tf32_rna(w11);
            uint32_t al0 = __float_as_uint(w00 - __uint_as_float(ah0));
            uint32_t al1 = __float_as_uint(w10 - __uint_as_float(ah1));
            uint32_t al2 = __float_as_uint(w01 - __uint_as_float(ah2));
            uint32_t al3 = __float_as_uint(w11 - __uint_as_float(ah3));
            int r0 = (s*8 + t)*PITCH + h*32 + g;
            int r1 = r0 + 4*PITCH;
            #pragma unroll
            for (int nt=0; nt<4; nt++){
                float f0 = h_t[r0 + nt*8];
                float f1 = h_t[r1 + nt*8];
                uint32_t bh0 = tf32_rna(f0);
                uint32_t bh1 = tf32_rna(f1);
                uint32_t bl0 = __float_as_uint(f0 - __uint_as_float(bh0));
                uint32_t bl1 = __float_as_uint(f1 - __uint_as_float(bh1));
                mma_tf32(acc[nt], ah0, ah1, ah2, ah3, bh0, bh1);
                mma_tf32(acc[nt], ah0, ah1, ah2, ah3, bl0, bl1);
                mma_tf32(acc[nt], al0, al1, al2, al3, bh0, bh1);
            }
        }
    }

    lv0 += __shfl_xor_sync(0xffffffffu, lv0, 1);
    lv0 += __shfl_xor_sync(0xffffffffu, lv0, 2);
    lv1 += __shfl_xor_sync(0xffffffffu, lv1, 1);
    lv1 += __shfl_xor_sync(0xffffffffu, lv1, 2);
    if (t == 0){
        if (gi0 < Nn) g_plv[split][(b*NHEADS+h)*Nn + gi0] = lv0;
        if (gi1 < Nn) g_plv[split][(b*NHEADS+h)*Nn + gi1] = lv1;
    }

    float* pac = g_pacc[split];
    #pragma unroll
    for (int nt=0; nt<4; nt++){
        int d0 = h*32 + nt*8 + 2*t;
        if (gi0 < Nn){
            size_t x = ((size_t)(b*Nn + gi0))*Dd + d0;
            *(float2*)(pac + x) = make_float2(acc[nt][0], acc[nt][1]);
        }
        if (gi1 < Nn){
            size_t x = ((size_t)(b*Nn + gi1))*Dd + d0;
            *(float2*)(pac + x) = make_float2(acc[nt][2], acc[nt][3]);
        }
    }
}

// ---------------- factor attention: U -> A ----------------
__global__ void fa_kernel(const float* __restrict__ feats,
    const float* __restrict__ projW, float* __restrict__ A)
{
    __shared__ float pw[64][65];
    __shared__ float ft[64][64];
    int tid = threadIdx.x;
    int ntile = blockIdx.x & 31;
    int hb_   = blockIdx.x >> 5;
    int hn = hb_ >> 1, b = hb_ & 1;
    int n0 = ntile*64;
    const float* P = projW + (size_t)hn*64*64;
    for (int idx=tid; idx<4096; idx+=256) pw[idx>>6][idx&63] = P[idx];
    for (int idx=tid; idx<4096; idx+=256){
        int r=idx>>6, m=idx&63; int n=n0+r;
        ft[r][m] = (n<Nn) ? feats[((size_t)(b*Nn+n))*Ff+m] : 0.f;
    }
    __syncthreads();
    int w = tid>>5, lane = tid&31;
    for (int rr=0; rr<8; rr++){
        int r = w*8+rr; int n=n0+r;
        if (n>=Nn) continue;
        float u0=0.f,u1=0.f;
        #pragma unroll
        for (int m=0;m<64;m++){
            float f = ft[r][m];
            u0 += f*pw[lane][m];
            u1 += f*pw[lane+32][m];
        }
        u0 = lrelu(u0); u1 = lrelu(u1);
        float mx = fmaxf(u0,u1);
        #pragma unroll
        for (int off=16; off; off>>=1)
            mx = fmaxf(mx, __shfl_xor_sync(0xffffffffu, mx, off));
        float e0 = __expf(u0-mx), e1 = __expf(u1-mx);
        float ss = e0+e1;
        #pragma unroll
        for (int off=16; off; off>>=1)
            ss += __shfl_xor_sync(0xffffffffu, ss, off);
        float inv = 1.f/ss;
        size_t base = ((size_t)hb_*Nn + n)*64;
        A[base+lane]    = e0*inv;
        A[base+lane+32] = e1*inv;
    }
}

// ---------------- a_bar = A.mean(axis=n) ----------------
__global__ void abar_kernel(const float* __restrict__ A)
{
    __shared__ float red[8][64];
    int tid=threadIdx.x; int k=tid&63, grp=tid>>6;
    const float* base = A + (size_t)blockIdx.x*Nn*64;
    float s=0.f;
    for (int n=grp; n<Nn; n+=8) s += base[(size_t)n*64+k];
    red[grp][k]=s;
    __syncthreads();
    if (grp==0){
        float t=0.f;
        #pragma unroll
        for (int g=0; g<8; g++) t += red[g][k];
        g_abar[blockIdx.x*64+k] = t * (1.f/Nn);
    }
}

// ---------------- recon = feats @ a_bar ----------------
__global__ void recon_kernel(const float* __restrict__ feats, float* __restrict__ out)
{
    int w = threadIdx.x>>5, lane=threadIdx.x&31;
    int ro = blockIdx.x*8 + w;
    if (ro >= HN*Bb*Nn) return;
    int hn = ro / (Bb*Nn);
    int rem = ro % (Bb*Nn);
    int b = rem / Nn, n = rem % Nn;
    const float* f  = feats  + (size_t)(b*Nn+n)*Ff;
    const float* ab = g_abar + (hn*Bb+b)*Ff;
    float p = f[lane]*ab[lane] + f[lane+32]*ab[lane+32];
    #pragma unroll
    for (int off=16; off; off>>=1)
        p += __shfl_xor_sync(0xffffffffu, p, off);
    if (lane==0) out[ro] = p;
}

extern "C" void kernel_launch(void* const* d_in, const int* in_sizes, int n_in,
                              void* d_out, int out_size)
{
    const float* feats = (const float*)d_in[0];
    const int* ind = (const int*)d_in[1];
    const int* uni = (const int*)d_in[2];
    const float* bn_g = (const float*)d_in[3];
    const float* bn_b = (const float*)d_in[4];
    const float* bn_m = (const float*)d_in[5];
    const float* bn_v = (const float*)d_in[6];
    const float* W1   = (const float*)d_in[7];
    const float* b1   = (const float*)d_in[8];
    const float* W2   = (const float*)d_in[9];
    const float* b2   = (const float*)d_in[10];
    const float* giW  = (const float*)d_in[11];
    const float* gias = (const float*)d_in[12];
    const float* giad = (const float*)d_in[13];
    const float* guW  = (const float*)d_in[14];
    const float* guas = (const float*)d_in[15];
    const float* guad = (const float*)d_in[16];
    const float* hW   = (const float*)d_in[17];
    const float* hb   = (const float*)d_in[18];
    const float* pW   = (const float*)d_in[19];

    float* out  = (float*)d_out;
    float* C    = out;
    float* CBI  = out + 512000;
    float* CBU  = out + 1024000;
    float* HI   = out + 1536000;
    float* HU   = out + 2048000;
    float* FOUT = out + 2560000;
    float* ROUT = out + 2572000;
    float* AOUT = out + 2584000;

    static int smem_set = 0;
    const int smem_bytes = SM_FLOATS * 4;
    if (!smem_set){
        cudaFuncSetAttribute(gat_attn_tc,
            cudaFuncAttributeMaxDynamicSharedMemorySize, smem_bytes);
        smem_set = 1;
    }

    enc_proj1<<<500,256>>>(feats, bn_g, bn_b, bn_m, bn_v, W1, b1, W2, b2, C,
                           giW, gias, giad);
    tmax_kernel<<<8,256>>>();
    gat_attn_tc<<<Bb*NTILES*SPLITS,256,smem_bytes>>>(ind);

    comb_proj2<<<500,256>>>(C, guW, guas, guad, HI, CBI);
    tmax_kernel<<<8,256>>>();
    gat_attn_tc<<<Bb*NTILES*SPLITS,256,smem_bytes>>>(uni);

    comb2_fact<<<500,256>>>(C, CBI, hW, hb, HU, CBU, FOUT);

    fa_kernel<<<192,256>>>(feats, pW, AOUT);
    abar_kernel<<<6,512>>>(AOUT);
    recon_kernel<<<1500,256>>>(feats, ROUT);
}

// round 13
// speedup vs baseline: 2.0882x; 1.0879x over previous
#include <cuda_runtime.h>
#include <cstdint>

#define Bb 2
#define Nn 2000
#define NP 2048
#define Ff 64
#define Dd 128
#define NHEADS 4
#define DH 32
#define HN 3
#define DEEP 384
#define SLOPE 0.1f
#define NEG_INF -1e30f
#define TJ 64
#define NTILES 63
#define NCHUNK 32
#define SPLITS 8
#define CPS (NCHUNK/SPLITS)
#define LOG2E 1.44269504f
#define PITCH 136

__device__ float g_hv[Bb*NP*Dd];
__device__ float g_ssrc[Bb*NHEADS*Nn];
__device__ float g_sdst[Bb*NHEADS*Nn];
__device__ float g_tmax[Bb*NHEADS];
__device__ float g_abar[HN*Bb*Ff];
__device__ float g_pacc[SPLITS][Bb*Nn*Dd];
__device__ float g_plv[SPLITS][Bb*NHEADS*Nn];

__device__ __forceinline__ float lrelu(float x){ return fmaxf(x, SLOPE*x); }

__device__ __forceinline__ uint32_t tf32_rna(float x){
    uint32_t r;
    asm("cvt.rna.tf32.f32 %0, %1;" : "=r"(r) : "f"(x));
    return r;
}
__device__ __forceinline__ void mma_tf32(float* c,
    uint32_t a0, uint32_t a1, uint32_t a2, uint32_t a3,
    uint32_t b0, uint32_t b1)
{
    asm volatile(
        "mma.sync.aligned.m16n8k8.row.col.f32.tf32.tf32.f32 "
        "{%0,%1,%2,%3}, {%4,%5,%6,%7}, {%8,%9}, {%0,%1,%2,%3};"
        : "+f"(c[0]), "+f"(c[1]), "+f"(c[2]), "+f"(c[3])
        : "r"(a0), "r"(a1), "r"(a2), "r"(a3), "r"(b0), "r"(b1));
}
__device__ __forceinline__ uint32_t smem_u32(const void* p){
    uint32_t a;
    asm("{ .reg .u64 t; cvta.to.shared.u64 t, %1; cvt.u32.u64 %0, t; }" : "=r"(a) : "l"(p));
    return a;
}
__device__ __forceinline__ void cp16(uint32_t dst, const void* src){
    asm volatile("cp.async.cg.shared.global [%0], [%1], 16;" :: "r"(dst), "l"(src));
}
#define CP_COMMIT() asm volatile("cp.async.commit_group;" ::: "memory")
#define CP_WAIT0()  asm volatile("cp.async.wait_group 0;" ::: "memory")

// ---- proj tail, 8 rows: xs[8][Dd] -> g_hv + scores --------------------------
__device__ __forceinline__ void proj_tail8(const float xs[8][Dd],
    const float* __restrict__ W, const float* __restrict__ a_src,
    const float* __restrict__ a_dst, int row0, int tid)
{
    int col = tid & 127, grp = tid >> 7;
    float acc[4];
    #pragma unroll
    for (int r=0;r<4;r++) acc[r]=0.f;
    #pragma unroll 4
    for (int k=0;k<Dd;k++){
        float w = W[k*Dd + col];
        #pragma unroll
        for (int r=0;r<4;r++) acc[r] += xs[grp*4+r][k]*w;
    }
    int head = col >> 5, lane = col & 31;
    float av = a_src[head*DH + lane];
    float bv = a_dst[head*DH + lane];
    #pragma unroll
    for (int r=0;r<4;r++){
        int g = row0 + grp*4 + r;
        int b = g / Nn, n = g % Nn;
        g_hv[((size_t)(b*NP + n))*Dd + col] = acc[r];
        float p = acc[r]*av, q = acc[r]*bv;
        #pragma unroll
        for (int off=16; off; off>>=1){
            p += __shfl_xor_sync(0xffffffffu, p, off);
            q += __shfl_xor_sync(0xffffffffu, q, off);
        }
        if (lane == 0){
            g_ssrc[(b*NHEADS+head)*Nn + n] = p;
            g_sdst[(b*NHEADS+head)*Nn + n] = q;
        }
    }
}

// ---- warp-per-row combine ----------------------------------------------------
__device__ __forceinline__ float4 combine_row(int gr, int lane)
{
    int b = gr / Nn, i = gr % Nn;
    int head = lane >> 3;
    size_t x4 = (size_t)gr*Dd + lane*4;
    float4 a = make_float4(0.f,0.f,0.f,0.f);
    float lv = 0.f;
    #pragma unroll
    for (int s=0;s<SPLITS;s++){
        float4 p = *(const float4*)(g_pacc[s] + x4);
        a.x += p.x; a.y += p.y; a.z += p.z; a.w += p.w;
        lv += g_plv[s][(b*NHEADS+head)*Nn + i];
    }
    float inv = 1.f / lv;
    return make_float4(a.x*inv, a.y*inv, a.z*inv, a.w*inv);
}

// ---------------- fused BN + encoder MLP + GAT1 projection (8 rows) ---------
__global__ __launch_bounds__(256) void enc_proj1(const float* __restrict__ feats,
    const float* __restrict__ gamma, const float* __restrict__ beta,
    const float* __restrict__ mean, const float* __restrict__ var,
    const float* __restrict__ W1, const float* __restrict__ b1,
    const float* __restrict__ W2, const float* __restrict__ b2,
    float* __restrict__ C,
    const float* __restrict__ giW, const float* __restrict__ gias,
    const float* __restrict__ giad)
{
    __shared__ float xn[8][Ff];
    __shared__ float hid[8][Dd];
    __shared__ float xs[8][Dd];
    int tid = threadIdx.x;
    int col = tid & 127, grp = tid >> 7;
    int row0 = blockIdx.x * 8;
    for (int idx = tid; idx < 8*Ff; idx += 256) {
        int r = idx >> 6, f = idx & 63;
        float v = feats[(size_t)(row0+r)*Ff + f];
        xn[r][f] = (v - mean[f]) * rsqrtf(var[f] + 1e-5f) * gamma[f] + beta[f];
    }
    __syncthreads();
    float acc[4];
    float bb = b1[col];
    #pragma unroll
    for (int r=0;r<4;r++) acc[r] = bb;
    #pragma unroll 4
    for (int f=0; f<Ff; f++){
        float w = W1[f*Dd + col];
        #pragma unroll
        for (int r=0;r<4;r++) acc[r] += xn[grp*4+r][f]*w;
    }
    #pragma unroll
    for (int r=0;r<4;r++) hid[grp*4+r][col] = fmaxf(acc[r], 0.f);
    __syncthreads();
    bb = b2[col];
    #pragma unroll
    for (int r=0;r<4;r++) acc[r] = bb;
    #pragma unroll 4
    for (int k=0;k<Dd;k++){
        float w = W2[k*Dd + col];
        #pragma unroll
        for (int r=0;r<4;r++) acc[r] += hid[grp*4+r][k]*w;
    }
    #pragma unroll
    for (int r=0;r<4;r++){
        C[(size_t)(row0+grp*4+r)*Dd + col] = acc[r];
        xs[grp*4+r][col] = acc[r];
    }
    __syncthreads();
    proj_tail8(xs, giW, gias, giad, row0, tid);

    // zero padding rows [Nn,NP) of g_hv
    int tg = blockIdx.x*256 + tid;
    if (tg < Bb*(NP-Nn)*Dd){
        int bb2 = tg / ((NP-Nn)*Dd);
        int rem = tg % ((NP-Nn)*Dd);
        g_hv[((size_t)(bb2*NP + Nn))*Dd + rem] = 0.f;
    }
}

// ---------------- fused combine(GAT1) + GAT2 projection (8 rows) ------------
__global__ __launch_bounds__(256) void comb_proj2(const float* __restrict__ C,
    const float* __restrict__ guW, const float* __restrict__ guas,
    const float* __restrict__ guad,
    float* __restrict__ HI, float* __restrict__ CBI)
{
    __shared__ float xs[8][Dd];
    int tid = threadIdx.x;
    int w = tid >> 5, lane = tid & 31;
    int row0 = blockIdx.x * 8;
    int gr = row0 + w;
    {
        float4 o = combine_row(gr, lane);
        size_t x4 = (size_t)gr*Dd + lane*4;
        float4 ci = *(const float4*)(C + x4);
        float4 cb = make_float4(ci.x-o.x, ci.y-o.y, ci.z-o.z, ci.w-o.w);
        *(float4*)(HI + x4)  = o;
        *(float4*)(CBI + x4) = cb;
        *(float4*)&xs[w][lane*4] = cb;
    }
    __syncthreads();
    proj_tail8(xs, guW, guas, guad, row0, tid);
}

// ---------------- fused combine(GAT2) + factor heads (8 rows) ---------------
__global__ __launch_bounds__(256) void comb2_fact(const float* __restrict__ Cc,
    const float* __restrict__ CBI,
    const float* __restrict__ hW, const float* __restrict__ hb,
    float* __restrict__ HU, float* __restrict__ CBU, float* __restrict__ FOUT)
{
    __shared__ float cbis[8][Dd];
    __shared__ float cbus[8][Dd];
    int tid = threadIdx.x;
    int w = tid >> 5, lane = tid & 31;
    int row0 = blockIdx.x * 8;
    int gr = row0 + w;
    {
        float4 o = combine_row(gr, lane);
        size_t x4 = (size_t)gr*Dd + lane*4;
        float4 ci = *(const float4*)(CBI + x4);
        float4 cb = make_float4(ci.x-o.x, ci.y-o.y, ci.z-o.z, ci.w-o.w);
        *(float4*)(HU + x4)  = o;
        *(float4*)(CBU + x4) = cb;
        *(float4*)&cbis[w][lane*4] = ci;
        *(float4*)&cbus[w][lane*4] = cb;
    }
    __syncthreads();
    float a0=0.f, a1=0.f, a2=0.f;
    #pragma unroll
    for (int it=0; it<12; it++){
        int idx = it*32 + lane;
        float v;
        if (idx < 128)      v = Cc[(size_t)gr*Dd + idx];
        else if (idx < 256) v = cbis[w][idx-128];
        else                v = cbus[w][idx-256];
        a0 += v*hW[0*DEEP+idx];
        a1 += v*hW[1*DEEP+idx];
        a2 += v*hW[2*DEEP+idx];
    }
    #pragma unroll
    for (int off=16; off; off>>=1){
        a0 += __shfl_xor_sync(0xffffffffu, a0, off);
        a1 += __shfl_xor_sync(0xffffffffu, a1, off);
        a2 += __shfl_xor_sync(0xffffffffu, a2, off);
    }
    if (lane==0){
        FOUT[0*Bb*Nn + gr] = lrelu(a0 + hb[0]);
        FOUT[1*Bb*Nn + gr] = lrelu(a1 + hb[1]);
        FOUT[2*Bb*Nn + gr] = lrelu(a2 + hb[2]);
    }
}

// ---------------- per-(b,head) max of s_dst ----------------
__global__ void tmax_kernel()
{
    __shared__ float red[256];
    const float* t = g_sdst + blockIdx.x * Nn;
    float m = NEG_INF;
    for (int n = threadIdx.x; n < Nn; n += 256) m = fmaxf(m, t[n]);
    red[threadIdx.x] = m;
    __syncthreads();
    #pragma unroll
    for (int s=128; s; s>>=1){
        if (threadIdx.x < s) red[threadIdx.x] = fmaxf(red[threadIdx.x], red[threadIdx.x+s]);
        __syncthreads();
    }
    if (threadIdx.x == 0) g_tmax[blockIdx.x] = red[0];
}

// ---------------- GAT attention: tf32 mma.sync, 2-term compensation ----------
#define SM_H   0
#define SM_T   (TJ*PITCH)
#define SM_MB  (TJ*PITCH + NHEADS*TJ)
#define SM_FLOATS (TJ*PITCH + NHEADS*TJ + 64)

__global__ __launch_bounds__(256,4) void gat_attn_tc(const int* __restrict__ mask)
{
    extern __shared__ float sm[];
    float* h_t = sm + SM_H;
    float* t_tile = sm + SM_T;
    unsigned long long* m_bits = (unsigned long long*)(sm + SM_MB);
    uint32_t sbase = smem_u32(sm);
    uint32_t sb_h = sbase + SM_H*4;

    int tid = threadIdx.x;
    int w = tid >> 5, lane = tid & 31;
    int h = w & 3, mh = w >> 2;
    int g = lane >> 2, t = lane & 3;
    int split = blockIdx.x % SPLITS;
    int tmp   = blockIdx.x / SPLITS;
    int b     = tmp / NTILES;
    int i0    = (tmp % NTILES) * 32;
    int il0 = mh*16 + g, il1 = il0 + 8;
    int gi0 = i0 + il0, gi1 = i0 + il1;

    float tmx = g_tmax[b*NHEADS + h];
    float s0 = (gi0 < Nn) ? g_ssrc[(b*NHEADS+h)*Nn + gi0] : 0.f;
    float s1 = (gi1 < Nn) ? g_ssrc[(b*NHEADS+h)*Nn + gi1] : 0.f;
    float m20 = lrelu(s0 + tmx) * LOG2E;
    float m21 = lrelu(s1 + tmx) * LOG2E;
    float lv0 = 0.f, lv1 = 0.f;
    float acc[4][4];
    #pragma unroll
    for (int nt=0;nt<4;nt++){ acc[nt][0]=0.f; acc[nt][1]=0.f; acc[nt][2]=0.f; acc[nt][3]=0.f; }

    const int* mrow = mask + (size_t)b*Nn*Nn + (size_t)i0*Nn;
    int mr = tid >> 3, moct = tid & 7;
    int fjj = tid >> 5, fc4 = tid & 31;

    int c0 = split * CPS;
    for (int c = c0; c < c0 + CPS; c++){
        int j0 = c * TJ;
        __syncthreads();

        const float* srch = g_hv + ((size_t)b*NP + j0)*Dd;
        #pragma unroll
        for (int u=0; u<8; u++){
            int jj = fjj + u*8;
            cp16(sb_h + (uint32_t)(jj*(PITCH*4) + fc4*16), srch + (size_t)jj*Dd + fc4*4);
        }
        CP_COMMIT();

        {
            int hh = tid >> 6, jj = tid & 63;
            t_tile[hh*TJ + jj] = (j0+jj < Nn) ? g_sdst[(b*NHEADS+hh)*Nn + j0+jj] : 0.f;
        }
        {
            unsigned int byte = 0;
            int j = j0 + moct*8;
            if (i0 + mr < Nn){
                const int* p = mrow + (size_t)mr*Nn + j;
                if (j + 7 < Nn){
                    int4 A = *(const int4*)p;
                    int4 Bv = *(const int4*)(p+4);
                    byte = (unsigned)(A.x!=0) | ((unsigned)(A.y!=0)<<1)
                         | ((unsigned)(A.z!=0)<<2) | ((unsigned)(A.w!=0)<<3)
                         | ((unsigned)(Bv.x!=0)<<4) | ((unsigned)(Bv.y!=0)<<5)
                         | ((unsigned)(Bv.z!=0)<<6) | ((unsigned)(Bv.w!=0)<<7);
                } else {
                    #pragma unroll
                    for (int k=0;k<8;k++)
                        if (j+k < Nn && p[k] != 0) byte |= (1u<<k);
                }
            }
            ((unsigned char*)m_bits)[mr*8 + moct] = (unsigned char)byte;
        }
        CP_WAIT0();
        __syncthreads();

        unsigned long long bits0 = m_bits[il0] >> t;
        unsigned long long bits1 = m_bits[il1] >> t;

        #pragma unroll
        for (int s=0; s<8; s++){
            float ta = t_tile[h*TJ + s*8 + t];
            float tb = t_tile[h*TJ + s*8 + t + 4];
            float e00 = lrelu(s0 + ta), e01 = lrelu(s0 + tb);
            float e10 = lrelu(s1 + ta), e11 = lrelu(s1 + tb);
            float w00 = ((bits0 >> (8*s))   & 1ull) ? exp2f(fmaf(e00, LOG2E, -m20)) : 0.f;
            float w01 = ((bits0 >> (8*s+4)) & 1ull) ? exp2f(fmaf(e01, LOG2E, -m20)) : 0.f;
            float w10 = ((bits1 >> (8*s))   & 1ull) ? exp2f(fmaf(e10, LOG2E, -m21)) : 0.f;
            float w11 = ((bits1 >> (8*s+4)) & 1ull) ? exp2f(fmaf(e11, LOG2E, -m21)) : 0.f;
            lv0 += w00 + w01;
            lv1 += w10 + w11;
            uint32_t ah0 = tf32_rna(w00), ah1 = tf32_rna(w10);
            uint32_t ah2 = tf32_rna(w01), ah3 = tf32_rna(w11);
            int r0 = (s*8 + t)*PITCH + h*32 + g;
            int r1 = r0 + 4*PITCH;
            #pragma unroll
            for (int nt=0; nt<4; nt++){
                float f0 = h_t[r0 + nt*8];
                float f1 = h_t[r1 + nt*8];
                uint32_t bh0 = tf32_rna(f0);
                uint32_t bh1 = tf32_rna(f1);
                uint32_t bl0 = __float_as_uint(f0 - __uint_as_float(bh0));
                uint32_t bl1 = __float_as_uint(f1 - __uint_as_float(bh1));
                mma_tf32(acc[nt], ah0, ah1, ah2, ah3, bh0, bh1);
                mma_tf32(acc[nt], ah0, ah1, ah2, ah3, bl0, bl1);
            }
        }
    }

    lv0 += __shfl_xor_sync(0xffffffffu, lv0, 1);
    lv0 += __shfl_xor_sync(0xffffffffu, lv0, 2);
    lv1 += __shfl_xor_sync(0xffffffffu, lv1, 1);
    lv1 += __shfl_xor_sync(0xffffffffu, lv1, 2);
    if (t == 0){
        if (gi0 < Nn) g_plv[split][(b*NHEADS+h)*Nn + gi0] = lv0;
        if (gi1 < Nn) g_plv[split][(b*NHEADS+h)*Nn + gi1] = lv1;
    }

    float* pac = g_pacc[split];
    #pragma unroll
    for (int nt=0; nt<4; nt++){
        int d0 = h*32 + nt*8 + 2*t;
        if (gi0 < Nn){
            size_t x = ((size_t)(b*Nn + gi0))*Dd + d0;
            *(float2*)(pac + x) = make_float2(acc[nt][0], acc[nt][1]);
        }
        if (gi1 < Nn){
            size_t x = ((size_t)(b*Nn + gi1))*Dd + d0;
            *(float2*)(pac + x) = make_float2(acc[nt][2], acc[nt][3]);
        }
    }
}

// ---------------- factor attention: U -> A ----------------
__global__ void fa_kernel(const float* __restrict__ feats,
    const float* __restrict__ projW, float* __restrict__ A)
{
    __shared__ float pw[64][65];
    __shared__ float ft[64][64];
    int tid = threadIdx.x;
    int ntile = blockIdx.x & 31;
    int hb_   = blockIdx.x >> 5;
    int hn = hb_ >> 1, b = hb_ & 1;
    int n0 = ntile*64;
    const float* P = projW + (size_t)hn*64*64;
    for (int idx=tid; idx<4096; idx+=256) pw[idx>>6][idx&63] = P[idx];
    for (int idx=tid; idx<4096; idx+=256){
        int r=idx>>6, m=idx&63; int n=n0+r;
        ft[r][m] = (n<Nn) ? feats[((size_t)(b*Nn+n))*Ff+m] : 0.f;
    }
    __syncthreads();
    int w = tid>>5, lane = tid&31;
    for (int rr=0; rr<8; rr++){
        int r = w*8+rr; int n=n0+r;
        if (n>=Nn) continue;
        float u0=0.f,u1=0.f;
        #pragma unroll
        for (int m=0;m<64;m++){
            float f = ft[r][m];
            u0 += f*pw[lane][m];
            u1 += f*pw[lane+32][m];
        }
        u0 = lrelu(u0); u1 = lrelu(u1);
        float mx = fmaxf(u0,u1);
        #pragma unroll
        for (int off=16; off; off>>=1)
            mx = fmaxf(mx, __shfl_xor_sync(0xffffffffu, mx, off));
        float e0 = __expf(u0-mx), e1 = __expf(u1-mx);
        float ss = e0+e1;
        #pragma unroll
        for (int off=16; off; off>>=1)
            ss += __shfl_xor_sync(0xffffffffu, ss, off);
        float inv = 1.f/ss;
        size_t base = ((size_t)hb_*Nn + n)*64;
        A[base+lane]    = e0*inv;
        A[base+lane+32] = e1*inv;
    }
}

// ---------------- a_bar = A.mean(axis=n) ----------------
__global__ void abar_kernel(const float* __restrict__ A)
{
    __shared__ float red[8][64];
    int tid=threadIdx.x; int k=tid&63, grp=tid>>6;
    const float* base = A + (size_t)blockIdx.x*Nn*64;
    float s=0.f;
    for (int n=grp; n<Nn; n+=8) s += base[(size_t)n*64+k];
    red[grp][k]=s;
    __syncthreads();
    if (grp==0){
        float t=0.f;
        #pragma unroll
        for (int g=0; g<8; g++) t += red[g][k];
        g_abar[blockIdx.x*64+k] = t * (1.f/Nn);
    }
}

// ---------------- recon = feats @ a_bar ----------------
__global__ void recon_kernel(const float* __restrict__ feats, float* __restrict__ out)
{
    int w = threadIdx.x>>5, lane=threadIdx.x&31;
    int ro = blockIdx.x*8 + w;
    if (ro >= HN*Bb*Nn) return;
    int hn = ro / (Bb*Nn);
    int rem = ro % (Bb*Nn);
    int b = rem / Nn, n = rem % Nn;
    const float* f  = feats  + (size_t)(b*Nn+n)*Ff;
    const float* ab = g_abar + (hn*Bb+b)*Ff;
    float p = f[lane]*ab[lane] + f[lane+32]*ab[lane+32];
    #pragma unroll
    for (int off=16; off; off>>=1)
        p += __shfl_xor_sync(0xffffffffu, p, off);
    if (lane==0) out[ro] = p;
}

extern "C" void kernel_launch(void* const* d_in, const int* in_sizes, int n_in,
                              void* d_out, int out_size)
{
    const float* feats = (const float*)d_in[0];
    const int* ind = (const int*)d_in[1];
    const int* uni = (const int*)d_in[2];
    const float* bn_g = (const float*)d_in[3];
    const float* bn_b = (const float*)d_in[4];
    const float* bn_m = (const float*)d_in[5];
    const float* bn_v = (const float*)d_in[6];
    const float* W1   = (const float*)d_in[7];
    const float* b1   = (const float*)d_in[8];
    const float* W2   = (const float*)d_in[9];
    const float* b2   = (const float*)d_in[10];
    const float* giW  = (const float*)d_in[11];
    const float* gias = (const float*)d_in[12];
    const float* giad = (const float*)d_in[13];
    const float* guW  = (const float*)d_in[14];
    const float* guas = (const float*)d_in[15];
    const float* guad = (const float*)d_in[16];
    const float* hW   = (const float*)d_in[17];
    const float* hb   = (const float*)d_in[18];
    const float* pW   = (const float*)d_in[19];

    float* out  = (float*)d_out;
    float* C    = out;
    float* CBI  = out + 512000;
    float* CBU  = out + 1024000;
    float* HI   = out + 1536000;
    float* HU   = out + 2048000;
    float* FOUT = out + 2560000;
    float* ROUT = out + 2572000;
    float* AOUT = out + 2584000;

    static int smem_set = 0;
    const int smem_bytes = SM_FLOATS * 4;
    if (!smem_set){
        cudaFuncSetAttribute(gat_attn_tc,
            cudaFuncAttributeMaxDynamicSharedMemorySize, smem_bytes);
        smem_set = 1;
    }

    enc_proj1<<<500,256>>>(feats, bn_g, bn_b, bn_m, bn_v, W1, b1, W2, b2, C,
                           giW, gias, giad);
    tmax_kernel<<<8,256>>>();
    gat_attn_tc<<<Bb*NTILES*SPLITS,256,smem_bytes>>>(ind);

    comb_proj2<<<500,256>>>(C, guW, guas, guad, HI, CBI);
    tmax_kernel<<<8,256>>>();
    gat_attn_tc<<<Bb*NTILES*SPLITS,256,smem_bytes>>>(uni);

    comb2_fact<<<500,256>>>(C, CBI, hW, hb, HU, CBU, FOUT);

    fa_kernel<<<192,256>>>(feats, pW, AOUT);
    abar_kernel<<<6,512>>>(AOUT);
    recon_kernel<<<1500,256>>>(feats, ROUT);
}

// round 16
// speedup vs baseline: 2.1435x; 1.0265x over previous
#include <cuda_runtime.h>
#include <cstdint>

#define Bb 2
#define Nn 2000
#define NP 2048
#define Ff 64
#define Dd 128
#define NHEADS 4
#define DH 32
#define HN 3
#define DEEP 384
#define SLOPE 0.1f
#define NEG_INF -1e30f
#define TJ 64
#define NTILES 63
#define NCHUNK 32
#define SPLITS 8
#define CPS (NCHUNK/SPLITS)
#define LOG2E 1.44269504f
#define PITCH 136

__device__ float g_hv[Bb*NP*Dd];
__device__ float g_ssrc[Bb*NHEADS*Nn];
__device__ float g_sdst[Bb*NHEADS*Nn];
__device__ float g_tmax[Bb*NHEADS];
__device__ float g_abar[HN*Bb*Ff];
__device__ float g_pacc[SPLITS][Bb*Nn*Dd];
__device__ float g_plv[SPLITS][Bb*NHEADS*Nn];

__device__ __forceinline__ float lrelu(float x){ return fmaxf(x, SLOPE*x); }

__device__ __forceinline__ uint32_t tf32_rna(float x){
    uint32_t r;
    asm("cvt.rna.tf32.f32 %0, %1;" : "=r"(r) : "f"(x));
    return r;
}
__device__ __forceinline__ void mma_tf32(float* c,
    uint32_t a0, uint32_t a1, uint32_t a2, uint32_t a3,
    uint32_t b0, uint32_t b1)
{
    asm volatile(
        "mma.sync.aligned.m16n8k8.row.col.f32.tf32.tf32.f32 "
        "{%0,%1,%2,%3}, {%4,%5,%6,%7}, {%8,%9}, {%0,%1,%2,%3};"
        : "+f"(c[0]), "+f"(c[1]), "+f"(c[2]), "+f"(c[3])
        : "r"(a0), "r"(a1), "r"(a2), "r"(a3), "r"(b0), "r"(b1));
}
__device__ __forceinline__ uint32_t smem_u32(const void* p){
    uint32_t a;
    asm("{ .reg .u64 t; cvta.to.shared.u64 t, %1; cvt.u32.u64 %0, t; }" : "=r"(a) : "l"(p));
    return a;
}
__device__ __forceinline__ void cp16(uint32_t dst, const void* src){
    asm volatile("cp.async.cg.shared.global [%0], [%1], 16;" :: "r"(dst), "l"(src));
}
#define CP_COMMIT() asm volatile("cp.async.commit_group;" ::: "memory")
#define CP_WAIT0()  asm volatile("cp.async.wait_group 0;" ::: "memory")

// ---- proj tail, 4 rows: xs[4][Dd] -> g_hv + scores --------------------------
__device__ __forceinline__ void proj_tail4(const float xs[4][Dd],
    const float* __restrict__ W, const float* __restrict__ a_src,
    const float* __restrict__ a_dst, int row0, int tid)
{
    int col = tid & 127, grp = tid >> 7;
    float acc[2];
    acc[0]=0.f; acc[1]=0.f;
    #pragma unroll 4
    for (int k=0;k<Dd;k++){
        float w = W[k*Dd + col];
        acc[0] += xs[grp*2  ][k]*w;
        acc[1] += xs[grp*2+1][k]*w;
    }
    int head = col >> 5, lane = col & 31;
    float av = a_src[head*DH + lane];
    float bv = a_dst[head*DH + lane];
    #pragma unroll
    for (int r=0;r<2;r++){
        int g = row0 + grp*2 + r;
        int b = g / Nn, n = g % Nn;
        g_hv[((size_t)(b*NP + n))*Dd + col] = acc[r];
        float p = acc[r]*av, q = acc[r]*bv;
        #pragma unroll
        for (int off=16; off; off>>=1){
            p += __shfl_xor_sync(0xffffffffu, p, off);
            q += __shfl_xor_sync(0xffffffffu, q, off);
        }
        if (lane == 0){
            g_ssrc[(b*NHEADS+head)*Nn + n] = p;
            g_sdst[(b*NHEADS+head)*Nn + n] = q;
        }
    }
}

// ---- half-row combine: 64 cols of row gr via float2 per lane ---------------
// col = half*64 + lane*2  (32 lanes x 2 floats = exactly 64 columns)
__device__ __forceinline__ float2 combine_row64(int gr, int half, int lane)
{
    int b = gr / Nn, i = gr % Nn;
    int col = half*64 + lane*2;
    int head = col >> 5;
    size_t x2 = (size_t)gr*Dd + col;
    float2 a = make_float2(0.f,0.f);
    float lv = 0.f;
    #pragma unroll
    for (int s=0;s<SPLITS;s++){
        float2 p = *(const float2*)(g_pacc[s] + x2);
        a.x += p.x; a.y += p.y;
        lv += g_plv[s][(b*NHEADS+head)*Nn + i];
    }
    float inv = 1.f / lv;
    return make_float2(a.x*inv, a.y*inv);
}

// ---------------- fused BN + encoder MLP + GAT1 projection (4 rows) ---------
__global__ __launch_bounds__(256) void enc_proj1(const float* __restrict__ feats,
    const float* __restrict__ gamma, const float* __restrict__ beta,
    const float* __restrict__ mean, const float* __restrict__ var,
    const float* __restrict__ W1, const float* __restrict__ b1,
    const float* __restrict__ W2, const float* __restrict__ b2,
    float* __restrict__ C,
    const float* __restrict__ giW, const float* __restrict__ gias,
    const float* __restrict__ giad)
{
    __shared__ float xn[4][Ff];
    __shared__ float hid[4][Dd];
    __shared__ float xs[4][Dd];
    int tid = threadIdx.x;
    int col = tid & 127, grp = tid >> 7;
    int row0 = blockIdx.x * 4;
    {
        int r = tid >> 6, f = tid & 63;
        float v = feats[(size_t)(row0+r)*Ff + f];
        xn[r][f] = (v - mean[f]) * rsqrtf(var[f] + 1e-5f) * gamma[f] + beta[f];
    }
    __syncthreads();
    float acc[2];
    float bb = b1[col];
    acc[0] = bb; acc[1] = bb;
    #pragma unroll 4
    for (int f=0; f<Ff; f++){
        float w = W1[f*Dd + col];
        acc[0] += xn[grp*2  ][f]*w;
        acc[1] += xn[grp*2+1][f]*w;
    }
    hid[grp*2  ][col] = fmaxf(acc[0], 0.f);
    hid[grp*2+1][col] = fmaxf(acc[1], 0.f);
    __syncthreads();
    bb = b2[col];
    acc[0] = bb; acc[1] = bb;
    #pragma unroll 4
    for (int k=0;k<Dd;k++){
        float w = W2[k*Dd + col];
        acc[0] += hid[grp*2  ][k]*w;
        acc[1] += hid[grp*2+1][k]*w;
    }
    #pragma unroll
    for (int r=0;r<2;r++){
        C[(size_t)(row0+grp*2+r)*Dd + col] = acc[r];
        xs[grp*2+r][col] = acc[r];
    }
    __syncthreads();
    proj_tail4(xs, giW, gias, giad, row0, tid);

    // zero padding rows [Nn,NP) of g_hv
    int tg = blockIdx.x*256 + tid;
    if (tg < Bb*(NP-Nn)*Dd){
        int bb2 = tg / ((NP-Nn)*Dd);
        int rem = tg % ((NP-Nn)*Dd);
        g_hv[((size_t)(bb2*NP + Nn))*Dd + rem] = 0.f;
    }
}

// ---------------- fused combine(GAT1) + GAT2 projection (4 rows) ------------
__global__ __launch_bounds__(256) void comb_proj2(const float* __restrict__ C,
    const float* __restrict__ guW, const float* __restrict__ guas,
    const float* __restrict__ guad,
    float* __restrict__ HI, float* __restrict__ CBI)
{
    __shared__ float xs[4][Dd];
    int tid = threadIdx.x;
    int w = tid >> 5, lane = tid & 31;
    int row0 = blockIdx.x * 4;
    int rl = w >> 1, half = w & 1;
    int gr = row0 + rl;
    {
        float2 o = combine_row64(gr, half, lane);
        size_t x2 = (size_t)gr*Dd + half*64 + lane*2;
        float2 ci = *(const float2*)(C + x2);
        float2 cb = make_float2(ci.x-o.x, ci.y-o.y);
        *(float2*)(HI + x2)  = o;
        *(float2*)(CBI + x2) = cb;
        *(float2*)&xs[rl][half*64 + lane*2] = cb;
    }
    __syncthreads();
    proj_tail4(xs, guW, guas, guad, row0, tid);
}

// ---------------- fused combine(GAT2) + factor heads (4 rows) ---------------
__global__ __launch_bounds__(256) void comb2_fact(const float* __restrict__ Cc,
    const float* __restrict__ CBI,
    const float* __restrict__ hW, const float* __restrict__ hb,
    float* __restrict__ HU, float* __restrict__ CBU, float* __restrict__ FOUT)
{
    __shared__ float cbis[4][Dd];
    __shared__ float cbus[4][Dd];
    __shared__ float spart[2][4][3];
    int tid = threadIdx.x;
    int w = tid >> 5, lane = tid & 31;
    int row0 = blockIdx.x * 4;
    {
        int rl = w >> 1, half = w & 1;
        int gr = row0 + rl;
        float2 o = combine_row64(gr, half, lane);
        size_t x2 = (size_t)gr*Dd + half*64 + lane*2;
        float2 ci = *(const float2*)(CBI + x2);
        float2 cb = make_float2(ci.x-o.x, ci.y-o.y);
        *(float2*)(HU + x2)  = o;
        *(float2*)(CBU + x2) = cb;
        *(float2*)&cbis[rl][half*64 + lane*2] = ci;
        *(float2*)&cbus[rl][half*64 + lane*2] = cb;
    }
    __syncthreads();
    {
        int rl = w & 3, half = w >> 2;
        int gr = row0 + rl;
        float a0=0.f, a1=0.f, a2=0.f;
        #pragma unroll
        for (int it=0; it<6; it++){
            int idx = half*192 + it*32 + lane;
            float v;
            if (idx < 128)      v = Cc[(size_t)gr*Dd + idx];
            else if (idx < 256) v = cbis[rl][idx-128];
            else                v = cbus[rl][idx-256];
            a0 += v*hW[0*DEEP+idx];
            a1 += v*hW[1*DEEP+idx];
            a2 += v*hW[2*DEEP+idx];
        }
        #pragma unroll
        for (int off=16; off; off>>=1){
            a0 += __shfl_xor_sync(0xffffffffu, a0, off);
            a1 += __shfl_xor_sync(0xffffffffu, a1, off);
            a2 += __shfl_xor_sync(0xffffffffu, a2, off);
        }
        if (lane == 0){
            spart[half][rl][0] = a0;
            spart[half][rl][1] = a1;
            spart[half][rl][2] = a2;
        }
    }
    __syncthreads();
    if (tid < 12){
        int r = tid / 3, c = tid % 3;
        float v = spart[0][r][c] + spart[1][r][c] + hb[c];
        FOUT[c*Bb*Nn + row0 + r] = lrelu(v);
    }
}

// ---------------- per-(b,head) max of s_dst ----------------
__global__ void tmax_kernel()
{
    __shared__ float red[256];
    const float* t = g_sdst + blockIdx.x * Nn;
    float m = NEG_INF;
    for (int n = threadIdx.x; n < Nn; n += 256) m = fmaxf(m, t[n]);
    red[threadIdx.x] = m;
    __syncthreads();
    #pragma unroll
    for (int s=128; s; s>>=1){
        if (threadIdx.x < s) red[threadIdx.x] = fmaxf(red[threadIdx.x], red[threadIdx.x+s]);
        __syncthreads();
    }
    if (threadIdx.x == 0) g_tmax[blockIdx.x] = red[0];
}

// ---------------- GAT attention: tf32 mma.sync, 2-term compensation ----------
#define SM_H   0
#define SM_T   (TJ*PITCH)
#define SM_MB  (TJ*PITCH + NHEADS*TJ)
#define SM_FLOATS (TJ*PITCH + NHEADS*TJ + 64)

__global__ __launch_bounds__(256,4) void gat_attn_tc(const int* __restrict__ mask)
{
    extern __shared__ float sm[];
    float* h_t = sm + SM_H;
    float* t_tile = sm + SM_T;
    unsigned long long* m_bits = (unsigned long long*)(sm + SM_MB);
    uint32_t sbase = smem_u32(sm);
    uint32_t sb_h = sbase + SM_H*4;

    int tid = threadIdx.x;
    int w = tid >> 5, lane = tid & 31;
    int h = w & 3, mh = w >> 2;
    int g = lane >> 2, t = lane & 3;
    int split = blockIdx.x % SPLITS;
    int tmp   = blockIdx.x / SPLITS;
    int b     = tmp / NTILES;
    int i0    = (tmp % NTILES) * 32;
    int il0 = mh*16 + g, il1 = il0 + 8;
    int gi0 = i0 + il0, gi1 = i0 + il1;

    float tmx = g_tmax[b*NHEADS + h];
    float s0 = (gi0 < Nn) ? g_ssrc[(b*NHEADS+h)*Nn + gi0] : 0.f;
    float s1 = (gi1 < Nn) ? g_ssrc[(b*NHEADS+h)*Nn + gi1] : 0.f;
    float m20 = lrelu(s0 + tmx) * LOG2E;
    float m21 = lrelu(s1 + tmx) * LOG2E;
    float lv0 = 0.f, lv1 = 0.f;
    float acc[4][4];
    #pragma unroll
    for (int nt=0;nt<4;nt++){ acc[nt][0]=0.f; acc[nt][1]=0.f; acc[nt][2]=0.f; acc[nt][3]=0.f; }

    const int* mrow = mask + (size_t)b*Nn*Nn + (size_t)i0*Nn;
    int mr = tid >> 3, moct = tid & 7;
    int fjj = tid >> 5, fc4 = tid & 31;

    int c0 = split * CPS;
    for (int c = c0; c < c0 + CPS; c++){
        int j0 = c * TJ;
        __syncthreads();

        const float* srch = g_hv + ((size_t)b*NP + j0)*Dd;
        #pragma unroll
        for (int u=0; u<8; u++){
            int jj = fjj + u*8;
            cp16(sb_h + (uint32_t)(jj*(PITCH*4) + fc4*16), srch + (size_t)jj*Dd + fc4*4);
        }
        CP_COMMIT();

        {
            int hh = tid >> 6, jj = tid & 63;
            t_tile[hh*TJ + jj] = (j0+jj < Nn) ? g_sdst[(b*NHEADS+hh)*Nn + j0+jj] : 0.f;
        }
        {
            unsigned int byte = 0;
            int j = j0 + moct*8;
            if (i0 + mr < Nn){
                const int* p = mrow + (size_t)mr*Nn + j;
                if (j + 7 < Nn){
                    int4 A = *(const int4*)p;
                    int4 Bv = *(const int4*)(p+4);
                    byte = (unsigned)(A.x!=0) | ((unsigned)(A.y!=0)<<1)
                         | ((unsigned)(A.z!=0)<<2) | ((unsigned)(A.w!=0)<<3)
                         | ((unsigned)(Bv.x!=0)<<4) | ((unsigned)(Bv.y!=0)<<5)
                         | ((unsigned)(Bv.z!=0)<<6) | ((unsigned)(Bv.w!=0)<<7);
                } else {
                    #pragma unroll
                    for (int k=0;k<8;k++)
                        if (j+k < Nn && p[k] != 0) byte |= (1u<<k);
                }
            }
            ((unsigned char*)m_bits)[mr*8 + moct] = (unsigned char)byte;
        }
        CP_WAIT0();
        __syncthreads();

        unsigned long long bits0 = m_bits[il0] >> t;
        unsigned long long bits1 = m_bits[il1] >> t;

        #pragma unroll
        for (int s=0; s<8; s++){
            float ta = t_tile[h*TJ + s*8 + t];
            float tb = t_tile[h*TJ + s*8 + t + 4];
            float e00 = lrelu(s0 + ta), e01 = lrelu(s0 + tb);
            float e10 = lrelu(s1 + ta), e11 = lrelu(s1 + tb);
            float w00 = ((bits0 >> (8*s))   & 1ull) ? exp2f(fmaf(e00, LOG2E, -m20)) : 0.f;
            float w01 = ((bits0 >> (8*s+4)) & 1ull) ? exp2f(fmaf(e01, LOG2E, -m20)) : 0.f;
            float w10 = ((bits1 >> (8*s))   & 1ull) ? exp2f(fmaf(e10, LOG2E, -m21)) : 0.f;
            float w11 = ((bits1 >> (8*s+4)) & 1ull) ? exp2f(fmaf(e11, LOG2E, -m21)) : 0.f;
            lv0 += w00 + w01;
            lv1 += w10 + w11;
            uint32_t ah0 = tf32_rna(w00), ah1 = tf32_rna(w10);
            uint32_t ah2 = tf32_rna(w01), ah3 = tf32_rna(w11);
            int r0 = (s*8 + t)*PITCH + h*32 + g;
            int r1 = r0 + 4*PITCH;
            #pragma unroll
            for (int nt=0; nt<4; nt++){
                float f0 = h_t[r0 + nt*8];
                float f1 = h_t[r1 + nt*8];
                uint32_t bh0 = tf32_rna(f0);
                uint32_t bh1 = tf32_rna(f1);
                uint32_t bl0 = __float_as_uint(f0 - __uint_as_float(bh0));
                uint32_t bl1 = __float_as_uint(f1 - __uint_as_float(bh1));
                mma_tf32(acc[nt], ah0, ah1, ah2, ah3, bh0, bh1);
                mma_tf32(acc[nt], ah0, ah1, ah2, ah3, bl0, bl1);
            }
        }
    }

    lv0 += __shfl_xor_sync(0xffffffffu, lv0, 1);
    lv0 += __shfl_xor_sync(0xffffffffu, lv0, 2);
    lv1 += __shfl_xor_sync(0xffffffffu, lv1, 1);
    lv1 += __shfl_xor_sync(0xffffffffu, lv1, 2);
    if (t == 0){
        if (gi0 < Nn) g_plv[split][(b*NHEADS+h)*Nn + gi0] = lv0;
        if (gi1 < Nn) g_plv[split][(b*NHEADS+h)*Nn + gi1] = lv1;
    }

    float* pac = g_pacc[split];
    #pragma unroll
    for (int nt=0; nt<4; nt++){
        int d0 = h*32 + nt*8 + 2*t;
        if (gi0 < Nn){
            size_t x = ((size_t)(b*Nn + gi0))*Dd + d0;
            *(float2*)(pac + x) = make_float2(acc[nt][0], acc[nt][1]);
        }
        if (gi1 < Nn){
            size_t x = ((size_t)(b*Nn + gi1))*Dd + d0;
            *(float2*)(pac + x) = make_float2(acc[nt][2], acc[nt][3]);
        }
    }
}

// ---------------- factor attention: U -> A ----------------
__global__ void fa_kernel(const float* __restrict__ feats,
    const float* __restrict__ projW, float* __restrict__ A)
{
    __shared__ float pw[64][65];
    __shared__ float ft[64][64];
    int tid = threadIdx.x;
    int ntile = blockIdx.x & 31;
    int hb_   = blockIdx.x >> 5;
    int hn = hb_ >> 1, b = hb_ & 1;
    int n0 = ntile*64;
    const float* P = projW + (size_t)hn*64*64;
    for (int idx=tid; idx<4096; idx+=256) pw[idx>>6][idx&63] = P[idx];
    for (int idx=tid; idx<4096; idx+=256){
        int r=idx>>6, m=idx&63; int n=n0+r;
        ft[r][m] = (n<Nn) ? feats[((size_t)(b*Nn+n))*Ff+m] : 0.f;
    }
    __syncthreads();
    int w = tid>>5, lane = tid&31;
    for (int rr=0; rr<8; rr++){
        int r = w*8+rr; int n=n0+r;
        if (n>=Nn) continue;
        float u0=0.f,u1=0.f;
        #pragma unroll
        for (int m=0;m<64;m++){
            float f = ft[r][m];
            u0 += f*pw[lane][m];
            u1 += f*pw[lane+32][m];
        }
        u0 = lrelu(u0); u1 = lrelu(u1);
        float mx = fmaxf(u0,u1);
        #pragma unroll
        for (int off=16; off; off>>=1)
            mx = fmaxf(mx, __shfl_xor_sync(0xffffffffu, mx, off));
        float e0 = __expf(u0-mx), e1 = __expf(u1-mx);
        float ss = e0+e1;
        #pragma unroll
        for (int off=16; off; off>>=1)
            ss += __shfl_xor_sync(0xffffffffu, ss, off);
        float inv = 1.f/ss;
        size_t base = ((size_t)hb_*Nn + n)*64;
        A[base+lane]    = e0*inv;
        A[base+lane+32] = e1*inv;
    }
}

// ---------------- a_bar = A.mean(axis=n) ----------------
__global__ void abar_kernel(const float* __restrict__ A)
{
    __shared__ float red[8][64];
    int tid=threadIdx.x; int k=tid&63, grp=tid>>6;
    const float* base = A + (size_t)blockIdx.x*Nn*64;
    float s=0.f;
    for (int n=grp; n<Nn; n+=8) s += base[(size_t)n*64+k];
    red[grp][k]=s;
    __syncthreads();
    if (grp==0){
        float t=0.f;
        #pragma unroll
        for (int g=0; g<8; g++) t += red[g][k];
        g_abar[blockIdx.x*64+k] = t * (1.f/Nn);
    }
}

// ---------------- recon = feats @ a_bar ----------------
__global__ void recon_kernel(const float* __restrict__ feats, float* __restrict__ out)
{
    int w = threadIdx.x>>5, lane=threadIdx.x&31;
    int ro = blockIdx.x*8 + w;
    if (ro >= HN*Bb*Nn) return;
    int hn = ro / (Bb*Nn);
    int rem = ro % (Bb*Nn);
    int b = rem / Nn, n = rem % Nn;
    const float* f  = feats  + (size_t)(b*Nn+n)*Ff;
    const float* ab = g_abar + (hn*Bb+b)*Ff;
    float p = f[lane]*ab[lane] + f[lane+32]*ab[lane+32];
    #pragma unroll
    for (int off=16; off; off>>=1)
        p += __shfl_xor_sync(0xffffffffu, p, off);
    if (lane==0) out[ro] = p;
}

extern "C" void kernel_launch(void* const* d_in, const int* in_sizes, int n_in,
                              void* d_out, int out_size)
{
    const float* feats = (const float*)d_in[0];
    const int* ind = (const int*)d_in[1];
    const int* uni = (const int*)d_in[2];
    const float* bn_g = (const float*)d_in[3];
    const float* bn_b = (const float*)d_in[4];
    const float* bn_m = (const float*)d_in[5];
    const float* bn_v = (const float*)d_in[6];
    const float* W1   = (const float*)d_in[7];
    const float* b1   = (const float*)d_in[8];
    const float* W2   = (const float*)d_in[9];
    const float* b2   = (const float*)d_in[10];
    const float* giW  = (const float*)d_in[11];
    const float* gias = (const float*)d_in[12];
    const float* giad = (const float*)d_in[13];
    const float* guW  = (const float*)d_in[14];
    const float* guas = (const float*)d_in[15];
    const float* guad = (const float*)d_in[16];
    const float* hW   = (const float*)d_in[17];
    const float* hb   = (const float*)d_in[18];
    const float* pW   = (const float*)d_in[19];

    float* out  = (float*)d_out;
    float* C    = out;
    float* CBI  = out + 512000;
    float* CBU  = out + 1024000;
    float* HI   = out + 1536000;
    float* HU   = out + 2048000;
    float* FOUT = out + 2560000;
    float* ROUT = out + 2572000;
    float* AOUT = out + 2584000;

    static int smem_set = 0;
    const int smem_bytes = SM_FLOATS * 4;
    if (!smem_set){
        cudaFuncSetAttribute(gat_attn_tc,
            cudaFuncAttributeMaxDynamicSharedMemorySize, smem_bytes);
        smem_set = 1;
    }

    enc_proj1<<<1000,256>>>(feats, bn_g, bn_b, bn_m, bn_v, W1, b1, W2, b2, C,
                            giW, gias, giad);
    tmax_kernel<<<8,256>>>();
    gat_attn_tc<<<Bb*NTILES*SPLITS,256,smem_bytes>>>(ind);

    comb_proj2<<<1000,256>>>(C, guW, guas, guad, HI, CBI);
    tmax_kernel<<<8,256>>>();
    gat_attn_tc<<<Bb*NTILES*SPLITS,256,smem_bytes>>>(uni);

    comb2_fact<<<1000,256>>>(C, CBI, hW, hb, HU, CBU, FOUT);

    fa_kernel<<<192,256>>>(feats, pW, AOUT);
    abar_kernel<<<6,512>>>(AOUT);
    recon_kernel<<<1500,256>>>(feats, ROUT);
}

// round 17
// speedup vs baseline: 2.3056x; 1.0756x over previous
#include <cuda_runtime.h>
#include <cstdint>

#define Bb 2
#define Nn 2000
#define NP 2048
#define Ff 64
#define Dd 128
#define NHEADS 4
#define DH 32
#define HN 3
#define DEEP 384
#define SLOPE 0.1f
#define NEG_INF -1e30f
#define TJ 64
#define NTILES 63
#define NCHUNK 32
#define SPLITS 8
#define CPS (NCHUNK/SPLITS)
#define LOG2E 1.44269504f
#define PITCH 136

__device__ float g_hv[Bb*NP*Dd];
__device__ float g_ssrc[Bb*NHEADS*Nn];
__device__ float g_sdst[Bb*NHEADS*Nn];
__device__ float g_tmax[Bb*NHEADS];
__device__ float g_abar[HN*Bb*Ff];
__device__ float g_pacc[SPLITS][Bb*Nn*Dd];
__device__ float g_plv[SPLITS][Bb*NHEADS*Nn];

__device__ __forceinline__ float lrelu(float x){ return fmaxf(x, SLOPE*x); }

__device__ __forceinline__ uint32_t tf32_rna(float x){
    uint32_t r;
    asm("cvt.rna.tf32.f32 %0, %1;" : "=r"(r) : "f"(x));
    return r;
}
__device__ __forceinline__ void mma_tf32(float* c,
    uint32_t a0, uint32_t a1, uint32_t a2, uint32_t a3,
    uint32_t b0, uint32_t b1)
{
    asm volatile(
        "mma.sync.aligned.m16n8k8.row.col.f32.tf32.tf32.f32 "
        "{%0,%1,%2,%3}, {%4,%5,%6,%7}, {%8,%9}, {%0,%1,%2,%3};"
        : "+f"(c[0]), "+f"(c[1]), "+f"(c[2]), "+f"(c[3])
        : "r"(a0), "r"(a1), "r"(a2), "r"(a3), "r"(b0), "r"(b1));
}
__device__ __forceinline__ uint32_t smem_u32(const void* p){
    uint32_t a;
    asm("{ .reg .u64 t; cvta.to.shared.u64 t, %1; cvt.u32.u64 %0, t; }" : "=r"(a) : "l"(p));
    return a;
}
__device__ __forceinline__ void cp16(uint32_t dst, const void* src){
    asm volatile("cp.async.cg.shared.global [%0], [%1], 16;" :: "r"(dst), "l"(src));
}
#define CP_COMMIT() asm volatile("cp.async.commit_group;" ::: "memory")
#define CP_WAIT0()  asm volatile("cp.async.wait_group 0;" ::: "memory")

// ---- proj tail, 4 rows: xs[4][Dd] -> g_hv + scores --------------------------
__device__ __forceinline__ void proj_tail4(const float xs[4][Dd],
    const float* __restrict__ W, const float* __restrict__ a_src,
    const float* __restrict__ a_dst, int row0, int tid)
{
    int col = tid & 127, grp = tid >> 7;
    float acc[2];
    acc[0]=0.f; acc[1]=0.f;
    #pragma unroll 4
    for (int k=0;k<Dd;k++){
        float w = W[k*Dd + col];
        acc[0] += xs[grp*2  ][k]*w;
        acc[1] += xs[grp*2+1][k]*w;
    }
    int head = col >> 5, lane = col & 31;
    float av = a_src[head*DH + lane];
    float bv = a_dst[head*DH + lane];
    #pragma unroll
    for (int r=0;r<2;r++){
        int g = row0 + grp*2 + r;
        int b = g / Nn, n = g % Nn;
        g_hv[((size_t)(b*NP + n))*Dd + col] = acc[r];
        float p = acc[r]*av, q = acc[r]*bv;
        #pragma unroll
        for (int off=16; off; off>>=1){
            p += __shfl_xor_sync(0xffffffffu, p, off);
            q += __shfl_xor_sync(0xffffffffu, q, off);
        }
        if (lane == 0){
            g_ssrc[(b*NHEADS+head)*Nn + n] = p;
            g_sdst[(b*NHEADS+head)*Nn + n] = q;
        }
    }
}

// ---- half-row combine: 64 cols of row gr via float2 per lane ---------------
__device__ __forceinline__ float2 combine_row64(int gr, int half, int lane)
{
    int b = gr / Nn, i = gr % Nn;
    int col = half*64 + lane*2;
    int head = col >> 5;
    size_t x2 = (size_t)gr*Dd + col;
    float2 a = make_float2(0.f,0.f);
    float lv = 0.f;
    #pragma unroll
    for (int s=0;s<SPLITS;s++){
        float2 p = *(const float2*)(g_pacc[s] + x2);
        a.x += p.x; a.y += p.y;
        lv += g_plv[s][(b*NHEADS+head)*Nn + i];
    }
    float inv = 1.f / lv;
    return make_float2(a.x*inv, a.y*inv);
}

// ---------------- fused BN + encoder MLP + GAT1 projection (4 rows) ---------
__global__ __launch_bounds__(256) void enc_proj1(const float* __restrict__ feats,
    const float* __restrict__ gamma, const float* __restrict__ beta,
    const float* __restrict__ mean, const float* __restrict__ var,
    const float* __restrict__ W1, const float* __restrict__ b1,
    const float* __restrict__ W2, const float* __restrict__ b2,
    float* __restrict__ C,
    const float* __restrict__ giW, const float* __restrict__ gias,
    const float* __restrict__ giad)
{
    __shared__ float xn[4][Ff];
    __shared__ float hid[4][Dd];
    __shared__ float xs[4][Dd];
    int tid = threadIdx.x;
    int col = tid & 127, grp = tid >> 7;
    int row0 = blockIdx.x * 4;
    {
        int r = tid >> 6, f = tid & 63;
        float v = feats[(size_t)(row0+r)*Ff + f];
        xn[r][f] = (v - mean[f]) * rsqrtf(var[f] + 1e-5f) * gamma[f] + beta[f];
    }
    __syncthreads();
    float acc[2];
    float bb = b1[col];
    acc[0] = bb; acc[1] = bb;
    #pragma unroll 4
    for (int f=0; f<Ff; f++){
        float w = W1[f*Dd + col];
        acc[0] += xn[grp*2  ][f]*w;
        acc[1] += xn[grp*2+1][f]*w;
    }
    hid[grp*2  ][col] = fmaxf(acc[0], 0.f);
    hid[grp*2+1][col] = fmaxf(acc[1], 0.f);
    __syncthreads();
    bb = b2[col];
    acc[0] = bb; acc[1] = bb;
    #pragma unroll 4
    for (int k=0;k<Dd;k++){
        float w = W2[k*Dd + col];
        acc[0] += hid[grp*2  ][k]*w;
        acc[1] += hid[grp*2+1][k]*w;
    }
    #pragma unroll
    for (int r=0;r<2;r++){
        C[(size_t)(row0+grp*2+r)*Dd + col] = acc[r];
        xs[grp*2+r][col] = acc[r];
    }
    __syncthreads();
    proj_tail4(xs, giW, gias, giad, row0, tid);

    // zero padding rows [Nn,NP) of g_hv
    int tg = blockIdx.x*256 + tid;
    if (tg < Bb*(NP-Nn)*Dd){
        int bb2 = tg / ((NP-Nn)*Dd);
        int rem = tg % ((NP-Nn)*Dd);
        g_hv[((size_t)(bb2*NP + Nn))*Dd + rem] = 0.f;
    }
}

// ---------------- fused combine(GAT1) + GAT2 projection (4 rows) ------------
__global__ __launch_bounds__(256) void comb_proj2(const float* __restrict__ C,
    const float* __restrict__ guW, const float* __restrict__ guas,
    const float* __restrict__ guad,
    float* __restrict__ HI, float* __restrict__ CBI)
{
    __shared__ float xs[4][Dd];
    int tid = threadIdx.x;
    int w = tid >> 5, lane = tid & 31;
    int row0 = blockIdx.x * 4;
    int rl = w >> 1, half = w & 1;
    int gr = row0 + rl;
    {
        float2 o = combine_row64(gr, half, lane);
        size_t x2 = (size_t)gr*Dd + half*64 + lane*2;
        float2 ci = *(const float2*)(C + x2);
        float2 cb = make_float2(ci.x-o.x, ci.y-o.y);
        *(float2*)(HI + x2)  = o;
        *(float2*)(CBI + x2) = cb;
        *(float2*)&xs[rl][half*64 + lane*2] = cb;
    }
    __syncthreads();
    proj_tail4(xs, guW, guas, guad, row0, tid);
}

// ---------------- fused combine(GAT2) + factor heads (4 rows) ---------------
__global__ __launch_bounds__(256) void comb2_fact(const float* __restrict__ Cc,
    const float* __restrict__ CBI,
    const float* __restrict__ hW, const float* __restrict__ hb,
    float* __restrict__ HU, float* __restrict__ CBU, float* __restrict__ FOUT)
{
    __shared__ float cbis[4][Dd];
    __shared__ float cbus[4][Dd];
    __shared__ float spart[2][4][3];
    int tid = threadIdx.x;
    int w = tid >> 5, lane = tid & 31;
    int row0 = blockIdx.x * 4;
    {
        int rl = w >> 1, half = w & 1;
        int gr = row0 + rl;
        float2 o = combine_row64(gr, half, lane);
        size_t x2 = (size_t)gr*Dd + half*64 + lane*2;
        float2 ci = *(const float2*)(CBI + x2);
        float2 cb = make_float2(ci.x-o.x, ci.y-o.y);
        *(float2*)(HU + x2)  = o;
        *(float2*)(CBU + x2) = cb;
        *(float2*)&cbis[rl][half*64 + lane*2] = ci;
        *(float2*)&cbus[rl][half*64 + lane*2] = cb;
    }
    __syncthreads();
    {
        int rl = w & 3, half = w >> 2;
        int gr = row0 + rl;
        float a0=0.f, a1=0.f, a2=0.f;
        #pragma unroll
        for (int it=0; it<6; it++){
            int idx = half*192 + it*32 + lane;
            float v;
            if (idx < 128)      v = Cc[(size_t)gr*Dd + idx];
            else if (idx < 256) v = cbis[rl][idx-128];
            else                v = cbus[rl][idx-256];
            a0 += v*hW[0*DEEP+idx];
            a1 += v*hW[1*DEEP+idx];
            a2 += v*hW[2*DEEP+idx];
        }
        #pragma unroll
        for (int off=16; off; off>>=1){
            a0 += __shfl_xor_sync(0xffffffffu, a0, off);
            a1 += __shfl_xor_sync(0xffffffffu, a1, off);
            a2 += __shfl_xor_sync(0xffffffffu, a2, off);
        }
        if (lane == 0){
            spart[half][rl][0] = a0;
            spart[half][rl][1] = a1;
            spart[half][rl][2] = a2;
        }
    }
    __syncthreads();
    if (tid < 12){
        int r = tid / 3, c = tid % 3;
        float v = spart[0][r][c] + spart[1][r][c] + hb[c];
        FOUT[c*Bb*Nn + row0 + r] = lrelu(v);
    }
}

// ---------------- per-(b,head) max of s_dst ----------------
__global__ void tmax_kernel()
{
    __shared__ float red[256];
    const float* t = g_sdst + blockIdx.x * Nn;
    float m = NEG_INF;
    for (int n = threadIdx.x; n < Nn; n += 256) m = fmaxf(m, t[n]);
    red[threadIdx.x] = m;
    __syncthreads();
    #pragma unroll
    for (int s=128; s; s>>=1){
        if (threadIdx.x < s) red[threadIdx.x] = fmaxf(red[threadIdx.x], red[threadIdx.x+s]);
        __syncthreads();
    }
    if (threadIdx.x == 0) g_tmax[blockIdx.x] = red[0];
}

// ---------------- GAT attention: tf32 mma.sync, B single-term ----------------
#define SM_H   0
#define SM_T   (TJ*PITCH)
#define SM_MB  (TJ*PITCH + NHEADS*TJ)
#define SM_FLOATS (TJ*PITCH + NHEADS*TJ + 64)

__global__ __launch_bounds__(256,4) void gat_attn_tc(const int* __restrict__ mask)
{
    extern __shared__ float sm[];
    float* h_t = sm + SM_H;
    float* t_tile = sm + SM_T;
    unsigned long long* m_bits = (unsigned long long*)(sm + SM_MB);
    uint32_t sbase = smem_u32(sm);
    uint32_t sb_h = sbase + SM_H*4;

    int tid = threadIdx.x;
    int w = tid >> 5, lane = tid & 31;
    int h = w & 3, mh = w >> 2;
    int g = lane >> 2, t = lane & 3;
    int split = blockIdx.x % SPLITS;
    int tmp   = blockIdx.x / SPLITS;
    int b     = tmp / NTILES;
    int i0    = (tmp % NTILES) * 32;
    int il0 = mh*16 + g, il1 = il0 + 8;
    int gi0 = i0 + il0, gi1 = i0 + il1;

    float tmx = g_tmax[b*NHEADS + h];
    float s0 = (gi0 < Nn) ? g_ssrc[(b*NHEADS+h)*Nn + gi0] : 0.f;
    float s1 = (gi1 < Nn) ? g_ssrc[(b*NHEADS+h)*Nn + gi1] : 0.f;
    float m20 = lrelu(s0 + tmx) * LOG2E;
    float m21 = lrelu(s1 + tmx) * LOG2E;
    float lv0 = 0.f, lv1 = 0.f;
    float acc[4][4];
    #pragma unroll
    for (int nt=0;nt<4;nt++){ acc[nt][0]=0.f; acc[nt][1]=0.f; acc[nt][2]=0.f; acc[nt][3]=0.f; }

    const int* mrow = mask + (size_t)b*Nn*Nn + (size_t)i0*Nn;
    int mr = tid >> 3, moct = tid & 7;
    int fjj = tid >> 5, fc4 = tid & 31;

    int c0 = split * CPS;
    for (int c = c0; c < c0 + CPS; c++){
        int j0 = c * TJ;
        __syncthreads();

        const float* srch = g_hv + ((size_t)b*NP + j0)*Dd;
        #pragma unroll
        for (int u=0; u<8; u++){
            int jj = fjj + u*8;
            cp16(sb_h + (uint32_t)(jj*(PITCH*4) + fc4*16), srch + (size_t)jj*Dd + fc4*4);
        }
        CP_COMMIT();

        {
            int hh = tid >> 6, jj = tid & 63;
            t_tile[hh*TJ + jj] = (j0+jj < Nn) ? g_sdst[(b*NHEADS+hh)*Nn + j0+jj] : 0.f;
        }
        {
            unsigned int byte = 0;
            int j = j0 + moct*8;
            if (i0 + mr < Nn){
                const int* p = mrow + (size_t)mr*Nn + j;
                if (j + 7 < Nn){
                    int4 A = *(const int4*)p;
                    int4 Bv = *(const int4*)(p+4);
                    byte = (unsigned)(A.x!=0) | ((unsigned)(A.y!=0)<<1)
                         | ((unsigned)(A.z!=0)<<2) | ((unsigned)(A.w!=0)<<3)
                         | ((unsigned)(Bv.x!=0)<<4) | ((unsigned)(Bv.y!=0)<<5)
                         | ((unsigned)(Bv.z!=0)<<6) | ((unsigned)(Bv.w!=0)<<7);
                } else {
                    #pragma unroll
                    for (int k=0;k<8;k++)
                        if (j+k < Nn && p[k] != 0) byte |= (1u<<k);
                }
            }
            ((unsigned char*)m_bits)[mr*8 + moct] = (unsigned char)byte;
        }
        CP_WAIT0();
        __syncthreads();

        unsigned long long bits0 = m_bits[il0] >> t;
        unsigned long long bits1 = m_bits[il1] >> t;

        #pragma unroll
        for (int s=0; s<8; s++){
            float ta = t_tile[h*TJ + s*8 + t];
            float tb = t_tile[h*TJ + s*8 + t + 4];
            float e00 = lrelu(s0 + ta), e01 = lrelu(s0 + tb);
            float e10 = lrelu(s1 + ta), e11 = lrelu(s1 + tb);
            float w00 = ((bits0 >> (8*s))   & 1ull) ? exp2f(fmaf(e00, LOG2E, -m20)) : 0.f;
            float w01 = ((bits0 >> (8*s+4)) & 1ull) ? exp2f(fmaf(e01, LOG2E, -m20)) : 0.f;
            float w10 = ((bits1 >> (8*s))   & 1ull) ? exp2f(fmaf(e10, LOG2E, -m21)) : 0.f;
            float w11 = ((bits1 >> (8*s+4)) & 1ull) ? exp2f(fmaf(e11, LOG2E, -m21)) : 0.f;
            lv0 += w00 + w01;
            lv1 += w10 + w11;
            uint32_t ah0 = tf32_rna(w00), ah1 = tf32_rna(w10);
            uint32_t ah2 = tf32_rna(w01), ah3 = tf32_rna(w11);
            int r0 = (s*8 + t)*PITCH + h*32 + g;
            int r1 = r0 + 4*PITCH;
            #pragma unroll
            for (int nt=0; nt<4; nt++){
                uint32_t bh0 = tf32_rna(h_t[r0 + nt*8]);
                uint32_t bh1 = tf32_rna(h_t[r1 + nt*8]);
                mma_tf32(acc[nt], ah0, ah1, ah2, ah3, bh0, bh1);
            }
        }
    }

    lv0 += __shfl_xor_sync(0xffffffffu, lv0, 1);
    lv0 += __shfl_xor_sync(0xffffffffu, lv0, 2);
    lv1 += __shfl_xor_sync(0xffffffffu, lv1, 1);
    lv1 += __shfl_xor_sync(0xffffffffu, lv1, 2);
    if (t == 0){
        if (gi0 < Nn) g_plv[split][(b*NHEADS+h)*Nn + gi0] = lv0;
        if (gi1 < Nn) g_plv[split][(b*NHEADS+h)*Nn + gi1] = lv1;
    }

    float* pac = g_pacc[split];
    #pragma unroll
    for (int nt=0; nt<4; nt++){
        int d0 = h*32 + nt*8 + 2*t;
        if (gi0 < Nn){
            size_t x = ((size_t)(b*Nn + gi0))*Dd + d0;
            *(float2*)(pac + x) = make_float2(acc[nt][0], acc[nt][1]);
        }
        if (gi1 < Nn){
            size_t x = ((size_t)(b*Nn + gi1))*Dd + d0;
            *(float2*)(pac + x) = make_float2(acc[nt][2], acc[nt][3]);
        }
    }
}

// ---------------- factor attention: U -> A ----------------
__global__ void fa_kernel(const float* __restrict__ feats,
    const float* __restrict__ projW, float* __restrict__ A)
{
    __shared__ float pw[64][65];
    __shared__ float ft[64][64];
    int tid = threadIdx.x;
    int ntile = blockIdx.x & 31;
    int hb_   = blockIdx.x >> 5;
    int hn = hb_ >> 1, b = hb_ & 1;
    int n0 = ntile*64;
    const float* P = projW + (size_t)hn*64*64;
    for (int idx=tid; idx<4096; idx+=256) pw[idx>>6][idx&63] = P[idx];
    for (int idx=tid; idx<4096; idx+=256){
        int r=idx>>6, m=idx&63; int n=n0+r;
        ft[r][m] = (n<Nn) ? feats[((size_t)(b*Nn+n))*Ff+m] : 0.f;
    }
    __syncthreads();
    int w = tid>>5, lane = tid&31;
    for (int rr=0; rr<8; rr++){
        int r = w*8+rr; int n=n0+r;
        if (n>=Nn) continue;
        float u0=0.f,u1=0.f;
        #pragma unroll
        for (int m=0;m<64;m++){
            float f = ft[r][m];
            u0 += f*pw[lane][m];
            u1 += f*pw[lane+32][m];
        }
        u0 = lrelu(u0); u1 = lrelu(u1);
        float mx = fmaxf(u0,u1);
        #pragma unroll
        for (int off=16; off; off>>=1)
            mx = fmaxf(mx, __shfl_xor_sync(0xffffffffu, mx, off));
        float e0 = __expf(u0-mx), e1 = __expf(u1-mx);
        float ss = e0+e1;
        #pragma unroll
        for (int off=16; off; off>>=1)
            ss += __shfl_xor_sync(0xffffffffu, ss, off);
        float inv = 1.f/ss;
        size_t base = ((size_t)hb_*Nn + n)*64;
        A[base+lane]    = e0*inv;
        A[base+lane+32] = e1*inv;
    }
}

// ---------------- a_bar = A.mean(axis=n) ----------------
__global__ void abar_kernel(const float* __restrict__ A)
{
    __shared__ float red[8][64];
    int tid=threadIdx.x; int k=tid&63, grp=tid>>6;
    const float* base = A + (size_t)blockIdx.x*Nn*64;
    float s=0.f;
    for (int n=grp; n<Nn; n+=8) s += base[(size_t)n*64+k];
    red[grp][k]=s;
    __syncthreads();
    if (grp==0){
        float t=0.f;
        #pragma unroll
        for (int g=0; g<8; g++) t += red[g][k];
        g_abar[blockIdx.x*64+k] = t * (1.f/Nn);
    }
}

// ---------------- recon = feats @ a_bar ----------------
__global__ void recon_kernel(const float* __restrict__ feats, float* __restrict__ out)
{
    int w = threadIdx.x>>5, lane=threadIdx.x&31;
    int ro = blockIdx.x*8 + w;
    if (ro >= HN*Bb*Nn) return;
    int hn = ro / (Bb*Nn);
    int rem = ro % (Bb*Nn);
    int b = rem / Nn, n = rem % Nn;
    const float* f  = feats  + (size_t)(b*Nn+n)*Ff;
    const float* ab = g_abar + (hn*Bb+b)*Ff;
    float p = f[lane]*ab[lane] + f[lane+32]*ab[lane+32];
    #pragma unroll
    for (int off=16; off; off>>=1)
        p += __shfl_xor_sync(0xffffffffu, p, off);
    if (lane==0) out[ro] = p;
}

extern "C" void kernel_launch(void* const* d_in, const int* in_sizes, int n_in,
                              void* d_out, int out_size)
{
    const float* feats = (const float*)d_in[0];
    const int* ind = (const int*)d_in[1];
    const int* uni = (const int*)d_in[2];
    const float* bn_g = (const float*)d_in[3];
    const float* bn_b = (const float*)d_in[4];
    const float* bn_m = (const float*)d_in[5];
    const float* bn_v = (const float*)d_in[6];
    const float* W1   = (const float*)d_in[7];
    const float* b1   = (const float*)d_in[8];
    const float* W2   = (const float*)d_in[9];
    const float* b2   = (const float*)d_in[10];
    const float* giW  = (const float*)d_in[11];
    const float* gias = (const float*)d_in[12];
    const float* giad = (const float*)d_in[13];
    const float* guW  = (const float*)d_in[14];
    const float* guas = (const float*)d_in[15];
    const float* guad = (const float*)d_in[16];
    const float* hW   = (const float*)d_in[17];
    const float* hb   = (const float*)d_in[18];
    const float* pW   = (const float*)d_in[19];

    float* out  = (float*)d_out;
    float* C    = out;
    float* CBI  = out + 512000;
    float* CBU  = out + 1024000;
    float* HI   = out + 1536000;
    float* HU   = out + 2048000;
    float* FOUT = out + 2560000;
    float* ROUT = out + 2572000;
    float* AOUT = out + 2584000;

    static int smem_set = 0;
    const int smem_bytes = SM_FLOATS * 4;
    if (!smem_set){
        cudaFuncSetAttribute(gat_attn_tc,
            cudaFuncAttributeMaxDynamicSharedMemorySize, smem_bytes);
        smem_set = 1;
    }

    enc_proj1<<<1000,256>>>(feats, bn_g, bn_b, bn_m, bn_v, W1, b1, W2, b2, C,
                            giW, gias, giad);
    tmax_kernel<<<8,256>>>();
    gat_attn_tc<<<Bb*NTILES*SPLITS,256,smem_bytes>>>(ind);

    comb_proj2<<<1000,256>>>(C, guW, guas, guad, HI, CBI);
    tmax_kernel<<<8,256>>>();
    gat_attn_tc<<<Bb*NTILES*SPLITS,256,smem_bytes>>>(uni);

    comb2_fact<<<1000,256>>>(C, CBI, hW, hb, HU, CBU, FOUT);

    fa_kernel<<<192,256>>>(feats, pW, AOUT);
    abar_kernel<<<6,512>>>(AOUT);
    recon_kernel<<<1500,256>>>(feats, ROUT);
}